// round 6
// baseline (speedup 1.0000x reference)
#include <cuda_runtime.h>
#include <cuda_bf16.h>
#include <cstdint>

#define ND 128
#define ED 32
#define HD 256
#define N_MAX 100000
#define E_MAX 1600000

typedef unsigned long long u64;
typedef unsigned int u32;

// ---------------- packed f32x2 helpers (scalar kernels) ----------------
__device__ __forceinline__ u64 ffma2(u64 a, u64 b, u64 c) {
    u64 d;
    asm("fma.rn.f32x2 %0, %1, %2, %3;" : "=l"(d) : "l"(a), "l"(b), "l"(c));
    return d;
}
__device__ __forceinline__ u64 dup2(float x) {
    u64 d;
    asm("mov.b64 %0, {%1, %1};" : "=l"(d) : "f"(x));
    return d;
}
__device__ __forceinline__ float2 unpk(u64 p) {
    float2 r;
    asm("mov.b64 {%0, %1}, %2;" : "=f"(r.x), "=f"(r.y) : "l"(p));
    return r;
}

// ---------------- warp-MMA helpers (family-compatible: sm_80+) ----------------
__device__ __forceinline__ u32 smem_u32(const void* p) {
    u32 a;
    asm("{ .reg .u64 t; cvta.to.shared.u64 t, %1; cvt.u32.u64 %0, t; }" : "=r"(a) : "l"(p));
    return a;
}
__device__ __forceinline__ void ldsm_x4(u32 addr, u32& r0, u32& r1, u32& r2, u32& r3) {
    asm volatile("ldmatrix.sync.aligned.m8n8.x4.shared.b16 {%0,%1,%2,%3}, [%4];"
        : "=r"(r0), "=r"(r1), "=r"(r2), "=r"(r3) : "r"(addr));
}
__device__ __forceinline__ void mma_bf16(float* d, u32 a0, u32 a1, u32 a2, u32 a3,
                                         u32 b0, u32 b1) {
    asm volatile("mma.sync.aligned.m16n8k16.row.col.f32.bf16.bf16.f32 "
        "{%0,%1,%2,%3}, {%4,%5,%6,%7}, {%8,%9}, {%0,%1,%2,%3};"
        : "+f"(d[0]), "+f"(d[1]), "+f"(d[2]), "+f"(d[3])
        : "r"(a0), "r"(a1), "r"(a2), "r"(a3), "r"(b0), "r"(b1));
}
__device__ __forceinline__ void bfsplit2(float a, float b, u32& hi, u32& lo) {
    __nv_bfloat162 h = __floats2bfloat162_rn(a, b);
    float ra = a - __bfloat162float(h.x);
    float rb = b - __bfloat162float(h.y);
    __nv_bfloat162 l = __floats2bfloat162_rn(ra, rb);
    hi = *(u32*)&h;
    lo = *(u32*)&l;
}
#define CP_ASYNC16(d, s) asm volatile("cp.async.cg.shared.global [%0], [%1], 16;" :: "r"(d), "l"(s) : "memory")
#define CP_COMMIT()      asm volatile("cp.async.commit_group;" ::: "memory")
#define CP_WAIT(n)       asm volatile("cp.async.wait_group %0;" :: "n"(n) : "memory")

// ---------------- scratch ----------------
__device__ int   g_src[E_MAX];
__device__ int   g_dst[E_MAX];
__device__ float g_Psrc[(size_t)N_MAX * HD];
__device__ float g_Pdst[(size_t)N_MAX * HD];
__device__ float g_agg [(size_t)N_MAX * ND];
// pre-split bf16 weight images (plain row-major, [n][k])
__device__ __align__(16) __nv_bfloat16 g_B1e[256 * 64];   // k<32: W1c_hi, k>=32: W1c_lo
__device__ __align__(16) __nv_bfloat16 g_B2e[128 * 512];  // k<256: W2_hi,  k>=256: W2_lo

// =================== K0: edge_index convert (int64 OR int32) ===================
__global__ void k_convert(const int* __restrict__ w, int E)
{
    __shared__ int s64;
    if (threadIdx.x == 0) {
        int b = 1;
        #pragma unroll
        for (int i = 0; i < 8; i++) if (w[2 * i + 1] != 0) b = 0;
        s64 = b;
    }
    __syncthreads();
    int i = blockIdx.x * blockDim.x + threadIdx.x;
    if (i >= E) return;
    if (s64) {
        const long long* e = (const long long*)w;
        g_src[i] = (int)e[i];
        g_dst[i] = (int)e[(size_t)E + i];
    } else {
        g_src[i] = w[i];
        g_dst[i] = w[(size_t)E + i];
    }
}

// =================== K_prep: build pre-split bf16 weight images =================
__global__ void k_prep(const float* __restrict__ mW1, const float* __restrict__ mW2)
{
    int tid = blockIdx.x * blockDim.x + threadIdx.x;
    int total = 256 * 32 + 128 * 256;
    for (int i = tid; i < total; i += gridDim.x * blockDim.x) {
        if (i < 256 * 32) {
            int n = i >> 5, k = i & 31;                 // W1c[k][n]
            float w = mW1[(size_t)(2 * ND + k) * HD + n];
            __nv_bfloat16 h = __float2bfloat16(w);
            __nv_bfloat16 l = __float2bfloat16(w - __bfloat162float(h));
            g_B1e[n * 64 + k]      = h;
            g_B1e[n * 64 + 32 + k] = l;
        } else {
            int q = i - 256 * 32;
            int n = q >> 8, j = q & 255;                // W2[j][n]
            float w = mW2[(size_t)j * ND + n];
            __nv_bfloat16 h = __float2bfloat16(w);
            __nv_bfloat16 l = __float2bfloat16(w - __bfloat162float(h));
            g_B2e[n * 512 + j]       = h;
            g_B2e[n * 512 + 256 + j] = l;
        }
    }
}

// =================== K1: per-node precompute (scalar, proven) ===================
__global__ __launch_bounds__(256) void k_node_pre(
    const float* __restrict__ x, const float* __restrict__ cong,
    const float* __restrict__ mW1, const float* __restrict__ mb1, int N)
{
    __shared__ __align__(16) float Xt[ND * 33];
    __shared__ __align__(16) float Bs[16 * HD];
    const int tid = threadIdx.x;
    const int cg = tid & 31, eg = tid >> 5;
    const int base = blockIdx.x * 32;

    for (int idx = tid; idx < 32 * ND; idx += 256) {
        int k = idx & (ND - 1), n = idx >> 7;
        int node = base + n;
        Xt[k * 33 + n] = (node < N) ? x[(size_t)node * ND + k] : 0.f;
    }
    float cg4[4];
    #pragma unroll
    for (int i = 0; i < 4; i++) {
        int node = base + eg * 4 + i;
        cg4[i] = (node < N) ? cong[node] : 0.f;
    }
    __syncthreads();

    for (int which = 0; which < 2; which++) {
        const float* W = mW1 + (size_t)which * ND * HD;
        u64 acc[4][2][2];
        #pragma unroll
        for (int i = 0; i < 4; i++)
            #pragma unroll
            for (int p = 0; p < 2; p++) { acc[i][p][0] = 0ull; acc[i][p][1] = 0ull; }

        for (int ko = 0; ko < ND; ko += 16) {
            {
                const float4* srcp = (const float4*)(W + (size_t)ko * HD);
                float4* dstp = (float4*)Bs;
                for (int idx = tid; idx < 16 * HD / 4; idx += 256) dstp[idx] = srcp[idx];
            }
            __syncthreads();
            #pragma unroll 4
            for (int kk = 0; kk < 16; kk++) {
                u64 aa[4];
                #pragma unroll
                for (int i = 0; i < 4; i++) aa[i] = dup2(Xt[(ko + kk) * 33 + eg * 4 + i]);
                #pragma unroll
                for (int p = 0; p < 2; p++) {
                    ulonglong2 b = *(const ulonglong2*)&Bs[kk * HD + 4 * cg + 128 * p];
                    #pragma unroll
                    for (int i = 0; i < 4; i++) {
                        acc[i][p][0] = ffma2(aa[i], b.x, acc[i][p][0]);
                        acc[i][p][1] = ffma2(aa[i], b.y, acc[i][p][1]);
                    }
                }
            }
            __syncthreads();
        }
        #pragma unroll
        for (int p = 0; p < 2; p++) {
            if (which == 0) {
                float4 w2 = *(const float4*)&mW1[(size_t)288 * HD + 128 * p + 4 * cg];
                #pragma unroll
                for (int i = 0; i < 4; i++) {
                    int node = base + eg * 4 + i;
                    if (node < N) {
                        float2 v0 = unpk(acc[i][p][0]), v1 = unpk(acc[i][p][1]);
                        float4 r = make_float4(v0.x + cg4[i] * w2.x, v0.y + cg4[i] * w2.y,
                                               v1.x + cg4[i] * w2.z, v1.y + cg4[i] * w2.w);
                        *(float4*)&g_Psrc[(size_t)node * HD + 128 * p + 4 * cg] = r;
                    }
                }
            } else {
                float4 b1 = *(const float4*)&mb1[128 * p + 4 * cg];
                #pragma unroll
                for (int i = 0; i < 4; i++) {
                    int node = base + eg * 4 + i;
                    if (node < N) {
                        float2 v0 = unpk(acc[i][p][0]), v1 = unpk(acc[i][p][1]);
                        float4 r = make_float4(v0.x + b1.x, v0.y + b1.y,
                                               v1.x + b1.z, v1.y + b1.w);
                        *(float4*)&g_Pdst[(size_t)node * HD + 128 * p + 4 * cg] = r;
                    }
                }
            }
        }
    }
    for (int idx = tid; idx < 32 * ND; idx += 256) {
        int node = base + (idx >> 7);
        if (node < N) g_agg[(size_t)node * ND + (idx & (ND - 1))] = 0.f;
    }
}

// =================== K2: warp-MMA edge kernel (v3: K-split layer 2) =============
// 128 edges/CTA, 512 threads. Warp w: wm = w&7 (rows 16wm..+15), wn = w>>3
// (which 32-col half of each 64-col hidden chunk it owns).
// Layer-1 D fragments are converted IN REGISTER to layer-2 A fragments
// (bf16 hi/lo). Layer 2 is K-split: each warp accumulates partial messages
// over ALL 128 output cols for its K-slice; the two wn-partials merge via
// the atomic scatter (bias added by wn==0 only). No smem h buffer at all.
// smem layout (bytes):
//   B1  @ 0       [256 rows][64 halves + pad]  stride 144   36864
//   A1  @ 36864   [128 rows][64 halves + pad]  stride 144   18432
//   B2  @ 55296   2 bufs x { hi[128][64] st144 | lo +18432 } 73728
//   src @ 129024  int[128];  dst @ 129536 int[128]
#define B1_OFF  0
#define A1_OFF  36864
#define B2_OFF  55296
#define SRC_OFF 129024
#define DST_OFF 129536
#define EDGE_SMEM 130048
#define B1_ST 144
#define A1_ST 144
#define B2_ST 144
#define B2_BUF 36864

__global__ __launch_bounds__(512) void k_edge_mma(
    const float* __restrict__ edge_attr, const float* __restrict__ mb2, int E)
{
    extern __shared__ __align__(16) char sm[];
    const u32 smu = smem_u32(sm);
    const int tid = threadIdx.x;
    const int w = tid >> 5, l = tid & 31;
    const int wm = w & 7, wn = w >> 3;
    const int g = l >> 2, t = l & 3;
    const int base = blockIdx.x * 128;
    const char* gB2 = (const char*)g_B2e;

    // ---- prefetch B2 chunk 0 into buf 0 (cp.async) ----
    #pragma unroll
    for (int r = 0; r < 4; r++) {
        int i = tid + 512 * r;
        int row = i >> 4, part = i & 15;
        if (part < 8) {
            CP_ASYNC16(smu + B2_OFF + row * B2_ST + part * 16,
                       gB2 + row * 1024 + part * 16);
        } else {
            int p = part - 8;
            CP_ASYNC16(smu + B2_OFF + 18432 + row * B2_ST + p * 16,
                       gB2 + row * 1024 + 512 + p * 16);
        }
    }
    CP_COMMIT();

    // ---- stage src/dst ----
    if (tid < 128) {
        int e = base + tid;
        ((int*)(sm + SRC_OFF))[tid] = (e < E) ? g_src[e] : 0;
        ((int*)(sm + DST_OFF))[tid] = (e < E) ? g_dst[e] : 0;
    }
    // ---- stage B1 ----
    for (int idx = tid; idx < 256 * 8; idx += 512) {
        int row = idx >> 3, ch = idx & 7;
        *(float4*)(sm + B1_OFF + row * B1_ST + ch * 16) =
            *(const float4*)((const char*)g_B1e + row * 128 + ch * 16);
    }
    // ---- stage A1: split edge_attr to bf16 hi|lo ----
    if (tid < 256) {
        int e = tid >> 1, h = tid & 1;
        char* arow = sm + A1_OFF + e * A1_ST;
        if (base + e < E) {
            const float4* src4 = (const float4*)(edge_attr + (size_t)(base + e) * ED + 16 * h);
            #pragma unroll
            for (int q = 0; q < 4; q++) {
                float4 v = src4[q];
                u32 h0, l0, h1, l1;
                bfsplit2(v.x, v.y, h0, l0);
                bfsplit2(v.z, v.w, h1, l1);
                int k = 16 * h + 4 * q;
                *(u32*)(arow + k * 2)            = h0;
                *(u32*)(arow + (k + 2) * 2)      = h1;
                *(u32*)(arow + (32 + k) * 2)     = l0;
                *(u32*)(arow + (32 + k + 2) * 2) = l1;
            }
        } else {
            #pragma unroll
            for (int q = 0; q < 8; q++) {
                int k = 16 * h + 2 * q;
                *(u32*)(arow + k * 2)        = 0u;
                *(u32*)(arow + (32 + k) * 2) = 0u;
            }
        }
    }
    __syncthreads();

    // per-lane ldmatrix address components
    const int lr   = l & 7;
    const int aRow = 16 * wm + lr + ((l >> 3) & 1) * 8;
    const int aKh  = (l >> 4) * 8;
    const int bRow = lr + (l >> 4) * 8;
    const int bKh  = ((l >> 3) & 1) * 8;
    const u32 a1base = smu + A1_OFF + aRow * A1_ST + aKh * 2;

    // this lane's two edge rows
    const int m0 = 16 * wm + g, m1 = m0 + 8;
    const int vs0 = ((const int*)(sm + SRC_OFF))[m0];
    const int vd0 = ((const int*)(sm + DST_OFF))[m0];
    const int vs1 = ((const int*)(sm + SRC_OFF))[m1];
    const int vd1 = ((const int*)(sm + DST_OFF))[m1];

    float acc2[16][4];
    #pragma unroll
    for (int j = 0; j < 16; j++)
        #pragma unroll
        for (int q = 0; q < 4; q++) acc2[j][q] = 0.f;

    // ================= fused chunk loop (no smem h buffer) =================
    #pragma unroll 1
    for (int c = 0; c < 4; c++) {
        // all warps finished layer-2 reads of buf (c+1)&1 (chunk c-1) -> safe to overwrite
        __syncthreads();
        if (c < 3) {
            int buf = (c + 1) & 1;
            #pragma unroll
            for (int r = 0; r < 4; r++) {
                int i = tid + 512 * r;
                int row = i >> 4, part = i & 15;
                if (part < 8) {
                    CP_ASYNC16(smu + B2_OFF + buf * B2_BUF + row * B2_ST + part * 16,
                               gB2 + row * 1024 + 128 * (c + 1) + part * 16);
                } else {
                    int p = part - 8;
                    CP_ASYNC16(smu + B2_OFF + buf * B2_BUF + 18432 + row * B2_ST + p * 16,
                               gB2 + row * 1024 + 512 + 128 * (c + 1) + p * 16);
                }
            }
            CP_COMMIT();
        }

        // ---- layer 1: acc1 = EA @ W1c[:, warp's 32 cols of chunk c] ----
        float acc1[4][4];
        #pragma unroll
        for (int j = 0; j < 4; j++)
            #pragma unroll
            for (int q = 0; q < 4; q++) acc1[j][q] = 0.f;

        // reload A1 fragments (keeps register pressure low)
        u32 fa[4][4];
        #pragma unroll
        for (int kt = 0; kt < 4; kt++)
            ldsm_x4(a1base + kt * 32, fa[kt][0], fa[kt][1], fa[kt][2], fa[kt][3]);

        #pragma unroll
        for (int jp = 0; jp < 2; jp++) {
            u32 bb = smu + B1_OFF + (64 * c + 32 * wn + 16 * jp + bRow) * B1_ST + bKh * 2;
            u32 b0, b1, b2, b3;
            ldsm_x4(bb + 0, b0, b1, b2, b3);      // W1hi k0-15
            mma_bf16(acc1[2 * jp],     fa[0][0], fa[0][1], fa[0][2], fa[0][3], b0, b1);
            mma_bf16(acc1[2 * jp + 1], fa[0][0], fa[0][1], fa[0][2], fa[0][3], b2, b3);
            mma_bf16(acc1[2 * jp],     fa[2][0], fa[2][1], fa[2][2], fa[2][3], b0, b1);
            mma_bf16(acc1[2 * jp + 1], fa[2][0], fa[2][1], fa[2][2], fa[2][3], b2, b3);
            ldsm_x4(bb + 32, b0, b1, b2, b3);     // W1hi k16-31
            mma_bf16(acc1[2 * jp],     fa[1][0], fa[1][1], fa[1][2], fa[1][3], b0, b1);
            mma_bf16(acc1[2 * jp + 1], fa[1][0], fa[1][1], fa[1][2], fa[1][3], b2, b3);
            mma_bf16(acc1[2 * jp],     fa[3][0], fa[3][1], fa[3][2], fa[3][3], b0, b1);
            mma_bf16(acc1[2 * jp + 1], fa[3][0], fa[3][1], fa[3][2], fa[3][3], b2, b3);
            ldsm_x4(bb + 64, b0, b1, b2, b3);     // W1lo k0-15
            mma_bf16(acc1[2 * jp],     fa[0][0], fa[0][1], fa[0][2], fa[0][3], b0, b1);
            mma_bf16(acc1[2 * jp + 1], fa[0][0], fa[0][1], fa[0][2], fa[0][3], b2, b3);
            ldsm_x4(bb + 96, b0, b1, b2, b3);     // W1lo k16-31
            mma_bf16(acc1[2 * jp],     fa[1][0], fa[1][1], fa[1][2], fa[1][3], b0, b1);
            mma_bf16(acc1[2 * jp + 1], fa[1][0], fa[1][1], fa[1][2], fa[1][3], b2, b3);
        }

        // ---- epilogue in registers: gather, relu, split -> layer-2 A frags ----
        // D(m16n8) tile j covers k-local 8j+2t -> A(m16k16) frag f=j>>1:
        //   a0=(g,k0-7) a1=(g+8,k0-7) a2=(g,k8-15) a3=(g+8,k8-15)
        u32 ah[2][4], al[2][4];
        #pragma unroll
        for (int j = 0; j < 4; j++) {
            int col = 64 * c + 32 * wn + 8 * j + 2 * t;
            float2 ps0 = *(const float2*)(g_Psrc + (size_t)vs0 * HD + col);
            float2 pd0 = *(const float2*)(g_Pdst + (size_t)vd0 * HD + col);
            float2 ps1 = *(const float2*)(g_Psrc + (size_t)vs1 * HD + col);
            float2 pd1 = *(const float2*)(g_Pdst + (size_t)vd1 * HD + col);
            float v0 = fmaxf(acc1[j][0] + ps0.x + pd0.x, 0.f);
            float v1 = fmaxf(acc1[j][1] + ps0.y + pd0.y, 0.f);
            float v2 = fmaxf(acc1[j][2] + ps1.x + pd1.x, 0.f);
            float v3 = fmaxf(acc1[j][3] + ps1.y + pd1.y, 0.f);
            int f = j >> 1, h = j & 1;
            bfsplit2(v0, v1, ah[f][2 * h],     al[f][2 * h]);
            bfsplit2(v2, v3, ah[f][2 * h + 1], al[f][2 * h + 1]);
        }

        // B2 buf for chunk c ready? (group for c+1 may still be in flight)
        if (c < 3) { CP_WAIT(1); } else { CP_WAIT(0); }
        __syncthreads();

        // ---- layer 2 (K-split): acc2[all 128 cols] += h_slice @ W2[kslice,:] ----
        const u32 b2b = smu + B2_OFF + (c & 1) * B2_BUF;
        #pragma unroll
        for (int f = 0; f < 2; f++) {
            u32 kof = (u32)(32 * wn + 16 * f + bKh) * 2;
            #pragma unroll
            for (int jp = 0; jp < 8; jp++) {
                u32 nrow = (u32)(16 * jp + bRow);
                u32 b0, b1, b2, b3;
                ldsm_x4(b2b + nrow * B2_ST + kof, b0, b1, b2, b3);           // W2hi
                mma_bf16(acc2[2 * jp],     ah[f][0], ah[f][1], ah[f][2], ah[f][3], b0, b1);
                mma_bf16(acc2[2 * jp + 1], ah[f][0], ah[f][1], ah[f][2], ah[f][3], b2, b3);
                mma_bf16(acc2[2 * jp],     al[f][0], al[f][1], al[f][2], al[f][3], b0, b1);
                mma_bf16(acc2[2 * jp + 1], al[f][0], al[f][1], al[f][2], al[f][3], b2, b3);
                ldsm_x4(b2b + 18432 + nrow * B2_ST + kof, b0, b1, b2, b3);   // W2lo
                mma_bf16(acc2[2 * jp],     ah[f][0], ah[f][1], ah[f][2], ah[f][3], b0, b1);
                mma_bf16(acc2[2 * jp + 1], ah[f][0], ah[f][1], ah[f][2], ah[f][3], b2, b3);
            }
        }
    }

    // ---- scatter: partial sums merge via atomics; bias only from wn==0 ----
    const bool e0 = (base + m0 < E), e1 = (base + m1 < E);
    #pragma unroll
    for (int j = 0; j < 16; j++) {
        int n = 8 * j + 2 * t;
        float bx = 0.f, by = 0.f;
        if (wn == 0) { float2 bv = *(const float2*)(mb2 + n); bx = bv.x; by = bv.y; }
        if (e0) {
            float x0 = acc2[j][0] + bx, x1 = acc2[j][1] + by;
            asm volatile("red.global.add.v2.f32 [%0], {%1, %2};"
                         :: "l"(g_agg + (size_t)vd0 * ND + n), "f"(x0), "f"(x1) : "memory");
        }
        if (e1) {
            float x0 = acc2[j][2] + bx, x1 = acc2[j][3] + by;
            asm volatile("red.global.add.v2.f32 [%0], {%1, %2};"
                         :: "l"(g_agg + (size_t)vd1 * ND + n), "f"(x0), "f"(x1) : "memory");
        }
    }
}

// =================== K3: node update MLP (scalar, proven) =======================
#define K3_SMEM (16640 * 4)
__global__ __launch_bounds__(256) void k_update(
    const float* __restrict__ x,
    const float* __restrict__ uW1, const float* __restrict__ ub1,
    const float* __restrict__ uW2, const float* __restrict__ ub2,
    float* __restrict__ out, int N)
{
    extern __shared__ __align__(16) float smf[];
    float* At = smf;
    float* Ht = smf;
    float* Ws = smf + 8448;
    float* B2 = smf + 8448;

    const int tid = threadIdx.x;
    const int cg = tid & 31, eg = tid >> 5;
    const int base = blockIdx.x * 32;

    for (int idx = tid; idx < 32 * HD; idx += 256) {
        int k = idx & (HD - 1), n = idx >> 8;
        int node = base + n;
        float v = 0.f;
        if (node < N)
            v = (k < ND) ? x[(size_t)node * ND + k]
                         : g_agg[(size_t)node * ND + (k - ND)];
        At[k * 33 + n] = v;
    }
    __syncthreads();

    u64 acc[4][2][2];
    #pragma unroll
    for (int i = 0; i < 4; i++)
        #pragma unroll
        for (int p = 0; p < 2; p++) { acc[i][p][0] = 0ull; acc[i][p][1] = 0ull; }

    for (int ko = 0; ko < HD; ko += 32) {
        {
            const float4* srcp = (const float4*)(uW1 + (size_t)ko * HD);
            float4* dstp = (float4*)Ws;
            for (int idx = tid; idx < 32 * HD / 4; idx += 256) dstp[idx] = srcp[idx];
        }
        __syncthreads();
        #pragma unroll 4
        for (int kk = 0; kk < 32; kk++) {
            u64 aa[4];
            #pragma unroll
            for (int i = 0; i < 4; i++) aa[i] = dup2(At[(ko + kk) * 33 + eg * 4 + i]);
            #pragma unroll
            for (int p = 0; p < 2; p++) {
                ulonglong2 b = *(const ulonglong2*)&Ws[kk * HD + 4 * cg + 128 * p];
                #pragma unroll
                for (int i = 0; i < 4; i++) {
                    acc[i][p][0] = ffma2(aa[i], b.x, acc[i][p][0]);
                    acc[i][p][1] = ffma2(aa[i], b.y, acc[i][p][1]);
                }
            }
        }
        __syncthreads();
    }

    #pragma unroll
    for (int p = 0; p < 2; p++) {
        float4 b1 = *(const float4*)&ub1[128 * p + 4 * cg];
        #pragma unroll
        for (int i = 0; i < 4; i++) {
            int n = eg * 4 + i;
            int jb = 128 * p + 4 * cg;
            float2 v0 = unpk(acc[i][p][0]), v1 = unpk(acc[i][p][1]);
            bool ok = (base + n < N);
            Ht[(jb + 0) * 33 + n] = ok ? fmaxf(v0.x + b1.x, 0.f) : 0.f;
            Ht[(jb + 1) * 33 + n] = ok ? fmaxf(v0.y + b1.y, 0.f) : 0.f;
            Ht[(jb + 2) * 33 + n] = ok ? fmaxf(v1.x + b1.z, 0.f) : 0.f;
            Ht[(jb + 3) * 33 + n] = ok ? fmaxf(v1.y + b1.w, 0.f) : 0.f;
        }
    }
    __syncthreads();

    u64 acc2[4][2];
    #pragma unroll
    for (int i = 0; i < 4; i++) { acc2[i][0] = 0ull; acc2[i][1] = 0ull; }

    for (int ko = 0; ko < HD; ko += 32) {
        {
            const float4* srcp = (const float4*)(uW2 + (size_t)ko * ND);
            float4* dstp = (float4*)B2;
            for (int idx = tid; idx < 32 * ND / 4; idx += 256) dstp[idx] = srcp[idx];
        }
        __syncthreads();
        #pragma unroll 4
        for (int kk = 0; kk < 32; kk++) {
            ulonglong2 b = *(const ulonglong2*)&B2[kk * ND + 4 * cg];
            #pragma unroll
            for (int i = 0; i < 4; i++) {
                u64 aa = dup2(Ht[(ko + kk) * 33 + eg * 4 + i]);
                acc2[i][0] = ffma2(aa, b.x, acc2[i][0]);
                acc2[i][1] = ffma2(aa, b.y, acc2[i][1]);
            }
        }
        __syncthreads();
    }

    float4 b2v = *(const float4*)&ub2[4 * cg];
    #pragma unroll
    for (int i = 0; i < 4; i++) {
        int node = base + eg * 4 + i;
        if (node < N) {
            float2 m0 = unpk(acc2[i][0]), m1 = unpk(acc2[i][1]);
            float4 r = make_float4(m0.x + b2v.x, m0.y + b2v.y, m1.x + b2v.z, m1.y + b2v.w);
            *(float4*)&out[(size_t)node * ND + 4 * cg] = r;
        }
    }
}

// =================== launcher ===================================================
extern "C" void kernel_launch(void* const* d_in, const int* in_sizes, int n_in,
                              void* d_out, int out_size)
{
    const float* x    = (const float*)d_in[0];
    const int*   ei   = (const int*)  d_in[1];
    const float* ea   = (const float*)d_in[2];
    const float* cong = (const float*)d_in[3];
    const float* mW1  = (const float*)d_in[4];
    const float* mb1  = (const float*)d_in[5];
    const float* mW2  = (const float*)d_in[6];
    const float* mb2  = (const float*)d_in[7];
    const float* uW1  = (const float*)d_in[8];
    const float* ub1  = (const float*)d_in[9];
    const float* uW2  = (const float*)d_in[10];
    const float* ub2  = (const float*)d_in[11];

    int N = in_sizes[0] / ND;
    int E = in_sizes[1] / 2;
    if (N > N_MAX) N = N_MAX;
    if (E > E_MAX) E = E_MAX;

    cudaFuncSetAttribute(k_edge_mma, cudaFuncAttributeMaxDynamicSharedMemorySize, EDGE_SMEM);
    cudaFuncSetAttribute(k_update,   cudaFuncAttributeMaxDynamicSharedMemorySize, K3_SMEM);

    k_convert  <<<(E + 255) / 256, 256>>>(ei, E);
    k_prep     <<<160, 256>>>(mW1, mW2);
    k_node_pre <<<(N + 31) / 32, 256>>>(x, cong, mW1, mb1, N);
    k_edge_mma <<<(E + 127) / 128, 512, EDGE_SMEM>>>(ea, mb2, E);
    k_update   <<<(N + 31) / 32, 256, K3_SMEM>>>(x, uW1, ub1, uW2, ub2, (float*)d_out, N);
}

// round 7
// speedup vs baseline: 1.1649x; 1.1649x over previous
#include <cuda_runtime.h>
#include <cuda_bf16.h>
#include <cstdint>

#define ND 128
#define ED 32
#define HD 256
#define N_MAX 100000
#define E_MAX 1600000

typedef unsigned long long u64;
typedef unsigned int u32;

// ---------------- packed f32x2 helpers (scalar kernels) ----------------
__device__ __forceinline__ u64 ffma2(u64 a, u64 b, u64 c) {
    u64 d;
    asm("fma.rn.f32x2 %0, %1, %2, %3;" : "=l"(d) : "l"(a), "l"(b), "l"(c));
    return d;
}
__device__ __forceinline__ u64 dup2(float x) {
    u64 d;
    asm("mov.b64 %0, {%1, %1};" : "=l"(d) : "f"(x));
    return d;
}
__device__ __forceinline__ float2 unpk(u64 p) {
    float2 r;
    asm("mov.b64 {%0, %1}, %2;" : "=f"(r.x), "=f"(r.y) : "l"(p));
    return r;
}

// ---------------- warp-MMA helpers (family-compatible: sm_80+) ----------------
__device__ __forceinline__ u32 smem_u32(const void* p) {
    u32 a;
    asm("{ .reg .u64 t; cvta.to.shared.u64 t, %1; cvt.u32.u64 %0, t; }" : "=r"(a) : "l"(p));
    return a;
}
__device__ __forceinline__ void ldsm_x4(u32 addr, u32& r0, u32& r1, u32& r2, u32& r3) {
    asm volatile("ldmatrix.sync.aligned.m8n8.x4.shared.b16 {%0,%1,%2,%3}, [%4];"
        : "=r"(r0), "=r"(r1), "=r"(r2), "=r"(r3) : "r"(addr));
}
__device__ __forceinline__ void mma_bf16(float* d, u32 a0, u32 a1, u32 a2, u32 a3,
                                         u32 b0, u32 b1) {
    asm volatile("mma.sync.aligned.m16n8k16.row.col.f32.bf16.bf16.f32 "
        "{%0,%1,%2,%3}, {%4,%5,%6,%7}, {%8,%9}, {%0,%1,%2,%3};"
        : "+f"(d[0]), "+f"(d[1]), "+f"(d[2]), "+f"(d[3])
        : "r"(a0), "r"(a1), "r"(a2), "r"(a3), "r"(b0), "r"(b1));
}
__device__ __forceinline__ void bfsplit2(float a, float b, u32& hi, u32& lo) {
    __nv_bfloat162 h = __floats2bfloat162_rn(a, b);
    float ra = a - __bfloat162float(h.x);
    float rb = b - __bfloat162float(h.y);
    __nv_bfloat162 l = __floats2bfloat162_rn(ra, rb);
    hi = *(u32*)&h;
    lo = *(u32*)&l;
}
#define CP_ASYNC16(d, s) asm volatile("cp.async.cg.shared.global [%0], [%1], 16;" :: "r"(d), "l"(s) : "memory")
#define CP_COMMIT()      asm volatile("cp.async.commit_group;" ::: "memory")
#define CP_WAIT(n)       asm volatile("cp.async.wait_group %0;" :: "n"(n) : "memory")

// ---------------- scratch ----------------
__device__ int   g_src[E_MAX];
__device__ int   g_dst[E_MAX];
__device__ float g_Psrc[(size_t)N_MAX * HD];
__device__ float g_Pdst[(size_t)N_MAX * HD];
__device__ float g_agg [(size_t)N_MAX * ND];
// pre-split bf16 weight images (plain row-major, [n][k])
__device__ __align__(16) __nv_bfloat16 g_B1e[256 * 64];   // k<32: W1c_hi, k>=32: W1c_lo
__device__ __align__(16) __nv_bfloat16 g_B2e[128 * 512];  // k<256: W2_hi,  k>=256: W2_lo

// =================== K0: edge_index convert (int64 OR int32) ===================
__global__ void k_convert(const int* __restrict__ w, int E)
{
    __shared__ int s64;
    if (threadIdx.x == 0) {
        int b = 1;
        #pragma unroll
        for (int i = 0; i < 8; i++) if (w[2 * i + 1] != 0) b = 0;
        s64 = b;
    }
    __syncthreads();
    int i = blockIdx.x * blockDim.x + threadIdx.x;
    if (i >= E) return;
    if (s64) {
        const long long* e = (const long long*)w;
        g_src[i] = (int)e[i];
        g_dst[i] = (int)e[(size_t)E + i];
    } else {
        g_src[i] = w[i];
        g_dst[i] = w[(size_t)E + i];
    }
}

// =================== K_prep: build pre-split bf16 weight images =================
__global__ void k_prep(const float* __restrict__ mW1, const float* __restrict__ mW2)
{
    int tid = blockIdx.x * blockDim.x + threadIdx.x;
    int total = 256 * 32 + 128 * 256;
    for (int i = tid; i < total; i += gridDim.x * blockDim.x) {
        if (i < 256 * 32) {
            int n = i >> 5, k = i & 31;                 // W1c[k][n]
            float w = mW1[(size_t)(2 * ND + k) * HD + n];
            __nv_bfloat16 h = __float2bfloat16(w);
            __nv_bfloat16 l = __float2bfloat16(w - __bfloat162float(h));
            g_B1e[n * 64 + k]      = h;
            g_B1e[n * 64 + 32 + k] = l;
        } else {
            int q = i - 256 * 32;
            int n = q >> 8, j = q & 255;                // W2[j][n]
            float w = mW2[(size_t)j * ND + n];
            __nv_bfloat16 h = __float2bfloat16(w);
            __nv_bfloat16 l = __float2bfloat16(w - __bfloat162float(h));
            g_B2e[n * 512 + j]       = h;
            g_B2e[n * 512 + 256 + j] = l;
        }
    }
}

// =================== K1: per-node precompute (scalar, proven) ===================
__global__ __launch_bounds__(256) void k_node_pre(
    const float* __restrict__ x, const float* __restrict__ cong,
    const float* __restrict__ mW1, const float* __restrict__ mb1, int N)
{
    __shared__ __align__(16) float Xt[ND * 33];
    __shared__ __align__(16) float Bs[16 * HD];
    const int tid = threadIdx.x;
    const int cg = tid & 31, eg = tid >> 5;
    const int base = blockIdx.x * 32;

    for (int idx = tid; idx < 32 * ND; idx += 256) {
        int k = idx & (ND - 1), n = idx >> 7;
        int node = base + n;
        Xt[k * 33 + n] = (node < N) ? x[(size_t)node * ND + k] : 0.f;
    }
    float cg4[4];
    #pragma unroll
    for (int i = 0; i < 4; i++) {
        int node = base + eg * 4 + i;
        cg4[i] = (node < N) ? cong[node] : 0.f;
    }
    __syncthreads();

    for (int which = 0; which < 2; which++) {
        const float* W = mW1 + (size_t)which * ND * HD;
        u64 acc[4][2][2];
        #pragma unroll
        for (int i = 0; i < 4; i++)
            #pragma unroll
            for (int p = 0; p < 2; p++) { acc[i][p][0] = 0ull; acc[i][p][1] = 0ull; }

        for (int ko = 0; ko < ND; ko += 16) {
            {
                const float4* srcp = (const float4*)(W + (size_t)ko * HD);
                float4* dstp = (float4*)Bs;
                for (int idx = tid; idx < 16 * HD / 4; idx += 256) dstp[idx] = srcp[idx];
            }
            __syncthreads();
            #pragma unroll 4
            for (int kk = 0; kk < 16; kk++) {
                u64 aa[4];
                #pragma unroll
                for (int i = 0; i < 4; i++) aa[i] = dup2(Xt[(ko + kk) * 33 + eg * 4 + i]);
                #pragma unroll
                for (int p = 0; p < 2; p++) {
                    ulonglong2 b = *(const ulonglong2*)&Bs[kk * HD + 4 * cg + 128 * p];
                    #pragma unroll
                    for (int i = 0; i < 4; i++) {
                        acc[i][p][0] = ffma2(aa[i], b.x, acc[i][p][0]);
                        acc[i][p][1] = ffma2(aa[i], b.y, acc[i][p][1]);
                    }
                }
            }
            __syncthreads();
        }
        #pragma unroll
        for (int p = 0; p < 2; p++) {
            if (which == 0) {
                float4 w2 = *(const float4*)&mW1[(size_t)288 * HD + 128 * p + 4 * cg];
                #pragma unroll
                for (int i = 0; i < 4; i++) {
                    int node = base + eg * 4 + i;
                    if (node < N) {
                        float2 v0 = unpk(acc[i][p][0]), v1 = unpk(acc[i][p][1]);
                        float4 r = make_float4(v0.x + cg4[i] * w2.x, v0.y + cg4[i] * w2.y,
                                               v1.x + cg4[i] * w2.z, v1.y + cg4[i] * w2.w);
                        *(float4*)&g_Psrc[(size_t)node * HD + 128 * p + 4 * cg] = r;
                    }
                }
            } else {
                float4 b1 = *(const float4*)&mb1[128 * p + 4 * cg];
                #pragma unroll
                for (int i = 0; i < 4; i++) {
                    int node = base + eg * 4 + i;
                    if (node < N) {
                        float2 v0 = unpk(acc[i][p][0]), v1 = unpk(acc[i][p][1]);
                        float4 r = make_float4(v0.x + b1.x, v0.y + b1.y,
                                               v1.x + b1.z, v1.y + b1.w);
                        *(float4*)&g_Pdst[(size_t)node * HD + 128 * p + 4 * cg] = r;
                    }
                }
            }
        }
    }
    for (int idx = tid; idx < 32 * ND; idx += 256) {
        int node = base + (idx >> 7);
        if (node < N) g_agg[(size_t)node * ND + (idx & (ND - 1))] = 0.f;
    }
}

// =================== K2: warp-MMA edge kernel (v4 = v2 + gather prefetch) =======
// 128 edges/CTA, 512 threads. Warp w: wm = w&7 (rows 16wm..+15), wn = w>>3 (N half).
// Per 64-col hidden chunk c: PREFETCH gathers -> layer1 MMA (hides LDG latency)
// -> relu/split/stage -> layer2 MMA, with cp.async double-buffered B2 prefetch.
// smem layout (bytes):
//   B1  @ 0       [256 rows][64 halves + pad]  stride 144    36864
//   A2c @ 36864   [128 rows][64 hi | 64 lo]    stride 272    34816   (A1 aliases here)
//   B2  @ 71680   2 bufs x { hi[128][64] st144 | lo +18432 }  73728
//   src @ 145408  int[128];  dst @ 145920 int[128]
#define B1_OFF  0
#define A2_OFF  36864
#define B2_OFF  71680
#define SRC_OFF 145408
#define DST_OFF 145920
#define EDGE_SMEM 146432
#define B1_ST 144
#define A1_ST 144
#define A2_ST 272
#define B2_ST 144
#define B2_BUF 36864

__global__ __launch_bounds__(512, 1) void k_edge_mma(
    const float* __restrict__ edge_attr, const float* __restrict__ mb2, int E)
{
    extern __shared__ __align__(16) char sm[];
    const u32 smu = smem_u32(sm);
    const int tid = threadIdx.x;
    const int w = tid >> 5, l = tid & 31;
    const int wm = w & 7, wn = w >> 3;
    const int g = l >> 2, t = l & 3;
    const int base = blockIdx.x * 128;
    const char* gB2 = (const char*)g_B2e;

    // ---- prefetch B2 chunk 0 into buf 0 (cp.async) ----
    #pragma unroll
    for (int r = 0; r < 4; r++) {
        int i = tid + 512 * r;
        int row = i >> 4, part = i & 15;
        if (part < 8) {
            CP_ASYNC16(smu + B2_OFF + row * B2_ST + part * 16,
                       gB2 + row * 1024 + part * 16);
        } else {
            int p = part - 8;
            CP_ASYNC16(smu + B2_OFF + 18432 + row * B2_ST + p * 16,
                       gB2 + row * 1024 + 512 + p * 16);
        }
    }
    CP_COMMIT();

    // ---- stage src/dst ----
    if (tid < 128) {
        int e = base + tid;
        ((int*)(sm + SRC_OFF))[tid] = (e < E) ? g_src[e] : 0;
        ((int*)(sm + DST_OFF))[tid] = (e < E) ? g_dst[e] : 0;
    }
    // ---- stage B1 ----
    for (int idx = tid; idx < 256 * 8; idx += 512) {
        int row = idx >> 3, ch = idx & 7;
        *(float4*)(sm + B1_OFF + row * B1_ST + ch * 16) =
            *(const float4*)((const char*)g_B1e + row * 128 + ch * 16);
    }
    // ---- stage A1 (aliases A2c region): split edge_attr to bf16 hi|lo ----
    if (tid < 256) {
        int e = tid >> 1, h = tid & 1;
        char* arow = sm + A2_OFF + e * A1_ST;
        if (base + e < E) {
            const float4* src4 = (const float4*)(edge_attr + (size_t)(base + e) * ED + 16 * h);
            #pragma unroll
            for (int q = 0; q < 4; q++) {
                float4 v = src4[q];
                u32 h0, l0, h1, l1;
                bfsplit2(v.x, v.y, h0, l0);
                bfsplit2(v.z, v.w, h1, l1);
                int k = 16 * h + 4 * q;
                *(u32*)(arow + k * 2)            = h0;
                *(u32*)(arow + (k + 2) * 2)      = h1;
                *(u32*)(arow + (32 + k) * 2)     = l0;
                *(u32*)(arow + (32 + k + 2) * 2) = l1;
            }
        } else {
            #pragma unroll
            for (int q = 0; q < 8; q++) {
                int k = 16 * h + 2 * q;
                *(u32*)(arow + k * 2)        = 0u;
                *(u32*)(arow + (32 + k) * 2) = 0u;
            }
        }
    }
    __syncthreads();

    // per-lane ldmatrix address components
    const int lr   = l & 7;
    const int aRow = 16 * wm + lr + ((l >> 3) & 1) * 8;
    const int aKh  = (l >> 4) * 8;
    const int bRow = lr + (l >> 4) * 8;
    const int bKh  = ((l >> 3) & 1) * 8;
    const u32 a1base = smu + A2_OFF + aRow * A1_ST + aKh * 2;  // A1 alias
    const u32 a2base = smu + A2_OFF + aRow * A2_ST + aKh * 2;

    // A1 fragments (k-tiles: 0=hi k0-15, 1=hi k16-31, 2=lo k0-15, 3=lo k16-31)
    u32 fa[4][4];
    #pragma unroll
    for (int kt = 0; kt < 4; kt++)
        ldsm_x4(a1base + kt * 32, fa[kt][0], fa[kt][1], fa[kt][2], fa[kt][3]);

    // this lane's two edge rows
    const int m0 = 16 * wm + g, m1 = m0 + 8;
    const int vs0 = ((const int*)(sm + SRC_OFF))[m0];
    const int vd0 = ((const int*)(sm + DST_OFF))[m0];
    const int vs1 = ((const int*)(sm + SRC_OFF))[m1];
    const int vd1 = ((const int*)(sm + DST_OFF))[m1];
    char* a2r0 = sm + A2_OFF + m0 * A2_ST;
    char* a2r1 = sm + A2_OFF + m1 * A2_ST;

    float acc2[8][4];
    #pragma unroll
    for (int j = 0; j < 8; j++)
        #pragma unroll
        for (int q = 0; q < 4; q++) acc2[j][q] = 0.f;

    // ================= fused chunk loop =================
    #pragma unroll 1
    for (int c = 0; c < 4; c++) {
        // ---- PREFETCH node-partial gathers for this chunk (hidden by layer-1 MMA) ----
        float2 ps0[4], pd0[4], ps1[4], pd1[4];
        #pragma unroll
        for (int nt = 0; nt < 4; nt++) {
            int col = 64 * c + 32 * wn + 8 * nt + 2 * t;
            ps0[nt] = *(const float2*)(g_Psrc + (size_t)vs0 * HD + col);
            pd0[nt] = *(const float2*)(g_Pdst + (size_t)vd0 * HD + col);
            ps1[nt] = *(const float2*)(g_Psrc + (size_t)vs1 * HD + col);
            pd1[nt] = *(const float2*)(g_Pdst + (size_t)vd1 * HD + col);
        }

        // ---- layer 1: acc1 = EA @ W1c[:, warp's 32 cols of chunk c] ----
        float acc1[4][4];
        #pragma unroll
        for (int j = 0; j < 4; j++)
            #pragma unroll
            for (int q = 0; q < 4; q++) acc1[j][q] = 0.f;

        #pragma unroll
        for (int jp = 0; jp < 2; jp++) {
            u32 bb = smu + B1_OFF + (64 * c + 32 * wn + 16 * jp + bRow) * B1_ST + bKh * 2;
            u32 b0, b1, b2, b3;
            ldsm_x4(bb + 0, b0, b1, b2, b3);      // W1hi k0-15
            mma_bf16(acc1[2 * jp],     fa[0][0], fa[0][1], fa[0][2], fa[0][3], b0, b1);
            mma_bf16(acc1[2 * jp + 1], fa[0][0], fa[0][1], fa[0][2], fa[0][3], b2, b3);
            mma_bf16(acc1[2 * jp],     fa[2][0], fa[2][1], fa[2][2], fa[2][3], b0, b1);
            mma_bf16(acc1[2 * jp + 1], fa[2][0], fa[2][1], fa[2][2], fa[2][3], b2, b3);
            ldsm_x4(bb + 32, b0, b1, b2, b3);     // W1hi k16-31
            mma_bf16(acc1[2 * jp],     fa[1][0], fa[1][1], fa[1][2], fa[1][3], b0, b1);
            mma_bf16(acc1[2 * jp + 1], fa[1][0], fa[1][1], fa[1][2], fa[1][3], b2, b3);
            mma_bf16(acc1[2 * jp],     fa[3][0], fa[3][1], fa[3][2], fa[3][3], b0, b1);
            mma_bf16(acc1[2 * jp + 1], fa[3][0], fa[3][1], fa[3][2], fa[3][3], b2, b3);
            ldsm_x4(bb + 64, b0, b1, b2, b3);     // W1lo k0-15
            mma_bf16(acc1[2 * jp],     fa[0][0], fa[0][1], fa[0][2], fa[0][3], b0, b1);
            mma_bf16(acc1[2 * jp + 1], fa[0][0], fa[0][1], fa[0][2], fa[0][3], b2, b3);
            ldsm_x4(bb + 96, b0, b1, b2, b3);     // W1lo k16-31
            mma_bf16(acc1[2 * jp],     fa[1][0], fa[1][1], fa[1][2], fa[1][3], b0, b1);
            mma_bf16(acc1[2 * jp + 1], fa[1][0], fa[1][1], fa[1][2], fa[1][3], b2, b3);
        }

        // all warps done with previous layer-2 reads (A2c + B2 buf) before overwrite
        __syncthreads();

        // ---- prefetch B2 chunk c+1 into buf (c+1)&1 ----
        if (c < 3) {
            int buf = (c + 1) & 1;
            #pragma unroll
            for (int r = 0; r < 4; r++) {
                int i = tid + 512 * r;
                int row = i >> 4, part = i & 15;
                if (part < 8) {
                    CP_ASYNC16(smu + B2_OFF + buf * B2_BUF + row * B2_ST + part * 16,
                               gB2 + row * 1024 + 128 * (c + 1) + part * 16);
                } else {
                    int p = part - 8;
                    CP_ASYNC16(smu + B2_OFF + buf * B2_BUF + 18432 + row * B2_ST + p * 16,
                               gB2 + row * 1024 + 512 + 128 * (c + 1) + p * 16);
                }
            }
            CP_COMMIT();
        }

        // ---- epilogue: add prefetched partials, relu, bf16-split into A2c ----
        #pragma unroll
        for (int nt = 0; nt < 4; nt++) {
            int lc = 32 * wn + 8 * nt + 2 * t;
            float v00 = fmaxf(acc1[nt][0] + ps0[nt].x + pd0[nt].x, 0.f);
            float v01 = fmaxf(acc1[nt][1] + ps0[nt].y + pd0[nt].y, 0.f);
            float v10 = fmaxf(acc1[nt][2] + ps1[nt].x + pd1[nt].x, 0.f);
            float v11 = fmaxf(acc1[nt][3] + ps1[nt].y + pd1[nt].y, 0.f);
            u32 h0, l0v, h1, l1v;
            bfsplit2(v00, v01, h0, l0v);
            bfsplit2(v10, v11, h1, l1v);
            *(u32*)(a2r0 + lc * 2)       = h0;
            *(u32*)(a2r0 + 128 + lc * 2) = l0v;
            *(u32*)(a2r1 + lc * 2)       = h1;
            *(u32*)(a2r1 + 128 + lc * 2) = l1v;
        }

        if (c < 3) { CP_WAIT(1); } else { CP_WAIT(0); }
        __syncthreads();

        // ---- layer 2: accumulate h_chunk @ W2_chunk (3-term) into acc2 ----
        const u32 b2b = smu + B2_OFF + (c & 1) * B2_BUF;
        #pragma unroll
        for (int t4 = 0; t4 < 4; t4++) {
            u32 ah0, ah1, ah2, ah3, al0, al1, al2, al3;
            ldsm_x4(a2base + t4 * 32,       ah0, ah1, ah2, ah3);
            ldsm_x4(a2base + 128 + t4 * 32, al0, al1, al2, al3);
            #pragma unroll
            for (int jp = 0; jp < 4; jp++) {
                u32 nrow = (u32)(64 * wn + 16 * jp + bRow);
                u32 kof  = (u32)(16 * t4 + bKh) * 2;
                u32 b0, b1, b2, b3;
                ldsm_x4(b2b + nrow * B2_ST + kof, b0, b1, b2, b3);           // W2hi
                mma_bf16(acc2[2 * jp],     ah0, ah1, ah2, ah3, b0, b1);
                mma_bf16(acc2[2 * jp + 1], ah0, ah1, ah2, ah3, b2, b3);
                mma_bf16(acc2[2 * jp],     al0, al1, al2, al3, b0, b1);
                mma_bf16(acc2[2 * jp + 1], al0, al1, al2, al3, b2, b3);
                ldsm_x4(b2b + 18432 + nrow * B2_ST + kof, b0, b1, b2, b3);   // W2lo
                mma_bf16(acc2[2 * jp],     ah0, ah1, ah2, ah3, b0, b1);
                mma_bf16(acc2[2 * jp + 1], ah0, ah1, ah2, ah3, b2, b3);
            }
        }
    }

    // ---- scatter: + mb2, red.v2 into g_agg[dst] ----
    const bool e0 = (base + m0 < E), e1 = (base + m1 < E);
    #pragma unroll
    for (int j = 0; j < 8; j++) {
        int n = 64 * wn + 8 * j + 2 * t;
        float2 bv = *(const float2*)(mb2 + n);
        if (e0) {
            float x0 = acc2[j][0] + bv.x, x1 = acc2[j][1] + bv.y;
            asm volatile("red.global.add.v2.f32 [%0], {%1, %2};"
                         :: "l"(g_agg + (size_t)vd0 * ND + n), "f"(x0), "f"(x1) : "memory");
        }
        if (e1) {
            float x0 = acc2[j][2] + bv.x, x1 = acc2[j][3] + bv.y;
            asm volatile("red.global.add.v2.f32 [%0], {%1, %2};"
                         :: "l"(g_agg + (size_t)vd1 * ND + n), "f"(x0), "f"(x1) : "memory");
        }
    }
}

// =================== K3: node update MLP (scalar, proven) =======================
#define K3_SMEM (16640 * 4)
__global__ __launch_bounds__(256) void k_update(
    const float* __restrict__ x,
    const float* __restrict__ uW1, const float* __restrict__ ub1,
    const float* __restrict__ uW2, const float* __restrict__ ub2,
    float* __restrict__ out, int N)
{
    extern __shared__ __align__(16) float smf[];
    float* At = smf;
    float* Ht = smf;
    float* Ws = smf + 8448;
    float* B2 = smf + 8448;

    const int tid = threadIdx.x;
    const int cg = tid & 31, eg = tid >> 5;
    const int base = blockIdx.x * 32;

    for (int idx = tid; idx < 32 * HD; idx += 256) {
        int k = idx & (HD - 1), n = idx >> 8;
        int node = base + n;
        float v = 0.f;
        if (node < N)
            v = (k < ND) ? x[(size_t)node * ND + k]
                         : g_agg[(size_t)node * ND + (k - ND)];
        At[k * 33 + n] = v;
    }
    __syncthreads();

    u64 acc[4][2][2];
    #pragma unroll
    for (int i = 0; i < 4; i++)
        #pragma unroll
        for (int p = 0; p < 2; p++) { acc[i][p][0] = 0ull; acc[i][p][1] = 0ull; }

    for (int ko = 0; ko < HD; ko += 32) {
        {
            const float4* srcp = (const float4*)(uW1 + (size_t)ko * HD);
            float4* dstp = (float4*)Ws;
            for (int idx = tid; idx < 32 * HD / 4; idx += 256) dstp[idx] = srcp[idx];
        }
        __syncthreads();
        #pragma unroll 4
        for (int kk = 0; kk < 32; kk++) {
            u64 aa[4];
            #pragma unroll
            for (int i = 0; i < 4; i++) aa[i] = dup2(At[(ko + kk) * 33 + eg * 4 + i]);
            #pragma unroll
            for (int p = 0; p < 2; p++) {
                ulonglong2 b = *(const ulonglong2*)&Ws[kk * HD + 4 * cg + 128 * p];
                #pragma unroll
                for (int i = 0; i < 4; i++) {
                    acc[i][p][0] = ffma2(aa[i], b.x, acc[i][p][0]);
                    acc[i][p][1] = ffma2(aa[i], b.y, acc[i][p][1]);
                }
            }
        }
        __syncthreads();
    }

    #pragma unroll
    for (int p = 0; p < 2; p++) {
        float4 b1 = *(const float4*)&ub1[128 * p + 4 * cg];
        #pragma unroll
        for (int i = 0; i < 4; i++) {
            int n = eg * 4 + i;
            int jb = 128 * p + 4 * cg;
            float2 v0 = unpk(acc[i][p][0]), v1 = unpk(acc[i][p][1]);
            bool ok = (base + n < N);
            Ht[(jb + 0) * 33 + n] = ok ? fmaxf(v0.x + b1.x, 0.f) : 0.f;
            Ht[(jb + 1) * 33 + n] = ok ? fmaxf(v0.y + b1.y, 0.f) : 0.f;
            Ht[(jb + 2) * 33 + n] = ok ? fmaxf(v1.x + b1.z, 0.f) : 0.f;
            Ht[(jb + 3) * 33 + n] = ok ? fmaxf(v1.y + b1.w, 0.f) : 0.f;
        }
    }
    __syncthreads();

    u64 acc2[4][2];
    #pragma unroll
    for (int i = 0; i < 4; i++) { acc2[i][0] = 0ull; acc2[i][1] = 0ull; }

    for (int ko = 0; ko < HD; ko += 32) {
        {
            const float4* srcp = (const float4*)(uW2 + (size_t)ko * ND);
            float4* dstp = (float4*)B2;
            for (int idx = tid; idx < 32 * ND / 4; idx += 256) dstp[idx] = srcp[idx];
        }
        __syncthreads();
        #pragma unroll 4
        for (int kk = 0; kk < 32; kk++) {
            ulonglong2 b = *(const ulonglong2*)&B2[kk * ND + 4 * cg];
            #pragma unroll
            for (int i = 0; i < 4; i++) {
                u64 aa = dup2(Ht[(ko + kk) * 33 + eg * 4 + i]);
                acc2[i][0] = ffma2(aa, b.x, acc2[i][0]);
                acc2[i][1] = ffma2(aa, b.y, acc2[i][1]);
            }
        }
        __syncthreads();
    }

    float4 b2v = *(const float4*)&ub2[4 * cg];
    #pragma unroll
    for (int i = 0; i < 4; i++) {
        int node = base + eg * 4 + i;
        if (node < N) {
            float2 m0 = unpk(acc2[i][0]), m1 = unpk(acc2[i][1]);
            float4 r = make_float4(m0.x + b2v.x, m0.y + b2v.y, m1.x + b2v.z, m1.y + b2v.w);
            *(float4*)&out[(size_t)node * ND + 4 * cg] = r;
        }
    }
}

// =================== launcher ===================================================
extern "C" void kernel_launch(void* const* d_in, const int* in_sizes, int n_in,
                              void* d_out, int out_size)
{
    const float* x    = (const float*)d_in[0];
    const int*   ei   = (const int*)  d_in[1];
    const float* ea   = (const float*)d_in[2];
    const float* cong = (const float*)d_in[3];
    const float* mW1  = (const float*)d_in[4];
    const float* mb1  = (const float*)d_in[5];
    const float* mW2  = (const float*)d_in[6];
    const float* mb2  = (const float*)d_in[7];
    const float* uW1  = (const float*)d_in[8];
    const float* ub1  = (const float*)d_in[9];
    const float* uW2  = (const float*)d_in[10];
    const float* ub2  = (const float*)d_in[11];

    int N = in_sizes[0] / ND;
    int E = in_sizes[1] / 2;
    if (N > N_MAX) N = N_MAX;
    if (E > E_MAX) E = E_MAX;

    cudaFuncSetAttribute(k_edge_mma, cudaFuncAttributeMaxDynamicSharedMemorySize, EDGE_SMEM);
    cudaFuncSetAttribute(k_update,   cudaFuncAttributeMaxDynamicSharedMemorySize, K3_SMEM);

    k_convert  <<<(E + 255) / 256, 256>>>(ei, E);
    k_prep     <<<160, 256>>>(mW1, mW2);
    k_node_pre <<<(N + 31) / 32, 256>>>(x, cong, mW1, mb1, N);
    k_edge_mma <<<(E + 127) / 128, 512, EDGE_SMEM>>>(ea, mb2, E);
    k_update   <<<(N + 31) / 32, 256, K3_SMEM>>>(x, uW1, ub1, uW2, ub2, (float*)d_out, N);
}

// round 8
// speedup vs baseline: 1.3624x; 1.1696x over previous
#include <cuda_runtime.h>
#include <cuda_fp16.h>
#include <cstdint>

#define ND 128
#define ED 32
#define HD 256
#define N_MAX 100000
#define E_MAX 1600000

typedef unsigned long long u64;
typedef unsigned int u32;

// ---------------- packed f32x2 helpers (scalar kernels) ----------------
__device__ __forceinline__ u64 ffma2(u64 a, u64 b, u64 c) {
    u64 d;
    asm("fma.rn.f32x2 %0, %1, %2, %3;" : "=l"(d) : "l"(a), "l"(b), "l"(c));
    return d;
}
__device__ __forceinline__ u64 dup2(float x) {
    u64 d;
    asm("mov.b64 %0, {%1, %1};" : "=l"(d) : "f"(x));
    return d;
}
__device__ __forceinline__ float2 unpk(u64 p) {
    float2 r;
    asm("mov.b64 {%0, %1}, %2;" : "=f"(r.x), "=f"(r.y) : "l"(p));
    return r;
}

// ---------------- warp-MMA helpers (family-compatible: sm_80+) ----------------
__device__ __forceinline__ u32 smem_u32(const void* p) {
    u32 a;
    asm("{ .reg .u64 t; cvta.to.shared.u64 t, %1; cvt.u32.u64 %0, t; }" : "=r"(a) : "l"(p));
    return a;
}
__device__ __forceinline__ void ldsm_x4(u32 addr, u32& r0, u32& r1, u32& r2, u32& r3) {
    asm volatile("ldmatrix.sync.aligned.m8n8.x4.shared.b16 {%0,%1,%2,%3}, [%4];"
        : "=r"(r0), "=r"(r1), "=r"(r2), "=r"(r3) : "r"(addr));
}
__device__ __forceinline__ void mma_f16(float* d, u32 a0, u32 a1, u32 a2, u32 a3,
                                        u32 b0, u32 b1) {
    asm volatile("mma.sync.aligned.m16n8k16.row.col.f32.f16.f16.f32 "
        "{%0,%1,%2,%3}, {%4,%5,%6,%7}, {%8,%9}, {%0,%1,%2,%3};"
        : "+f"(d[0]), "+f"(d[1]), "+f"(d[2]), "+f"(d[3])
        : "r"(a0), "r"(a1), "r"(a2), "r"(a3), "r"(b0), "r"(b1));
}
__device__ __forceinline__ u32 h2pack(float a, float b) {
    __half2 h = __floats2half2_rn(a, b);
    return *(u32*)&h;
}
#define CP_ASYNC16(d, s) asm volatile("cp.async.cg.shared.global [%0], [%1], 16;" :: "r"(d), "l"(s) : "memory")
#define CP_COMMIT()      asm volatile("cp.async.commit_group;" ::: "memory")
#define CP_WAIT(n)       asm volatile("cp.async.wait_group %0;" :: "n"(n) : "memory")

// ---------------- scratch ----------------
__device__ int   g_src[E_MAX];
__device__ int   g_dst[E_MAX];
__device__ float g_Psrc[(size_t)N_MAX * HD];
__device__ float g_Pdst[(size_t)N_MAX * HD];
__device__ float g_agg [(size_t)N_MAX * ND];
// fp16 weight images (row-major, [n][k])
__device__ __align__(16) __half g_B1h[256 * 32];   // W1c^T  [n=256][k=32]
__device__ __align__(16) __half g_B2h[128 * 256];  // W2^T   [n=128][k=256]

// =================== K0: edge_index convert (int64 OR int32) ===================
__global__ void k_convert(const int* __restrict__ w, int E)
{
    __shared__ int s64;
    if (threadIdx.x == 0) {
        int b = 1;
        #pragma unroll
        for (int i = 0; i < 8; i++) if (w[2 * i + 1] != 0) b = 0;
        s64 = b;
    }
    __syncthreads();
    int i = blockIdx.x * blockDim.x + threadIdx.x;
    if (i >= E) return;
    if (s64) {
        const long long* e = (const long long*)w;
        g_src[i] = (int)e[i];
        g_dst[i] = (int)e[(size_t)E + i];
    } else {
        g_src[i] = w[i];
        g_dst[i] = w[(size_t)E + i];
    }
}

// =================== K_prep: build fp16 weight images ===========================
__global__ void k_prep(const float* __restrict__ mW1, const float* __restrict__ mW2)
{
    int tid = blockIdx.x * blockDim.x + threadIdx.x;
    int total = 256 * 32 + 128 * 256;
    for (int i = tid; i < total; i += gridDim.x * blockDim.x) {
        if (i < 256 * 32) {
            int n = i >> 5, k = i & 31;                 // W1c[k][n]
            g_B1h[n * 32 + k] = __float2half(mW1[(size_t)(2 * ND + k) * HD + n]);
        } else {
            int q = i - 256 * 32;
            int n = q >> 8, j = q & 255;                // W2[j][n]
            g_B2h[n * 256 + j] = __float2half(mW2[(size_t)j * ND + n]);
        }
    }
}

// =================== K1: per-node precompute (scalar, proven) ===================
__global__ __launch_bounds__(256) void k_node_pre(
    const float* __restrict__ x, const float* __restrict__ cong,
    const float* __restrict__ mW1, const float* __restrict__ mb1, int N)
{
    __shared__ __align__(16) float Xt[ND * 33];
    __shared__ __align__(16) float Bs[16 * HD];
    const int tid = threadIdx.x;
    const int cg = tid & 31, eg = tid >> 5;
    const int base = blockIdx.x * 32;

    for (int idx = tid; idx < 32 * ND; idx += 256) {
        int k = idx & (ND - 1), n = idx >> 7;
        int node = base + n;
        Xt[k * 33 + n] = (node < N) ? x[(size_t)node * ND + k] : 0.f;
    }
    float cg4[4];
    #pragma unroll
    for (int i = 0; i < 4; i++) {
        int node = base + eg * 4 + i;
        cg4[i] = (node < N) ? cong[node] : 0.f;
    }
    __syncthreads();

    for (int which = 0; which < 2; which++) {
        const float* W = mW1 + (size_t)which * ND * HD;
        u64 acc[4][2][2];
        #pragma unroll
        for (int i = 0; i < 4; i++)
            #pragma unroll
            for (int p = 0; p < 2; p++) { acc[i][p][0] = 0ull; acc[i][p][1] = 0ull; }

        for (int ko = 0; ko < ND; ko += 16) {
            {
                const float4* srcp = (const float4*)(W + (size_t)ko * HD);
                float4* dstp = (float4*)Bs;
                for (int idx = tid; idx < 16 * HD / 4; idx += 256) dstp[idx] = srcp[idx];
            }
            __syncthreads();
            #pragma unroll 4
            for (int kk = 0; kk < 16; kk++) {
                u64 aa[4];
                #pragma unroll
                for (int i = 0; i < 4; i++) aa[i] = dup2(Xt[(ko + kk) * 33 + eg * 4 + i]);
                #pragma unroll
                for (int p = 0; p < 2; p++) {
                    ulonglong2 b = *(const ulonglong2*)&Bs[kk * HD + 4 * cg + 128 * p];
                    #pragma unroll
                    for (int i = 0; i < 4; i++) {
                        acc[i][p][0] = ffma2(aa[i], b.x, acc[i][p][0]);
                        acc[i][p][1] = ffma2(aa[i], b.y, acc[i][p][1]);
                    }
                }
            }
            __syncthreads();
        }
        #pragma unroll
        for (int p = 0; p < 2; p++) {
            if (which == 0) {
                float4 w2 = *(const float4*)&mW1[(size_t)288 * HD + 128 * p + 4 * cg];
                #pragma unroll
                for (int i = 0; i < 4; i++) {
                    int node = base + eg * 4 + i;
                    if (node < N) {
                        float2 v0 = unpk(acc[i][p][0]), v1 = unpk(acc[i][p][1]);
                        float4 r = make_float4(v0.x + cg4[i] * w2.x, v0.y + cg4[i] * w2.y,
                                               v1.x + cg4[i] * w2.z, v1.y + cg4[i] * w2.w);
                        *(float4*)&g_Psrc[(size_t)node * HD + 128 * p + 4 * cg] = r;
                    }
                }
            } else {
                float4 b1 = *(const float4*)&mb1[128 * p + 4 * cg];
                #pragma unroll
                for (int i = 0; i < 4; i++) {
                    int node = base + eg * 4 + i;
                    if (node < N) {
                        float2 v0 = unpk(acc[i][p][0]), v1 = unpk(acc[i][p][1]);
                        float4 r = make_float4(v0.x + b1.x, v0.y + b1.y,
                                               v1.x + b1.z, v1.y + b1.w);
                        *(float4*)&g_Pdst[(size_t)node * HD + 128 * p + 4 * cg] = r;
                    }
                }
            }
        }
    }
    for (int idx = tid; idx < 32 * ND; idx += 256) {
        int node = base + (idx >> 7);
        if (node < N) g_agg[(size_t)node * ND + (idx & (ND - 1))] = 0.f;
    }
}

// =================== K2: warp-MMA edge kernel (v5: plain fp16) ==================
// 128 edges/CTA, 512 threads. Warp w: wm = w&7 (rows 16wm..+15), wn = w>>3 (N half).
// Per 64-col hidden chunk c: PREFETCH gathers -> layer1 MMA -> relu/f16/stage
// -> layer2 MMA, with cp.async double-buffered B2 chunk prefetch.
// smem layout (bytes):
//   B1  @ 0      [256 rows][32 halves]  stride 80    20480
//   A2c @ 20480  [128 rows][64 halves]  stride 144   18432  (A1 [128][80B] aliases)
//   B2  @ 38912  2 bufs x [128 rows][64 halves] st144 36864
//   src @ 75776  int[128];  dst @ 76288 int[128]
#define B1_OFF  0
#define A2_OFF  20480
#define B2_OFF  38912
#define SRC_OFF 75776
#define DST_OFF 76288
#define EDGE_SMEM 76800
#define B1_ST 80
#define A1_ST 80
#define A2_ST 144
#define B2_ST 144
#define B2_BUF 18432

__global__ __launch_bounds__(512, 1) void k_edge_mma(
    const float* __restrict__ edge_attr, const float* __restrict__ mb2, int E)
{
    extern __shared__ __align__(16) char sm[];
    const u32 smu = smem_u32(sm);
    const int tid = threadIdx.x;
    const int w = tid >> 5, l = tid & 31;
    const int wm = w & 7, wn = w >> 3;
    const int g = l >> 2, t = l & 3;
    const int base = blockIdx.x * 128;
    const char* gB2 = (const char*)g_B2h;

    // ---- prefetch B2 chunk 0 into buf 0 (cp.async): 128 rows x 128B ----
    #pragma unroll
    for (int r = 0; r < 2; r++) {
        int i = tid + 512 * r;
        int row = i >> 3, part = i & 7;
        CP_ASYNC16(smu + B2_OFF + row * B2_ST + part * 16,
                   gB2 + row * 512 + part * 16);
    }
    CP_COMMIT();

    // ---- stage src/dst ----
    if (tid < 128) {
        int e = base + tid;
        ((int*)(sm + SRC_OFF))[tid] = (e < E) ? g_src[e] : 0;
        ((int*)(sm + DST_OFF))[tid] = (e < E) ? g_dst[e] : 0;
    }
    // ---- stage B1: 256 rows x 64B ----
    for (int idx = tid; idx < 256 * 4; idx += 512) {
        int row = idx >> 2, ch = idx & 3;
        *(float4*)(sm + B1_OFF + row * B1_ST + ch * 16) =
            *(const float4*)((const char*)g_B1h + row * 64 + ch * 16);
    }
    // ---- stage A1 (aliases A2c region): edge_attr -> fp16 ----
    if (tid < 256) {
        int e = tid >> 1, h = tid & 1;
        char* arow = sm + A2_OFF + e * A1_ST;
        if (base + e < E) {
            const float4* src4 = (const float4*)(edge_attr + (size_t)(base + e) * ED + 16 * h);
            #pragma unroll
            for (int q = 0; q < 4; q++) {
                float4 v = src4[q];
                int k = 16 * h + 4 * q;
                *(u32*)(arow + k * 2)       = h2pack(v.x, v.y);
                *(u32*)(arow + (k + 2) * 2) = h2pack(v.z, v.w);
            }
        } else {
            #pragma unroll
            for (int q = 0; q < 8; q++)
                *(u32*)(arow + (16 * h + 2 * q) * 2) = 0u;
        }
    }
    __syncthreads();

    // per-lane ldmatrix address components
    const int lr   = l & 7;
    const int aRow = 16 * wm + lr + ((l >> 3) & 1) * 8;
    const int aKh  = (l >> 4) * 8;
    const int bRow = lr + (l >> 4) * 8;
    const int bKh  = ((l >> 3) & 1) * 8;
    const u32 a1base = smu + A2_OFF + aRow * A1_ST + aKh * 2;  // A1 alias
    const u32 a2base = smu + A2_OFF + aRow * A2_ST + aKh * 2;

    // A1 fragments (k-tiles 0-15, 16-31), cached for all chunks
    u32 fa[2][4];
    #pragma unroll
    for (int kt = 0; kt < 2; kt++)
        ldsm_x4(a1base + kt * 32, fa[kt][0], fa[kt][1], fa[kt][2], fa[kt][3]);

    // this lane's two edge rows
    const int m0 = 16 * wm + g, m1 = m0 + 8;
    const int vs0 = ((const int*)(sm + SRC_OFF))[m0];
    const int vd0 = ((const int*)(sm + DST_OFF))[m0];
    const int vs1 = ((const int*)(sm + SRC_OFF))[m1];
    const int vd1 = ((const int*)(sm + DST_OFF))[m1];
    char* a2r0 = sm + A2_OFF + m0 * A2_ST;
    char* a2r1 = sm + A2_OFF + m1 * A2_ST;

    float acc2[8][4];
    #pragma unroll
    for (int j = 0; j < 8; j++)
        #pragma unroll
        for (int q = 0; q < 4; q++) acc2[j][q] = 0.f;

    // ================= fused chunk loop =================
    #pragma unroll 1
    for (int c = 0; c < 4; c++) {
        // ---- PREFETCH node-partial gathers (hidden by layer-1 MMA) ----
        float2 ps0[4], pd0[4], ps1[4], pd1[4];
        #pragma unroll
        for (int nt = 0; nt < 4; nt++) {
            int col = 64 * c + 32 * wn + 8 * nt + 2 * t;
            ps0[nt] = *(const float2*)(g_Psrc + (size_t)vs0 * HD + col);
            pd0[nt] = *(const float2*)(g_Pdst + (size_t)vd0 * HD + col);
            ps1[nt] = *(const float2*)(g_Psrc + (size_t)vs1 * HD + col);
            pd1[nt] = *(const float2*)(g_Pdst + (size_t)vd1 * HD + col);
        }

        // ---- layer 1: acc1 = EA @ W1c[:, warp's 32 cols of chunk c] ----
        float acc1[4][4];
        #pragma unroll
        for (int j = 0; j < 4; j++)
            #pragma unroll
            for (int q = 0; q < 4; q++) acc1[j][q] = 0.f;

        #pragma unroll
        for (int jp = 0; jp < 2; jp++) {
            u32 bb = smu + B1_OFF + (64 * c + 32 * wn + 16 * jp + bRow) * B1_ST + bKh * 2;
            u32 b0, b1, b2, b3;
            ldsm_x4(bb + 0, b0, b1, b2, b3);      // k0-15
            mma_f16(acc1[2 * jp],     fa[0][0], fa[0][1], fa[0][2], fa[0][3], b0, b1);
            mma_f16(acc1[2 * jp + 1], fa[0][0], fa[0][1], fa[0][2], fa[0][3], b2, b3);
            ldsm_x4(bb + 32, b0, b1, b2, b3);     // k16-31
            mma_f16(acc1[2 * jp],     fa[1][0], fa[1][1], fa[1][2], fa[1][3], b0, b1);
            mma_f16(acc1[2 * jp + 1], fa[1][0], fa[1][1], fa[1][2], fa[1][3], b2, b3);
        }

        // all warps done with previous layer-2 reads (A2c + B2 buf) before overwrite
        __syncthreads();

        // ---- prefetch B2 chunk c+1 into buf (c+1)&1 ----
        if (c < 3) {
            int buf = (c + 1) & 1;
            #pragma unroll
            for (int r = 0; r < 2; r++) {
                int i = tid + 512 * r;
                int row = i >> 3, part = i & 7;
                CP_ASYNC16(smu + B2_OFF + buf * B2_BUF + row * B2_ST + part * 16,
                           gB2 + row * 512 + 128 * (c + 1) + part * 16);
            }
            CP_COMMIT();
        }

        // ---- epilogue: add prefetched partials, relu, fp16 into A2c ----
        #pragma unroll
        for (int nt = 0; nt < 4; nt++) {
            int lc = 32 * wn + 8 * nt + 2 * t;
            float v00 = fmaxf(acc1[nt][0] + ps0[nt].x + pd0[nt].x, 0.f);
            float v01 = fmaxf(acc1[nt][1] + ps0[nt].y + pd0[nt].y, 0.f);
            float v10 = fmaxf(acc1[nt][2] + ps1[nt].x + pd1[nt].x, 0.f);
            float v11 = fmaxf(acc1[nt][3] + ps1[nt].y + pd1[nt].y, 0.f);
            *(u32*)(a2r0 + lc * 2) = h2pack(v00, v01);
            *(u32*)(a2r1 + lc * 2) = h2pack(v10, v11);
        }

        if (c < 3) { CP_WAIT(1); } else { CP_WAIT(0); }
        __syncthreads();

        // ---- layer 2: acc2 += h_chunk @ W2_chunk ----
        const u32 b2b = smu + B2_OFF + (c & 1) * B2_BUF;
        #pragma unroll
        for (int t4 = 0; t4 < 4; t4++) {
            u32 ah0, ah1, ah2, ah3;
            ldsm_x4(a2base + t4 * 32, ah0, ah1, ah2, ah3);
            #pragma unroll
            for (int jp = 0; jp < 4; jp++) {
                u32 nrow = (u32)(64 * wn + 16 * jp + bRow);
                u32 kof  = (u32)(16 * t4 + bKh) * 2;
                u32 b0, b1, b2, b3;
                ldsm_x4(b2b + nrow * B2_ST + kof, b0, b1, b2, b3);
                mma_f16(acc2[2 * jp],     ah0, ah1, ah2, ah3, b0, b1);
                mma_f16(acc2[2 * jp + 1], ah0, ah1, ah2, ah3, b2, b3);
            }
        }
    }

    // ---- scatter: + mb2, red.v2 into g_agg[dst] ----
    const bool e0 = (base + m0 < E), e1 = (base + m1 < E);
    #pragma unroll
    for (int j = 0; j < 8; j++) {
        int n = 64 * wn + 8 * j + 2 * t;
        float2 bv = *(const float2*)(mb2 + n);
        if (e0) {
            float x0 = acc2[j][0] + bv.x, x1 = acc2[j][1] + bv.y;
            asm volatile("red.global.add.v2.f32 [%0], {%1, %2};"
                         :: "l"(g_agg + (size_t)vd0 * ND + n), "f"(x0), "f"(x1) : "memory");
        }
        if (e1) {
            float x0 = acc2[j][2] + bv.x, x1 = acc2[j][3] + bv.y;
            asm volatile("red.global.add.v2.f32 [%0], {%1, %2};"
                         :: "l"(g_agg + (size_t)vd1 * ND + n), "f"(x0), "f"(x1) : "memory");
        }
    }
}

// =================== K3: node update MLP (scalar, proven) =======================
#define K3_SMEM (16640 * 4)
__global__ __launch_bounds__(256) void k_update(
    const float* __restrict__ x,
    const float* __restrict__ uW1, const float* __restrict__ ub1,
    const float* __restrict__ uW2, const float* __restrict__ ub2,
    float* __restrict__ out, int N)
{
    extern __shared__ __align__(16) float smf[];
    float* At = smf;
    float* Ht = smf;
    float* Ws = smf + 8448;
    float* B2 = smf + 8448;

    const int tid = threadIdx.x;
    const int cg = tid & 31, eg = tid >> 5;
    const int base = blockIdx.x * 32;

    for (int idx = tid; idx < 32 * HD; idx += 256) {
        int k = idx & (HD - 1), n = idx >> 8;
        int node = base + n;
        float v = 0.f;
        if (node < N)
            v = (k < ND) ? x[(size_t)node * ND + k]
                         : g_agg[(size_t)node * ND + (k - ND)];
        At[k * 33 + n] = v;
    }
    __syncthreads();

    u64 acc[4][2][2];
    #pragma unroll
    for (int i = 0; i < 4; i++)
        #pragma unroll
        for (int p = 0; p < 2; p++) { acc[i][p][0] = 0ull; acc[i][p][1] = 0ull; }

    for (int ko = 0; ko < HD; ko += 32) {
        {
            const float4* srcp = (const float4*)(uW1 + (size_t)ko * HD);
            float4* dstp = (float4*)Ws;
            for (int idx = tid; idx < 32 * HD / 4; idx += 256) dstp[idx] = srcp[idx];
        }
        __syncthreads();
        #pragma unroll 4
        for (int kk = 0; kk < 32; kk++) {
            u64 aa[4];
            #pragma unroll
            for (int i = 0; i < 4; i++) aa[i] = dup2(At[(ko + kk) * 33 + eg * 4 + i]);
            #pragma unroll
            for (int p = 0; p < 2; p++) {
                ulonglong2 b = *(const ulonglong2*)&Ws[kk * HD + 4 * cg + 128 * p];
                #pragma unroll
                for (int i = 0; i < 4; i++) {
                    acc[i][p][0] = ffma2(aa[i], b.x, acc[i][p][0]);
                    acc[i][p][1] = ffma2(aa[i], b.y, acc[i][p][1]);
                }
            }
        }
        __syncthreads();
    }

    #pragma unroll
    for (int p = 0; p < 2; p++) {
        float4 b1 = *(const float4*)&ub1[128 * p + 4 * cg];
        #pragma unroll
        for (int i = 0; i < 4; i++) {
            int n = eg * 4 + i;
            int jb = 128 * p + 4 * cg;
            float2 v0 = unpk(acc[i][p][0]), v1 = unpk(acc[i][p][1]);
            bool ok = (base + n < N);
            Ht[(jb + 0) * 33 + n] = ok ? fmaxf(v0.x + b1.x, 0.f) : 0.f;
            Ht[(jb + 1) * 33 + n] = ok ? fmaxf(v0.y + b1.y, 0.f) : 0.f;
            Ht[(jb + 2) * 33 + n] = ok ? fmaxf(v1.x + b1.z, 0.f) : 0.f;
            Ht[(jb + 3) * 33 + n] = ok ? fmaxf(v1.y + b1.w, 0.f) : 0.f;
        }
    }
    __syncthreads();

    u64 acc2[4][2];
    #pragma unroll
    for (int i = 0; i < 4; i++) { acc2[i][0] = 0ull; acc2[i][1] = 0ull; }

    for (int ko = 0; ko < HD; ko += 32) {
        {
            const float4* srcp = (const float4*)(uW2 + (size_t)ko * ND);
            float4* dstp = (float4*)B2;
            for (int idx = tid; idx < 32 * ND / 4; idx += 256) dstp[idx] = srcp[idx];
        }
        __syncthreads();
        #pragma unroll 4
        for (int kk = 0; kk < 32; kk++) {
            ulonglong2 b = *(const ulonglong2*)&B2[kk * ND + 4 * cg];
            #pragma unroll
            for (int i = 0; i < 4; i++) {
                u64 aa = dup2(Ht[(ko + kk) * 33 + eg * 4 + i]);
                acc2[i][0] = ffma2(aa, b.x, acc2[i][0]);
                acc2[i][1] = ffma2(aa, b.y, acc2[i][1]);
            }
        }
        __syncthreads();
    }

    float4 b2v = *(const float4*)&ub2[4 * cg];
    #pragma unroll
    for (int i = 0; i < 4; i++) {
        int node = base + eg * 4 + i;
        if (node < N) {
            float2 m0 = unpk(acc2[i][0]), m1 = unpk(acc2[i][1]);
            float4 r = make_float4(m0.x + b2v.x, m0.y + b2v.y, m1.x + b2v.z, m1.y + b2v.w);
            *(float4*)&out[(size_t)node * ND + 4 * cg] = r;
        }
    }
}

// =================== launcher ===================================================
extern "C" void kernel_launch(void* const* d_in, const int* in_sizes, int n_in,
                              void* d_out, int out_size)
{
    const float* x    = (const float*)d_in[0];
    const int*   ei   = (const int*)  d_in[1];
    const float* ea   = (const float*)d_in[2];
    const float* cong = (const float*)d_in[3];
    const float* mW1  = (const float*)d_in[4];
    const float* mb1  = (const float*)d_in[5];
    const float* mW2  = (const float*)d_in[6];
    const float* mb2  = (const float*)d_in[7];
    const float* uW1  = (const float*)d_in[8];
    const float* ub1  = (const float*)d_in[9];
    const float* uW2  = (const float*)d_in[10];
    const float* ub2  = (const float*)d_in[11];

    int N = in_sizes[0] / ND;
    int E = in_sizes[1] / 2;
    if (N > N_MAX) N = N_MAX;
    if (E > E_MAX) E = E_MAX;

    cudaFuncSetAttribute(k_edge_mma, cudaFuncAttributeMaxDynamicSharedMemorySize, EDGE_SMEM);
    cudaFuncSetAttribute(k_update,   cudaFuncAttributeMaxDynamicSharedMemorySize, K3_SMEM);

    k_convert  <<<(E + 255) / 256, 256>>>(ei, E);
    k_prep     <<<160, 256>>>(mW1, mW2);
    k_node_pre <<<(N + 31) / 32, 256>>>(x, cong, mW1, mb1, N);
    k_edge_mma <<<(E + 127) / 128, 512, EDGE_SMEM>>>(ea, mb2, E);
    k_update   <<<(N + 31) / 32, 256, K3_SMEM>>>(x, uW1, ub1, uW2, ub2, (float*)d_out, N);
}

// round 9
// speedup vs baseline: 1.4472x; 1.0622x over previous
#include <cuda_runtime.h>
#include <cuda_fp16.h>
#include <cstdint>

#define ND 128
#define ED 32
#define HD 256
#define N_MAX 100000
#define E_MAX 1600000

typedef unsigned long long u64;
typedef unsigned int u32;

// ---------------- packed f32x2 helpers (scalar kernels) ----------------
__device__ __forceinline__ u64 ffma2(u64 a, u64 b, u64 c) {
    u64 d;
    asm("fma.rn.f32x2 %0, %1, %2, %3;" : "=l"(d) : "l"(a), "l"(b), "l"(c));
    return d;
}
__device__ __forceinline__ u64 dup2(float x) {
    u64 d;
    asm("mov.b64 %0, {%1, %1};" : "=l"(d) : "f"(x));
    return d;
}
__device__ __forceinline__ float2 unpk(u64 p) {
    float2 r;
    asm("mov.b64 {%0, %1}, %2;" : "=f"(r.x), "=f"(r.y) : "l"(p));
    return r;
}

// ---------------- warp-MMA helpers (family-compatible: sm_80+) ----------------
__device__ __forceinline__ u32 smem_u32(const void* p) {
    u32 a;
    asm("{ .reg .u64 t; cvta.to.shared.u64 t, %1; cvt.u32.u64 %0, t; }" : "=r"(a) : "l"(p));
    return a;
}
__device__ __forceinline__ void ldsm_x4(u32 addr, u32& r0, u32& r1, u32& r2, u32& r3) {
    asm volatile("ldmatrix.sync.aligned.m8n8.x4.shared.b16 {%0,%1,%2,%3}, [%4];"
        : "=r"(r0), "=r"(r1), "=r"(r2), "=r"(r3) : "r"(addr));
}
__device__ __forceinline__ void mma_f16(float* d, u32 a0, u32 a1, u32 a2, u32 a3,
                                        u32 b0, u32 b1) {
    asm volatile("mma.sync.aligned.m16n8k16.row.col.f32.f16.f16.f32 "
        "{%0,%1,%2,%3}, {%4,%5,%6,%7}, {%8,%9}, {%0,%1,%2,%3};"
        : "+f"(d[0]), "+f"(d[1]), "+f"(d[2]), "+f"(d[3])
        : "r"(a0), "r"(a1), "r"(a2), "r"(a3), "r"(b0), "r"(b1));
}
__device__ __forceinline__ u32 h2pack(float a, float b) {
    __half2 h = __floats2half2_rn(a, b);
    return *(u32*)&h;
}
__device__ __forceinline__ float2 h2unpack(u32 p) {
    return __half22float2(*(__half2*)&p);
}
#define CP_ASYNC16(d, s) asm volatile("cp.async.cg.shared.global [%0], [%1], 16;" :: "r"(d), "l"(s) : "memory")
#define CP_COMMIT()      asm volatile("cp.async.commit_group;" ::: "memory")
#define CP_WAIT(n)       asm volatile("cp.async.wait_group %0;" :: "n"(n) : "memory")

// ---------------- scratch ----------------
__device__ int   g_src[E_MAX];
__device__ int   g_dst[E_MAX];
// fp16 node partials: 2 x 100k x 256 x 2B = 102 MB total -> fits in 126 MB L2
__device__ __align__(16) __half g_Psrc[(size_t)N_MAX * HD];
__device__ __align__(16) __half g_Pdst[(size_t)N_MAX * HD];
__device__ float g_agg [(size_t)N_MAX * ND];
// fp16 weight images (row-major, [n][k])
__device__ __align__(16) __half g_B1h[256 * 32];   // W1c^T  [n=256][k=32]
__device__ __align__(16) __half g_B2h[128 * 256];  // W2^T   [n=128][k=256]

// =================== K0: edge_index convert (int64 OR int32) ===================
__global__ void k_convert(const int* __restrict__ w, int E)
{
    __shared__ int s64;
    if (threadIdx.x == 0) {
        int b = 1;
        #pragma unroll
        for (int i = 0; i < 8; i++) if (w[2 * i + 1] != 0) b = 0;
        s64 = b;
    }
    __syncthreads();
    int i = blockIdx.x * blockDim.x + threadIdx.x;
    if (i >= E) return;
    if (s64) {
        const long long* e = (const long long*)w;
        g_src[i] = (int)e[i];
        g_dst[i] = (int)e[(size_t)E + i];
    } else {
        g_src[i] = w[i];
        g_dst[i] = w[(size_t)E + i];
    }
}

// =================== K_prep: build fp16 weight images ===========================
__global__ void k_prep(const float* __restrict__ mW1, const float* __restrict__ mW2)
{
    int tid = blockIdx.x * blockDim.x + threadIdx.x;
    int total = 256 * 32 + 128 * 256;
    for (int i = tid; i < total; i += gridDim.x * blockDim.x) {
        if (i < 256 * 32) {
            int n = i >> 5, k = i & 31;                 // W1c[k][n]
            g_B1h[n * 32 + k] = __float2half(mW1[(size_t)(2 * ND + k) * HD + n]);
        } else {
            int q = i - 256 * 32;
            int n = q >> 8, j = q & 255;                // W2[j][n]
            g_B2h[n * 256 + j] = __float2half(mW2[(size_t)j * ND + n]);
        }
    }
}

// =================== K1: per-node precompute (scalar; fp16 partial store) =======
__global__ __launch_bounds__(256) void k_node_pre(
    const float* __restrict__ x, const float* __restrict__ cong,
    const float* __restrict__ mW1, const float* __restrict__ mb1, int N)
{
    __shared__ __align__(16) float Xt[ND * 33];
    __shared__ __align__(16) float Bs[16 * HD];
    const int tid = threadIdx.x;
    const int cg = tid & 31, eg = tid >> 5;
    const int base = blockIdx.x * 32;

    for (int idx = tid; idx < 32 * ND; idx += 256) {
        int k = idx & (ND - 1), n = idx >> 7;
        int node = base + n;
        Xt[k * 33 + n] = (node < N) ? x[(size_t)node * ND + k] : 0.f;
    }
    float cg4[4];
    #pragma unroll
    for (int i = 0; i < 4; i++) {
        int node = base + eg * 4 + i;
        cg4[i] = (node < N) ? cong[node] : 0.f;
    }
    __syncthreads();

    for (int which = 0; which < 2; which++) {
        const float* W = mW1 + (size_t)which * ND * HD;
        u64 acc[4][2][2];
        #pragma unroll
        for (int i = 0; i < 4; i++)
            #pragma unroll
            for (int p = 0; p < 2; p++) { acc[i][p][0] = 0ull; acc[i][p][1] = 0ull; }

        for (int ko = 0; ko < ND; ko += 16) {
            {
                const float4* srcp = (const float4*)(W + (size_t)ko * HD);
                float4* dstp = (float4*)Bs;
                for (int idx = tid; idx < 16 * HD / 4; idx += 256) dstp[idx] = srcp[idx];
            }
            __syncthreads();
            #pragma unroll 4
            for (int kk = 0; kk < 16; kk++) {
                u64 aa[4];
                #pragma unroll
                for (int i = 0; i < 4; i++) aa[i] = dup2(Xt[(ko + kk) * 33 + eg * 4 + i]);
                #pragma unroll
                for (int p = 0; p < 2; p++) {
                    ulonglong2 b = *(const ulonglong2*)&Bs[kk * HD + 4 * cg + 128 * p];
                    #pragma unroll
                    for (int i = 0; i < 4; i++) {
                        acc[i][p][0] = ffma2(aa[i], b.x, acc[i][p][0]);
                        acc[i][p][1] = ffma2(aa[i], b.y, acc[i][p][1]);
                    }
                }
            }
            __syncthreads();
        }
        #pragma unroll
        for (int p = 0; p < 2; p++) {
            if (which == 0) {
                float4 w2 = *(const float4*)&mW1[(size_t)288 * HD + 128 * p + 4 * cg];
                #pragma unroll
                for (int i = 0; i < 4; i++) {
                    int node = base + eg * 4 + i;
                    if (node < N) {
                        float2 v0 = unpk(acc[i][p][0]), v1 = unpk(acc[i][p][1]);
                        uint2 hh = make_uint2(
                            h2pack(v0.x + cg4[i] * w2.x, v0.y + cg4[i] * w2.y),
                            h2pack(v1.x + cg4[i] * w2.z, v1.y + cg4[i] * w2.w));
                        *(uint2*)&g_Psrc[(size_t)node * HD + 128 * p + 4 * cg] = hh;
                    }
                }
            } else {
                float4 b1 = *(const float4*)&mb1[128 * p + 4 * cg];
                #pragma unroll
                for (int i = 0; i < 4; i++) {
                    int node = base + eg * 4 + i;
                    if (node < N) {
                        float2 v0 = unpk(acc[i][p][0]), v1 = unpk(acc[i][p][1]);
                        uint2 hh = make_uint2(
                            h2pack(v0.x + b1.x, v0.y + b1.y),
                            h2pack(v1.x + b1.z, v1.y + b1.w));
                        *(uint2*)&g_Pdst[(size_t)node * HD + 128 * p + 4 * cg] = hh;
                    }
                }
            }
        }
    }
    for (int idx = tid; idx < 32 * ND; idx += 256) {
        int node = base + (idx >> 7);
        if (node < N) g_agg[(size_t)node * ND + (idx & (ND - 1))] = 0.f;
    }
}

// =================== K2: warp-MMA edge kernel (v6: fp16 + fp16 gathers) =========
// 128 edges/CTA, 512 threads. Warp w: wm = w&7 (rows 16wm..+15), wn = w>>3 (N half).
// smem layout (bytes):
//   B1  @ 0      [256 rows][32 halves]  stride 80    20480
//   A2c @ 20480  [128 rows][64 halves]  stride 144   18432  (A1 [128][80B] aliases)
//   B2  @ 38912  2 bufs x [128 rows][64 halves] st144 36864
//   src @ 75776  int[128];  dst @ 76288 int[128]
#define B1_OFF  0
#define A2_OFF  20480
#define B2_OFF  38912
#define SRC_OFF 75776
#define DST_OFF 76288
#define EDGE_SMEM 76800
#define B1_ST 80
#define A1_ST 80
#define A2_ST 144
#define B2_ST 144
#define B2_BUF 18432

__global__ __launch_bounds__(512, 1) void k_edge_mma(
    const float* __restrict__ edge_attr, const float* __restrict__ mb2, int E)
{
    extern __shared__ __align__(16) char sm[];
    const u32 smu = smem_u32(sm);
    const int tid = threadIdx.x;
    const int w = tid >> 5, l = tid & 31;
    const int wm = w & 7, wn = w >> 3;
    const int g = l >> 2, t = l & 3;
    const int base = blockIdx.x * 128;
    const char* gB2 = (const char*)g_B2h;

    // ---- prefetch B2 chunk 0 into buf 0 (cp.async): 128 rows x 128B ----
    #pragma unroll
    for (int r = 0; r < 2; r++) {
        int i = tid + 512 * r;
        int row = i >> 3, part = i & 7;
        CP_ASYNC16(smu + B2_OFF + row * B2_ST + part * 16,
                   gB2 + row * 512 + part * 16);
    }
    CP_COMMIT();

    // ---- stage src/dst ----
    if (tid < 128) {
        int e = base + tid;
        ((int*)(sm + SRC_OFF))[tid] = (e < E) ? g_src[e] : 0;
        ((int*)(sm + DST_OFF))[tid] = (e < E) ? g_dst[e] : 0;
    }
    // ---- stage B1: 256 rows x 64B ----
    for (int idx = tid; idx < 256 * 4; idx += 512) {
        int row = idx >> 2, ch = idx & 3;
        *(float4*)(sm + B1_OFF + row * B1_ST + ch * 16) =
            *(const float4*)((const char*)g_B1h + row * 64 + ch * 16);
    }
    // ---- stage A1 (aliases A2c region): edge_attr -> fp16 ----
    if (tid < 256) {
        int e = tid >> 1, h = tid & 1;
        char* arow = sm + A2_OFF + e * A1_ST;
        if (base + e < E) {
            const float4* src4 = (const float4*)(edge_attr + (size_t)(base + e) * ED + 16 * h);
            #pragma unroll
            for (int q = 0; q < 4; q++) {
                float4 v = src4[q];
                int k = 16 * h + 4 * q;
                *(u32*)(arow + k * 2)       = h2pack(v.x, v.y);
                *(u32*)(arow + (k + 2) * 2) = h2pack(v.z, v.w);
            }
        } else {
            #pragma unroll
            for (int q = 0; q < 8; q++)
                *(u32*)(arow + (16 * h + 2 * q) * 2) = 0u;
        }
    }
    __syncthreads();

    // per-lane ldmatrix address components
    const int lr   = l & 7;
    const int aRow = 16 * wm + lr + ((l >> 3) & 1) * 8;
    const int aKh  = (l >> 4) * 8;
    const int bRow = lr + (l >> 4) * 8;
    const int bKh  = ((l >> 3) & 1) * 8;
    const u32 a1base = smu + A2_OFF + aRow * A1_ST + aKh * 2;  // A1 alias
    const u32 a2base = smu + A2_OFF + aRow * A2_ST + aKh * 2;

    // A1 fragments (k-tiles 0-15, 16-31), cached for all chunks
    u32 fa[2][4];
    #pragma unroll
    for (int kt = 0; kt < 2; kt++)
        ldsm_x4(a1base + kt * 32, fa[kt][0], fa[kt][1], fa[kt][2], fa[kt][3]);

    // this lane's two edge rows
    const int m0 = 16 * wm + g, m1 = m0 + 8;
    const int vs0 = ((const int*)(sm + SRC_OFF))[m0];
    const int vd0 = ((const int*)(sm + DST_OFF))[m0];
    const int vs1 = ((const int*)(sm + SRC_OFF))[m1];
    const int vd1 = ((const int*)(sm + DST_OFF))[m1];
    char* a2r0 = sm + A2_OFF + m0 * A2_ST;
    char* a2r1 = sm + A2_OFF + m1 * A2_ST;

    float acc2[8][4];
    #pragma unroll
    for (int j = 0; j < 8; j++)
        #pragma unroll
        for (int q = 0; q < 4; q++) acc2[j][q] = 0.f;

    // ================= fused chunk loop =================
    #pragma unroll 1
    for (int c = 0; c < 4; c++) {
        // ---- PREFETCH fp16 node-partial gathers (hidden by layer-1 MMA) ----
        u32 ps0[4], pd0[4], ps1[4], pd1[4];
        #pragma unroll
        for (int nt = 0; nt < 4; nt++) {
            int col = 64 * c + 32 * wn + 8 * nt + 2 * t;
            ps0[nt] = *(const u32*)(g_Psrc + (size_t)vs0 * HD + col);
            pd0[nt] = *(const u32*)(g_Pdst + (size_t)vd0 * HD + col);
            ps1[nt] = *(const u32*)(g_Psrc + (size_t)vs1 * HD + col);
            pd1[nt] = *(const u32*)(g_Pdst + (size_t)vd1 * HD + col);
        }

        // ---- layer 1: acc1 = EA @ W1c[:, warp's 32 cols of chunk c] ----
        float acc1[4][4];
        #pragma unroll
        for (int j = 0; j < 4; j++)
            #pragma unroll
            for (int q = 0; q < 4; q++) acc1[j][q] = 0.f;

        #pragma unroll
        for (int jp = 0; jp < 2; jp++) {
            u32 bb = smu + B1_OFF + (64 * c + 32 * wn + 16 * jp + bRow) * B1_ST + bKh * 2;
            u32 b0, b1, b2, b3;
            ldsm_x4(bb + 0, b0, b1, b2, b3);      // k0-15
            mma_f16(acc1[2 * jp],     fa[0][0], fa[0][1], fa[0][2], fa[0][3], b0, b1);
            mma_f16(acc1[2 * jp + 1], fa[0][0], fa[0][1], fa[0][2], fa[0][3], b2, b3);
            ldsm_x4(bb + 32, b0, b1, b2, b3);     // k16-31
            mma_f16(acc1[2 * jp],     fa[1][0], fa[1][1], fa[1][2], fa[1][3], b0, b1);
            mma_f16(acc1[2 * jp + 1], fa[1][0], fa[1][1], fa[1][2], fa[1][3], b2, b3);
        }

        // all warps done with previous layer-2 reads (A2c + B2 buf) before overwrite
        __syncthreads();

        // ---- prefetch B2 chunk c+1 into buf (c+1)&1 ----
        if (c < 3) {
            int buf = (c + 1) & 1;
            #pragma unroll
            for (int r = 0; r < 2; r++) {
                int i = tid + 512 * r;
                int row = i >> 3, part = i & 7;
                CP_ASYNC16(smu + B2_OFF + buf * B2_BUF + row * B2_ST + part * 16,
                           gB2 + row * 512 + 128 * (c + 1) + part * 16);
            }
            CP_COMMIT();
        }

        // ---- epilogue: add prefetched partials, relu, fp16 into A2c ----
        #pragma unroll
        for (int nt = 0; nt < 4; nt++) {
            int lc = 32 * wn + 8 * nt + 2 * t;
            float2 a0 = h2unpack(ps0[nt]), b0 = h2unpack(pd0[nt]);
            float2 a1 = h2unpack(ps1[nt]), b1 = h2unpack(pd1[nt]);
            float v00 = fmaxf(acc1[nt][0] + a0.x + b0.x, 0.f);
            float v01 = fmaxf(acc1[nt][1] + a0.y + b0.y, 0.f);
            float v10 = fmaxf(acc1[nt][2] + a1.x + b1.x, 0.f);
            float v11 = fmaxf(acc1[nt][3] + a1.y + b1.y, 0.f);
            *(u32*)(a2r0 + lc * 2) = h2pack(v00, v01);
            *(u32*)(a2r1 + lc * 2) = h2pack(v10, v11);
        }

        if (c < 3) { CP_WAIT(1); } else { CP_WAIT(0); }
        __syncthreads();

        // ---- layer 2: acc2 += h_chunk @ W2_chunk ----
        const u32 b2b = smu + B2_OFF + (c & 1) * B2_BUF;
        #pragma unroll
        for (int t4 = 0; t4 < 4; t4++) {
            u32 ah0, ah1, ah2, ah3;
            ldsm_x4(a2base + t4 * 32, ah0, ah1, ah2, ah3);
            #pragma unroll
            for (int jp = 0; jp < 4; jp++) {
                u32 nrow = (u32)(64 * wn + 16 * jp + bRow);
                u32 kof  = (u32)(16 * t4 + bKh) * 2;
                u32 b0, b1, b2, b3;
                ldsm_x4(b2b + nrow * B2_ST + kof, b0, b1, b2, b3);
                mma_f16(acc2[2 * jp],     ah0, ah1, ah2, ah3, b0, b1);
                mma_f16(acc2[2 * jp + 1], ah0, ah1, ah2, ah3, b2, b3);
            }
        }
    }

    // ---- scatter: + mb2, red.v2 into g_agg[dst] ----
    const bool e0 = (base + m0 < E), e1 = (base + m1 < E);
    #pragma unroll
    for (int j = 0; j < 8; j++) {
        int n = 64 * wn + 8 * j + 2 * t;
        float2 bv = *(const float2*)(mb2 + n);
        if (e0) {
            float x0 = acc2[j][0] + bv.x, x1 = acc2[j][1] + bv.y;
            asm volatile("red.global.add.v2.f32 [%0], {%1, %2};"
                         :: "l"(g_agg + (size_t)vd0 * ND + n), "f"(x0), "f"(x1) : "memory");
        }
        if (e1) {
            float x0 = acc2[j][2] + bv.x, x1 = acc2[j][3] + bv.y;
            asm volatile("red.global.add.v2.f32 [%0], {%1, %2};"
                         :: "l"(g_agg + (size_t)vd1 * ND + n), "f"(x0), "f"(x1) : "memory");
        }
    }
}

// =================== K3: node update MLP (scalar, proven) =======================
#define K3_SMEM (16640 * 4)
__global__ __launch_bounds__(256) void k_update(
    const float* __restrict__ x,
    const float* __restrict__ uW1, const float* __restrict__ ub1,
    const float* __restrict__ uW2, const float* __restrict__ ub2,
    float* __restrict__ out, int N)
{
    extern __shared__ __align__(16) float smf[];
    float* At = smf;
    float* Ht = smf;
    float* Ws = smf + 8448;
    float* B2 = smf + 8448;

    const int tid = threadIdx.x;
    const int cg = tid & 31, eg = tid >> 5;
    const int base = blockIdx.x * 32;

    for (int idx = tid; idx < 32 * HD; idx += 256) {
        int k = idx & (HD - 1), n = idx >> 8;
        int node = base + n;
        float v = 0.f;
        if (node < N)
            v = (k < ND) ? x[(size_t)node * ND + k]
                         : g_agg[(size_t)node * ND + (k - ND)];
        At[k * 33 + n] = v;
    }
    __syncthreads();

    u64 acc[4][2][2];
    #pragma unroll
    for (int i = 0; i < 4; i++)
        #pragma unroll
        for (int p = 0; p < 2; p++) { acc[i][p][0] = 0ull; acc[i][p][1] = 0ull; }

    for (int ko = 0; ko < HD; ko += 32) {
        {
            const float4* srcp = (const float4*)(uW1 + (size_t)ko * HD);
            float4* dstp = (float4*)Ws;
            for (int idx = tid; idx < 32 * HD / 4; idx += 256) dstp[idx] = srcp[idx];
        }
        __syncthreads();
        #pragma unroll 4
        for (int kk = 0; kk < 32; kk++) {
            u64 aa[4];
            #pragma unroll
            for (int i = 0; i < 4; i++) aa[i] = dup2(At[(ko + kk) * 33 + eg * 4 + i]);
            #pragma unroll
            for (int p = 0; p < 2; p++) {
                ulonglong2 b = *(const ulonglong2*)&Ws[kk * HD + 4 * cg + 128 * p];
                #pragma unroll
                for (int i = 0; i < 4; i++) {
                    acc[i][p][0] = ffma2(aa[i], b.x, acc[i][p][0]);
                    acc[i][p][1] = ffma2(aa[i], b.y, acc[i][p][1]);
                }
            }
        }
        __syncthreads();
    }

    #pragma unroll
    for (int p = 0; p < 2; p++) {
        float4 b1 = *(const float4*)&ub1[128 * p + 4 * cg];
        #pragma unroll
        for (int i = 0; i < 4; i++) {
            int n = eg * 4 + i;
            int jb = 128 * p + 4 * cg;
            float2 v0 = unpk(acc[i][p][0]), v1 = unpk(acc[i][p][1]);
            bool ok = (base + n < N);
            Ht[(jb + 0) * 33 + n] = ok ? fmaxf(v0.x + b1.x, 0.f) : 0.f;
            Ht[(jb + 1) * 33 + n] = ok ? fmaxf(v0.y + b1.y, 0.f) : 0.f;
            Ht[(jb + 2) * 33 + n] = ok ? fmaxf(v1.x + b1.z, 0.f) : 0.f;
            Ht[(jb + 3) * 33 + n] = ok ? fmaxf(v1.y + b1.w, 0.f) : 0.f;
        }
    }
    __syncthreads();

    u64 acc2[4][2];
    #pragma unroll
    for (int i = 0; i < 4; i++) { acc2[i][0] = 0ull; acc2[i][1] = 0ull; }

    for (int ko = 0; ko < HD; ko += 32) {
        {
            const float4* srcp = (const float4*)(uW2 + (size_t)ko * ND);
            float4* dstp = (float4*)B2;
            for (int idx = tid; idx < 32 * ND / 4; idx += 256) dstp[idx] = srcp[idx];
        }
        __syncthreads();
        #pragma unroll 4
        for (int kk = 0; kk < 32; kk++) {
            ulonglong2 b = *(const ulonglong2*)&B2[kk * ND + 4 * cg];
            #pragma unroll
            for (int i = 0; i < 4; i++) {
                u64 aa = dup2(Ht[(ko + kk) * 33 + eg * 4 + i]);
                acc2[i][0] = ffma2(aa, b.x, acc2[i][0]);
                acc2[i][1] = ffma2(aa, b.y, acc2[i][1]);
            }
        }
        __syncthreads();
    }

    float4 b2v = *(const float4*)&ub2[4 * cg];
    #pragma unroll
    for (int i = 0; i < 4; i++) {
        int node = base + eg * 4 + i;
        if (node < N) {
            float2 m0 = unpk(acc2[i][0]), m1 = unpk(acc2[i][1]);
            float4 r = make_float4(m0.x + b2v.x, m0.y + b2v.y, m1.x + b2v.z, m1.y + b2v.w);
            *(float4*)&out[(size_t)node * ND + 4 * cg] = r;
        }
    }
}

// =================== launcher ===================================================
extern "C" void kernel_launch(void* const* d_in, const int* in_sizes, int n_in,
                              void* d_out, int out_size)
{
    const float* x    = (const float*)d_in[0];
    const int*   ei   = (const int*)  d_in[1];
    const float* ea   = (const float*)d_in[2];
    const float* cong = (const float*)d_in[3];
    const float* mW1  = (const float*)d_in[4];
    const float* mb1  = (const float*)d_in[5];
    const float* mW2  = (const float*)d_in[6];
    const float* mb2  = (const float*)d_in[7];
    const float* uW1  = (const float*)d_in[8];
    const float* ub1  = (const float*)d_in[9];
    const float* uW2  = (const float*)d_in[10];
    const float* ub2  = (const float*)d_in[11];

    int N = in_sizes[0] / ND;
    int E = in_sizes[1] / 2;
    if (N > N_MAX) N = N_MAX;
    if (E > E_MAX) E = E_MAX;

    cudaFuncSetAttribute(k_edge_mma, cudaFuncAttributeMaxDynamicSharedMemorySize, EDGE_SMEM);
    cudaFuncSetAttribute(k_update,   cudaFuncAttributeMaxDynamicSharedMemorySize, K3_SMEM);

    k_convert  <<<(E + 255) / 256, 256>>>(ei, E);
    k_prep     <<<160, 256>>>(mW1, mW2);
    k_node_pre <<<(N + 31) / 32, 256>>>(x, cong, mW1, mb1, N);
    k_edge_mma <<<(E + 127) / 128, 512, EDGE_SMEM>>>(ea, mb2, E);
    k_update   <<<(N + 31) / 32, 256, K3_SMEM>>>(x, uW1, ub1, uW2, ub2, (float*)d_out, N);
}

// round 10
// speedup vs baseline: 1.7875x; 1.2351x over previous
#include <cuda_runtime.h>
#include <cuda_fp16.h>
#include <cstdint>

#define ND 128
#define ED 32
#define HD 256
#define N_MAX 100000
#define E_MAX 1600000

typedef unsigned long long u64;
typedef unsigned int u32;

// ---------------- packed f32x2 helpers (scalar kernels) ----------------
__device__ __forceinline__ u64 ffma2(u64 a, u64 b, u64 c) {
    u64 d;
    asm("fma.rn.f32x2 %0, %1, %2, %3;" : "=l"(d) : "l"(a), "l"(b), "l"(c));
    return d;
}
__device__ __forceinline__ u64 dup2(float x) {
    u64 d;
    asm("mov.b64 %0, {%1, %1};" : "=l"(d) : "f"(x));
    return d;
}
__device__ __forceinline__ float2 unpk(u64 p) {
    float2 r;
    asm("mov.b64 {%0, %1}, %2;" : "=f"(r.x), "=f"(r.y) : "l"(p));
    return r;
}

// ---------------- warp-MMA helpers (family-compatible: sm_80+) ----------------
__device__ __forceinline__ u32 smem_u32(const void* p) {
    u32 a;
    asm("{ .reg .u64 t; cvta.to.shared.u64 t, %1; cvt.u32.u64 %0, t; }" : "=r"(a) : "l"(p));
    return a;
}
__device__ __forceinline__ void ldsm_x4(u32 addr, u32& r0, u32& r1, u32& r2, u32& r3) {
    asm volatile("ldmatrix.sync.aligned.m8n8.x4.shared.b16 {%0,%1,%2,%3}, [%4];"
        : "=r"(r0), "=r"(r1), "=r"(r2), "=r"(r3) : "r"(addr));
}
__device__ __forceinline__ void mma_f16(float* d, u32 a0, u32 a1, u32 a2, u32 a3,
                                        u32 b0, u32 b1) {
    asm volatile("mma.sync.aligned.m16n8k16.row.col.f32.f16.f16.f32 "
        "{%0,%1,%2,%3}, {%4,%5,%6,%7}, {%8,%9}, {%0,%1,%2,%3};"
        : "+f"(d[0]), "+f"(d[1]), "+f"(d[2]), "+f"(d[3])
        : "r"(a0), "r"(a1), "r"(a2), "r"(a3), "r"(b0), "r"(b1));
}
__device__ __forceinline__ u32 h2pack(float a, float b) {
    __half2 h = __floats2half2_rn(a, b);
    return *(u32*)&h;
}
__device__ __forceinline__ float2 h2unpack(u32 p) {
    return __half22float2(*(__half2*)&p);
}
#define CP_ASYNC16(d, s) asm volatile("cp.async.cg.shared.global [%0], [%1], 16;" :: "r"(d), "l"(s) : "memory")
#define CP_COMMIT()      asm volatile("cp.async.commit_group;" ::: "memory")
#define CP_WAIT(n)       asm volatile("cp.async.wait_group %0;" :: "n"(n) : "memory")

// ---------------- scratch ----------------
__device__ int   g_src[E_MAX];
__device__ int   g_dst[E_MAX];
// fp16 node partials: 2 x 100k x 256 x 2B = 102 MB total -> fits in 126 MB L2
__device__ __align__(16) __half g_Psrc[(size_t)N_MAX * HD];
__device__ __align__(16) __half g_Pdst[(size_t)N_MAX * HD];
__device__ float g_agg [(size_t)N_MAX * ND];
// fp16 weight images (row-major, [n][k])
__device__ __align__(16) __half g_B1h[256 * 32];   // W1c^T  [n=256][k=32]
__device__ __align__(16) __half g_B2h[128 * 256];  // W2^T   [n=128][k=256]
__device__ __align__(16) __half g_U1h[256 * 256];  // uW1^T  [n=256][k=256]
__device__ __align__(16) __half g_U2h[128 * 256];  // uW2^T  [n=128][k=256]

// =================== K0: edge_index convert (int64 OR int32) ===================
__global__ void k_convert(const int* __restrict__ w, int E)
{
    __shared__ int s64;
    if (threadIdx.x == 0) {
        int b = 1;
        #pragma unroll
        for (int i = 0; i < 8; i++) if (w[2 * i + 1] != 0) b = 0;
        s64 = b;
    }
    __syncthreads();
    int i = blockIdx.x * blockDim.x + threadIdx.x;
    if (i >= E) return;
    if (s64) {
        const long long* e = (const long long*)w;
        g_src[i] = (int)e[i];
        g_dst[i] = (int)e[(size_t)E + i];
    } else {
        g_src[i] = w[i];
        g_dst[i] = w[(size_t)E + i];
    }
}

// =================== K_prep: build fp16 weight images ===========================
__global__ void k_prep(const float* __restrict__ mW1, const float* __restrict__ mW2,
                       const float* __restrict__ uW1, const float* __restrict__ uW2)
{
    int tid = blockIdx.x * blockDim.x + threadIdx.x;
    const int S1 = 256 * 32, S2 = S1 + 128 * 256, S3 = S2 + 256 * 256;
    int total = S3 + 128 * 256;
    for (int i = tid; i < total; i += gridDim.x * blockDim.x) {
        if (i < S1) {
            int n = i >> 5, k = i & 31;                 // W1c[k][n]
            g_B1h[n * 32 + k] = __float2half(mW1[(size_t)(2 * ND + k) * HD + n]);
        } else if (i < S2) {
            int q = i - S1;
            int n = q >> 8, j = q & 255;                // W2[j][n]
            g_B2h[n * 256 + j] = __float2half(mW2[(size_t)j * ND + n]);
        } else if (i < S3) {
            int q = i - S2;
            int n = q >> 8, k = q & 255;                // uW1[k][n]
            g_U1h[n * 256 + k] = __float2half(uW1[(size_t)k * HD + n]);
        } else {
            int q = i - S3;
            int n = q >> 8, k = q & 255;                // uW2[k][n]
            g_U2h[n * 256 + k] = __float2half(uW2[(size_t)k * ND + n]);
        }
    }
}

// =================== K1: per-node precompute (scalar; fp16 partial store) =======
__global__ __launch_bounds__(256) void k_node_pre(
    const float* __restrict__ x, const float* __restrict__ cong,
    const float* __restrict__ mW1, const float* __restrict__ mb1, int N)
{
    __shared__ __align__(16) float Xt[ND * 33];
    __shared__ __align__(16) float Bs[16 * HD];
    const int tid = threadIdx.x;
    const int cg = tid & 31, eg = tid >> 5;
    const int base = blockIdx.x * 32;

    for (int idx = tid; idx < 32 * ND; idx += 256) {
        int k = idx & (ND - 1), n = idx >> 7;
        int node = base + n;
        Xt[k * 33 + n] = (node < N) ? x[(size_t)node * ND + k] : 0.f;
    }
    float cg4[4];
    #pragma unroll
    for (int i = 0; i < 4; i++) {
        int node = base + eg * 4 + i;
        cg4[i] = (node < N) ? cong[node] : 0.f;
    }
    __syncthreads();

    for (int which = 0; which < 2; which++) {
        const float* W = mW1 + (size_t)which * ND * HD;
        u64 acc[4][2][2];
        #pragma unroll
        for (int i = 0; i < 4; i++)
            #pragma unroll
            for (int p = 0; p < 2; p++) { acc[i][p][0] = 0ull; acc[i][p][1] = 0ull; }

        for (int ko = 0; ko < ND; ko += 16) {
            {
                const float4* srcp = (const float4*)(W + (size_t)ko * HD);
                float4* dstp = (float4*)Bs;
                for (int idx = tid; idx < 16 * HD / 4; idx += 256) dstp[idx] = srcp[idx];
            }
            __syncthreads();
            #pragma unroll 4
            for (int kk = 0; kk < 16; kk++) {
                u64 aa[4];
                #pragma unroll
                for (int i = 0; i < 4; i++) aa[i] = dup2(Xt[(ko + kk) * 33 + eg * 4 + i]);
                #pragma unroll
                for (int p = 0; p < 2; p++) {
                    ulonglong2 b = *(const ulonglong2*)&Bs[kk * HD + 4 * cg + 128 * p];
                    #pragma unroll
                    for (int i = 0; i < 4; i++) {
                        acc[i][p][0] = ffma2(aa[i], b.x, acc[i][p][0]);
                        acc[i][p][1] = ffma2(aa[i], b.y, acc[i][p][1]);
                    }
                }
            }
            __syncthreads();
        }
        #pragma unroll
        for (int p = 0; p < 2; p++) {
            if (which == 0) {
                float4 w2 = *(const float4*)&mW1[(size_t)288 * HD + 128 * p + 4 * cg];
                #pragma unroll
                for (int i = 0; i < 4; i++) {
                    int node = base + eg * 4 + i;
                    if (node < N) {
                        float2 v0 = unpk(acc[i][p][0]), v1 = unpk(acc[i][p][1]);
                        uint2 hh = make_uint2(
                            h2pack(v0.x + cg4[i] * w2.x, v0.y + cg4[i] * w2.y),
                            h2pack(v1.x + cg4[i] * w2.z, v1.y + cg4[i] * w2.w));
                        *(uint2*)&g_Psrc[(size_t)node * HD + 128 * p + 4 * cg] = hh;
                    }
                }
            } else {
                float4 b1 = *(const float4*)&mb1[128 * p + 4 * cg];
                #pragma unroll
                for (int i = 0; i < 4; i++) {
                    int node = base + eg * 4 + i;
                    if (node < N) {
                        float2 v0 = unpk(acc[i][p][0]), v1 = unpk(acc[i][p][1]);
                        uint2 hh = make_uint2(
                            h2pack(v0.x + b1.x, v0.y + b1.y),
                            h2pack(v1.x + b1.z, v1.y + b1.w));
                        *(uint2*)&g_Pdst[(size_t)node * HD + 128 * p + 4 * cg] = hh;
                    }
                }
            }
        }
    }
    for (int idx = tid; idx < 32 * ND; idx += 256) {
        int node = base + (idx >> 7);
        if (node < N) g_agg[(size_t)node * ND + (idx & (ND - 1))] = 0.f;
    }
}

// =================== K2: warp-MMA edge kernel (v6, proven) ======================
#define B1_OFF  0
#define A2_OFF  20480
#define B2_OFF  38912
#define SRC_OFF 75776
#define DST_OFF 76288
#define EDGE_SMEM 76800
#define B1_ST 80
#define A1_ST 80
#define A2_ST 144
#define B2_ST 144
#define B2_BUF 18432

__global__ __launch_bounds__(512, 1) void k_edge_mma(
    const float* __restrict__ edge_attr, const float* __restrict__ mb2, int E)
{
    extern __shared__ __align__(16) char sm[];
    const u32 smu = smem_u32(sm);
    const int tid = threadIdx.x;
    const int w = tid >> 5, l = tid & 31;
    const int wm = w & 7, wn = w >> 3;
    const int g = l >> 2, t = l & 3;
    const int base = blockIdx.x * 128;
    const char* gB2 = (const char*)g_B2h;

    #pragma unroll
    for (int r = 0; r < 2; r++) {
        int i = tid + 512 * r;
        int row = i >> 3, part = i & 7;
        CP_ASYNC16(smu + B2_OFF + row * B2_ST + part * 16,
                   gB2 + row * 512 + part * 16);
    }
    CP_COMMIT();

    if (tid < 128) {
        int e = base + tid;
        ((int*)(sm + SRC_OFF))[tid] = (e < E) ? g_src[e] : 0;
        ((int*)(sm + DST_OFF))[tid] = (e < E) ? g_dst[e] : 0;
    }
    for (int idx = tid; idx < 256 * 4; idx += 512) {
        int row = idx >> 2, ch = idx & 3;
        *(float4*)(sm + B1_OFF + row * B1_ST + ch * 16) =
            *(const float4*)((const char*)g_B1h + row * 64 + ch * 16);
    }
    if (tid < 256) {
        int e = tid >> 1, h = tid & 1;
        char* arow = sm + A2_OFF + e * A1_ST;
        if (base + e < E) {
            const float4* src4 = (const float4*)(edge_attr + (size_t)(base + e) * ED + 16 * h);
            #pragma unroll
            for (int q = 0; q < 4; q++) {
                float4 v = src4[q];
                int k = 16 * h + 4 * q;
                *(u32*)(arow + k * 2)       = h2pack(v.x, v.y);
                *(u32*)(arow + (k + 2) * 2) = h2pack(v.z, v.w);
            }
        } else {
            #pragma unroll
            for (int q = 0; q < 8; q++)
                *(u32*)(arow + (16 * h + 2 * q) * 2) = 0u;
        }
    }
    __syncthreads();

    const int lr   = l & 7;
    const int aRow = 16 * wm + lr + ((l >> 3) & 1) * 8;
    const int aKh  = (l >> 4) * 8;
    const int bRow = lr + (l >> 4) * 8;
    const int bKh  = ((l >> 3) & 1) * 8;
    const u32 a1base = smu + A2_OFF + aRow * A1_ST + aKh * 2;
    const u32 a2base = smu + A2_OFF + aRow * A2_ST + aKh * 2;

    u32 fa[2][4];
    #pragma unroll
    for (int kt = 0; kt < 2; kt++)
        ldsm_x4(a1base + kt * 32, fa[kt][0], fa[kt][1], fa[kt][2], fa[kt][3]);

    const int m0 = 16 * wm + g, m1 = m0 + 8;
    const int vs0 = ((const int*)(sm + SRC_OFF))[m0];
    const int vd0 = ((const int*)(sm + DST_OFF))[m0];
    const int vs1 = ((const int*)(sm + SRC_OFF))[m1];
    const int vd1 = ((const int*)(sm + DST_OFF))[m1];
    char* a2r0 = sm + A2_OFF + m0 * A2_ST;
    char* a2r1 = sm + A2_OFF + m1 * A2_ST;

    float acc2[8][4];
    #pragma unroll
    for (int j = 0; j < 8; j++)
        #pragma unroll
        for (int q = 0; q < 4; q++) acc2[j][q] = 0.f;

    #pragma unroll 1
    for (int c = 0; c < 4; c++) {
        u32 ps0[4], pd0[4], ps1[4], pd1[4];
        #pragma unroll
        for (int nt = 0; nt < 4; nt++) {
            int col = 64 * c + 32 * wn + 8 * nt + 2 * t;
            ps0[nt] = *(const u32*)(g_Psrc + (size_t)vs0 * HD + col);
            pd0[nt] = *(const u32*)(g_Pdst + (size_t)vd0 * HD + col);
            ps1[nt] = *(const u32*)(g_Psrc + (size_t)vs1 * HD + col);
            pd1[nt] = *(const u32*)(g_Pdst + (size_t)vd1 * HD + col);
        }

        float acc1[4][4];
        #pragma unroll
        for (int j = 0; j < 4; j++)
            #pragma unroll
            for (int q = 0; q < 4; q++) acc1[j][q] = 0.f;

        #pragma unroll
        for (int jp = 0; jp < 2; jp++) {
            u32 bb = smu + B1_OFF + (64 * c + 32 * wn + 16 * jp + bRow) * B1_ST + bKh * 2;
            u32 b0, b1, b2, b3;
            ldsm_x4(bb + 0, b0, b1, b2, b3);
            mma_f16(acc1[2 * jp],     fa[0][0], fa[0][1], fa[0][2], fa[0][3], b0, b1);
            mma_f16(acc1[2 * jp + 1], fa[0][0], fa[0][1], fa[0][2], fa[0][3], b2, b3);
            ldsm_x4(bb + 32, b0, b1, b2, b3);
            mma_f16(acc1[2 * jp],     fa[1][0], fa[1][1], fa[1][2], fa[1][3], b0, b1);
            mma_f16(acc1[2 * jp + 1], fa[1][0], fa[1][1], fa[1][2], fa[1][3], b2, b3);
        }

        __syncthreads();

        if (c < 3) {
            int buf = (c + 1) & 1;
            #pragma unroll
            for (int r = 0; r < 2; r++) {
                int i = tid + 512 * r;
                int row = i >> 3, part = i & 7;
                CP_ASYNC16(smu + B2_OFF + buf * B2_BUF + row * B2_ST + part * 16,
                           gB2 + row * 512 + 128 * (c + 1) + part * 16);
            }
            CP_COMMIT();
        }

        #pragma unroll
        for (int nt = 0; nt < 4; nt++) {
            int lc = 32 * wn + 8 * nt + 2 * t;
            float2 a0 = h2unpack(ps0[nt]), b0 = h2unpack(pd0[nt]);
            float2 a1 = h2unpack(ps1[nt]), b1 = h2unpack(pd1[nt]);
            float v00 = fmaxf(acc1[nt][0] + a0.x + b0.x, 0.f);
            float v01 = fmaxf(acc1[nt][1] + a0.y + b0.y, 0.f);
            float v10 = fmaxf(acc1[nt][2] + a1.x + b1.x, 0.f);
            float v11 = fmaxf(acc1[nt][3] + a1.y + b1.y, 0.f);
            *(u32*)(a2r0 + lc * 2) = h2pack(v00, v01);
            *(u32*)(a2r1 + lc * 2) = h2pack(v10, v11);
        }

        if (c < 3) { CP_WAIT(1); } else { CP_WAIT(0); }
        __syncthreads();

        const u32 b2b = smu + B2_OFF + (c & 1) * B2_BUF;
        #pragma unroll
        for (int t4 = 0; t4 < 4; t4++) {
            u32 ah0, ah1, ah2, ah3;
            ldsm_x4(a2base + t4 * 32, ah0, ah1, ah2, ah3);
            #pragma unroll
            for (int jp = 0; jp < 4; jp++) {
                u32 nrow = (u32)(64 * wn + 16 * jp + bRow);
                u32 kof  = (u32)(16 * t4 + bKh) * 2;
                u32 b0, b1, b2, b3;
                ldsm_x4(b2b + nrow * B2_ST + kof, b0, b1, b2, b3);
                mma_f16(acc2[2 * jp],     ah0, ah1, ah2, ah3, b0, b1);
                mma_f16(acc2[2 * jp + 1], ah0, ah1, ah2, ah3, b2, b3);
            }
        }
    }

    const bool e0 = (base + m0 < E), e1 = (base + m1 < E);
    #pragma unroll
    for (int j = 0; j < 8; j++) {
        int n = 64 * wn + 8 * j + 2 * t;
        float2 bv = *(const float2*)(mb2 + n);
        if (e0) {
            float x0 = acc2[j][0] + bv.x, x1 = acc2[j][1] + bv.y;
            asm volatile("red.global.add.v2.f32 [%0], {%1, %2};"
                         :: "l"(g_agg + (size_t)vd0 * ND + n), "f"(x0), "f"(x1) : "memory");
        }
        if (e1) {
            float x0 = acc2[j][2] + bv.x, x1 = acc2[j][3] + bv.y;
            asm volatile("red.global.add.v2.f32 [%0], {%1, %2};"
                         :: "l"(g_agg + (size_t)vd1 * ND + n), "f"(x0), "f"(x1) : "memory");
        }
    }
}

// =================== K3: warp-MMA node update (v1: fp16 HMMA) ===================
// 128 nodes/CTA, 512 threads. Warp w: wm = w&7 (rows 16wm..+15), wn = w>>3.
// A1 = fp16([x | agg]) staged once [128][256]. Chunk loop (4 x 64 hidden cols):
// cp.async double-buffered uW1 chunk + uW2 chunk; layer1 MMA -> +ub1/relu/fp16
// -> A2 -> layer2 MMA; direct store (no atomics).
// smem layout (bytes):
//   A1 @ 0       [128 rows][256 halves + pad] stride 528   67584
//   A2 @ 67584   [128 rows][64 halves + pad]  stride 144   18432
//   B1 @ 86016   2 bufs x [64 rows][256 halves] st528      67584
//   B2 @ 153600  2 bufs x [128 rows][64 halves] st144      36864
#define U_A1_OFF 0
#define U_A2_OFF 67584
#define U_B1_OFF 86016
#define U_B2_OFF 153600
#define U_SMEM   190464
#define U_A1_ST  528
#define U_A2_ST  144
#define U_B1_ST  528
#define U_B2_ST  144
#define U_B1_BUF 33792
#define U_B2_BUF 18432

__global__ __launch_bounds__(512, 1) void k_update_mma(
    const float* __restrict__ x,
    const float* __restrict__ ub1, const float* __restrict__ ub2,
    float* __restrict__ out, int N)
{
    extern __shared__ __align__(16) char sm[];
    const u32 smu = smem_u32(sm);
    const int tid = threadIdx.x;
    const int w = tid >> 5, l = tid & 31;
    const int wm = w & 7, wn = w >> 3;
    const int g = l >> 2, t = l & 3;
    const int base = blockIdx.x * 128;
    const char* gB1 = (const char*)g_U1h;
    const char* gB2 = (const char*)g_U2h;

    // ---- prefetch chunk-0 weights (B1: 64 rows x 512B, B2: 128 rows x 128B) ----
    #pragma unroll
    for (int r = 0; r < 4; r++) {
        int i = tid + 512 * r;
        int row = i >> 5, part = i & 31;
        CP_ASYNC16(smu + U_B1_OFF + row * U_B1_ST + part * 16,
                   gB1 + row * 512 + part * 16);
    }
    #pragma unroll
    for (int r = 0; r < 2; r++) {
        int i = tid + 512 * r;
        int row = i >> 3, part = i & 7;
        CP_ASYNC16(smu + U_B2_OFF + row * U_B2_ST + part * 16,
                   gB2 + row * 512 + part * 16);
    }
    CP_COMMIT();

    // ---- stage A1 = fp16([x | agg]), row = tid>>2, quarter = tid&3 ----
    {
        int row = tid >> 2, q = tid & 3;
        int node = base + row;
        char* arow = sm + U_A1_OFF + row * U_A1_ST + q * 128;
        if (node < N) {
            const float4* srcp = (q < 2)
                ? (const float4*)(x + (size_t)node * ND + 64 * q)
                : (const float4*)(g_agg + (size_t)node * ND + 64 * (q - 2));
            #pragma unroll
            for (int i = 0; i < 16; i++) {
                float4 v = srcp[i];
                *(u32*)(arow + i * 8)     = h2pack(v.x, v.y);
                *(u32*)(arow + i * 8 + 4) = h2pack(v.z, v.w);
            }
        } else {
            #pragma unroll
            for (int i = 0; i < 32; i++) *(u32*)(arow + i * 4) = 0u;
        }
    }
    __syncthreads();

    // per-lane ldmatrix address components
    const int lr   = l & 7;
    const int aRow = 16 * wm + lr + ((l >> 3) & 1) * 8;
    const int aKh  = (l >> 4) * 8;
    const int bRow = lr + (l >> 4) * 8;
    const int bKh  = ((l >> 3) & 1) * 8;
    const u32 a1base = smu + U_A1_OFF + aRow * U_A1_ST + aKh * 2;
    const u32 a2base = smu + U_A2_OFF + aRow * U_A2_ST + aKh * 2;

    const int m0 = 16 * wm + g, m1 = m0 + 8;
    char* a2r0 = sm + U_A2_OFF + m0 * U_A2_ST;
    char* a2r1 = sm + U_A2_OFF + m1 * U_A2_ST;

    float acc2[8][4];
    #pragma unroll
    for (int j = 0; j < 8; j++)
        #pragma unroll
        for (int q = 0; q < 4; q++) acc2[j][q] = 0.f;

    // ================= fused chunk loop =================
    #pragma unroll 1
    for (int c = 0; c < 4; c++) {
        if (c > 0) __syncthreads();   // all warps done reading bufs of chunk c-1
        if (c < 3) {
            int buf = (c + 1) & 1;
            #pragma unroll
            for (int r = 0; r < 4; r++) {
                int i = tid + 512 * r;
                int row = i >> 5, part = i & 31;
                CP_ASYNC16(smu + U_B1_OFF + buf * U_B1_BUF + row * U_B1_ST + part * 16,
                           gB1 + (size_t)(64 * (c + 1) + row) * 512 + part * 16);
            }
            #pragma unroll
            for (int r = 0; r < 2; r++) {
                int i = tid + 512 * r;
                int row = i >> 3, part = i & 7;
                CP_ASYNC16(smu + U_B2_OFF + buf * U_B2_BUF + row * U_B2_ST + part * 16,
                           gB2 + row * 512 + 128 * (c + 1) + part * 16);
            }
            CP_COMMIT();
        }
        if (c < 3) { CP_WAIT(1); } else { CP_WAIT(0); }
        __syncthreads();

        // ---- layer 1: acc1 = A1 @ uW1[:, warp's 32 cols of chunk c], K=256 ----
        float acc1[4][4];
        #pragma unroll
        for (int j = 0; j < 4; j++)
            #pragma unroll
            for (int q = 0; q < 4; q++) acc1[j][q] = 0.f;

        const u32 b1b = smu + U_B1_OFF + (c & 1) * U_B1_BUF;
        #pragma unroll 2
        for (int kt = 0; kt < 16; kt++) {
            u32 fa0, fa1, fa2, fa3;
            ldsm_x4(a1base + kt * 32, fa0, fa1, fa2, fa3);
            #pragma unroll
            for (int jp = 0; jp < 2; jp++) {
                u32 nrow = (u32)(32 * wn + 16 * jp + bRow);
                u32 b0, b1, b2, b3;
                ldsm_x4(b1b + nrow * U_B1_ST + (u32)(16 * kt + bKh) * 2, b0, b1, b2, b3);
                mma_f16(acc1[2 * jp],     fa0, fa1, fa2, fa3, b0, b1);
                mma_f16(acc1[2 * jp + 1], fa0, fa1, fa2, fa3, b2, b3);
            }
        }

        // ---- epilogue: + ub1, relu, fp16 into A2 ----
        #pragma unroll
        for (int nt = 0; nt < 4; nt++) {
            int col = 64 * c + 32 * wn + 8 * nt + 2 * t;
            int lc  = 32 * wn + 8 * nt + 2 * t;
            float2 bv = *(const float2*)(ub1 + col);
            float v00 = fmaxf(acc1[nt][0] + bv.x, 0.f);
            float v01 = fmaxf(acc1[nt][1] + bv.y, 0.f);
            float v10 = fmaxf(acc1[nt][2] + bv.x, 0.f);
            float v11 = fmaxf(acc1[nt][3] + bv.y, 0.f);
            *(u32*)(a2r0 + lc * 2) = h2pack(v00, v01);
            *(u32*)(a2r1 + lc * 2) = h2pack(v10, v11);
        }
        __syncthreads();

        // ---- layer 2: acc2 += h_chunk @ uW2_chunk ----
        const u32 b2b = smu + U_B2_OFF + (c & 1) * U_B2_BUF;
        #pragma unroll
        for (int t4 = 0; t4 < 4; t4++) {
            u32 ah0, ah1, ah2, ah3;
            ldsm_x4(a2base + t4 * 32, ah0, ah1, ah2, ah3);
            #pragma unroll
            for (int jp = 0; jp < 4; jp++) {
                u32 nrow = (u32)(64 * wn + 16 * jp + bRow);
                u32 kof  = (u32)(16 * t4 + bKh) * 2;
                u32 b0, b1, b2, b3;
                ldsm_x4(b2b + nrow * U_B2_ST + kof, b0, b1, b2, b3);
                mma_f16(acc2[2 * jp],     ah0, ah1, ah2, ah3, b0, b1);
                mma_f16(acc2[2 * jp + 1], ah0, ah1, ah2, ah3, b2, b3);
            }
        }
    }

    // ---- store: + ub2, direct fp32 write ----
    const bool n0 = (base + m0 < N), n1 = (base + m1 < N);
    #pragma unroll
    for (int j = 0; j < 8; j++) {
        int n = 64 * wn + 8 * j + 2 * t;
        float2 bv = *(const float2*)(ub2 + n);
        if (n0) {
            float2 r = make_float2(acc2[j][0] + bv.x, acc2[j][1] + bv.y);
            *(float2*)&out[(size_t)(base + m0) * ND + n] = r;
        }
        if (n1) {
            float2 r = make_float2(acc2[j][2] + bv.x, acc2[j][3] + bv.y);
            *(float2*)&out[(size_t)(base + m1) * ND + n] = r;
        }
    }
}

// =================== launcher ===================================================
extern "C" void kernel_launch(void* const* d_in, const int* in_sizes, int n_in,
                              void* d_out, int out_size)
{
    const float* x    = (const float*)d_in[0];
    const int*   ei   = (const int*)  d_in[1];
    const float* ea   = (const float*)d_in[2];
    const float* cong = (const float*)d_in[3];
    const float* mW1  = (const float*)d_in[4];
    const float* mb1  = (const float*)d_in[5];
    const float* mW2  = (const float*)d_in[6];
    const float* mb2  = (const float*)d_in[7];
    const float* uW1  = (const float*)d_in[8];
    const float* ub1  = (const float*)d_in[9];
    const float* uW2  = (const float*)d_in[10];
    const float* ub2  = (const float*)d_in[11];

    int N = in_sizes[0] / ND;
    int E = in_sizes[1] / 2;
    if (N > N_MAX) N = N_MAX;
    if (E > E_MAX) E = E_MAX;

    cudaFuncSetAttribute(k_edge_mma,   cudaFuncAttributeMaxDynamicSharedMemorySize, EDGE_SMEM);
    cudaFuncSetAttribute(k_update_mma, cudaFuncAttributeMaxDynamicSharedMemorySize, U_SMEM);

    k_convert    <<<(E + 255) / 256, 256>>>(ei, E);
    k_prep       <<<160, 256>>>(mW1, mW2, uW1, uW2);
    k_node_pre   <<<(N + 31) / 32, 256>>>(x, cong, mW1, mb1, N);
    k_edge_mma   <<<(E + 127) / 128, 512, EDGE_SMEM>>>(ea, mb2, E);
    k_update_mma <<<(N + 127) / 128, 512, U_SMEM>>>(x, ub1, ub2, (float*)d_out, N);
}

// round 11
// speedup vs baseline: 1.9248x; 1.0769x over previous
#include <cuda_runtime.h>
#include <cuda_fp16.h>
#include <cstdint>

#define ND 128
#define ED 32
#define HD 256
#define N_MAX 100000
#define E_MAX 1600000

typedef unsigned long long u64;
typedef unsigned int u32;

// ---------------- packed f32x2 helpers (scalar kernels) ----------------
__device__ __forceinline__ u64 ffma2(u64 a, u64 b, u64 c) {
    u64 d;
    asm("fma.rn.f32x2 %0, %1, %2, %3;" : "=l"(d) : "l"(a), "l"(b), "l"(c));
    return d;
}
__device__ __forceinline__ u64 dup2(float x) {
    u64 d;
    asm("mov.b64 %0, {%1, %1};" : "=l"(d) : "f"(x));
    return d;
}
__device__ __forceinline__ float2 unpk(u64 p) {
    float2 r;
    asm("mov.b64 {%0, %1}, %2;" : "=f"(r.x), "=f"(r.y) : "l"(p));
    return r;
}

// ---------------- warp-MMA helpers (family-compatible: sm_80+) ----------------
__device__ __forceinline__ u32 smem_u32(const void* p) {
    u32 a;
    asm("{ .reg .u64 t; cvta.to.shared.u64 t, %1; cvt.u32.u64 %0, t; }" : "=r"(a) : "l"(p));
    return a;
}
__device__ __forceinline__ void ldsm_x4(u32 addr, u32& r0, u32& r1, u32& r2, u32& r3) {
    asm volatile("ldmatrix.sync.aligned.m8n8.x4.shared.b16 {%0,%1,%2,%3}, [%4];"
        : "=r"(r0), "=r"(r1), "=r"(r2), "=r"(r3) : "r"(addr));
}
__device__ __forceinline__ void mma_f16(float* d, u32 a0, u32 a1, u32 a2, u32 a3,
                                        u32 b0, u32 b1) {
    asm volatile("mma.sync.aligned.m16n8k16.row.col.f32.f16.f16.f32 "
        "{%0,%1,%2,%3}, {%4,%5,%6,%7}, {%8,%9}, {%0,%1,%2,%3};"
        : "+f"(d[0]), "+f"(d[1]), "+f"(d[2]), "+f"(d[3])
        : "r"(a0), "r"(a1), "r"(a2), "r"(a3), "r"(b0), "r"(b1));
}
__device__ __forceinline__ u32 h2pack(float a, float b) {
    __half2 h = __floats2half2_rn(a, b);
    return *(u32*)&h;
}
__device__ __forceinline__ float2 h2unpack(u32 p) {
    return __half22float2(*(__half2*)&p);
}
#define CP_ASYNC16(d, s) asm volatile("cp.async.cg.shared.global [%0], [%1], 16;" :: "r"(d), "l"(s) : "memory")
#define CP_COMMIT()      asm volatile("cp.async.commit_group;" ::: "memory")
#define CP_WAIT(n)       asm volatile("cp.async.wait_group %0;" :: "n"(n) : "memory")

// ---------------- scratch ----------------
__device__ int   g_src[E_MAX];
__device__ int   g_dst[E_MAX];
// fp16 node partials: 2 x 100k x 256 x 2B = 102 MB total -> fits in 126 MB L2
__device__ __align__(16) __half g_Psrc[(size_t)N_MAX * HD];
__device__ __align__(16) __half g_Pdst[(size_t)N_MAX * HD];
__device__ float g_agg [(size_t)N_MAX * ND];
// fp16 weight images (row-major, [n][k])
__device__ __align__(16) __half g_B1h[256 * 32];   // W1c^T  [n=256][k=32]
__device__ __align__(16) __half g_B2h[128 * 256];  // W2^T   [n=128][k=256]
__device__ __align__(16) __half g_U1h[256 * 256];  // uW1^T  [n=256][k=256]
__device__ __align__(16) __half g_U2h[128 * 256];  // uW2^T  [n=128][k=256]

// =================== K0: edge_index convert (int64 OR int32) ===================
__global__ void k_convert(const int* __restrict__ w, int E)
{
    __shared__ int s64;
    if (threadIdx.x == 0) {
        int b = 1;
        #pragma unroll
        for (int i = 0; i < 8; i++) if (w[2 * i + 1] != 0) b = 0;
        s64 = b;
    }
    __syncthreads();
    int i = blockIdx.x * blockDim.x + threadIdx.x;
    if (i >= E) return;
    if (s64) {
        const long long* e = (const long long*)w;
        g_src[i] = (int)e[i];
        g_dst[i] = (int)e[(size_t)E + i];
    } else {
        g_src[i] = w[i];
        g_dst[i] = w[(size_t)E + i];
    }
}

// =================== K_prep: build fp16 weight images ===========================
__global__ void k_prep(const float* __restrict__ mW1, const float* __restrict__ mW2,
                       const float* __restrict__ uW1, const float* __restrict__ uW2)
{
    int tid = blockIdx.x * blockDim.x + threadIdx.x;
    const int S1 = 256 * 32, S2 = S1 + 128 * 256, S3 = S2 + 256 * 256;
    int total = S3 + 128 * 256;
    for (int i = tid; i < total; i += gridDim.x * blockDim.x) {
        if (i < S1) {
            int n = i >> 5, k = i & 31;                 // W1c[k][n]
            g_B1h[n * 32 + k] = __float2half(mW1[(size_t)(2 * ND + k) * HD + n]);
        } else if (i < S2) {
            int q = i - S1;
            int n = q >> 8, j = q & 255;                // W2[j][n]
            g_B2h[n * 256 + j] = __float2half(mW2[(size_t)j * ND + n]);
        } else if (i < S3) {
            int q = i - S2;
            int n = q >> 8, k = q & 255;                // uW1[k][n]
            g_U1h[n * 256 + k] = __float2half(uW1[(size_t)k * HD + n]);
        } else {
            int q = i - S3;
            int n = q >> 8, k = q & 255;                // uW2[k][n]
            g_U2h[n * 256 + k] = __float2half(uW2[(size_t)k * ND + n]);
        }
    }
}

// =================== K1: per-node precompute (scalar; fp16 partial store) =======
__global__ __launch_bounds__(256) void k_node_pre(
    const float* __restrict__ x, const float* __restrict__ cong,
    const float* __restrict__ mW1, const float* __restrict__ mb1, int N)
{
    __shared__ __align__(16) float Xt[ND * 33];
    __shared__ __align__(16) float Bs[16 * HD];
    const int tid = threadIdx.x;
    const int cg = tid & 31, eg = tid >> 5;
    const int base = blockIdx.x * 32;

    for (int idx = tid; idx < 32 * ND; idx += 256) {
        int k = idx & (ND - 1), n = idx >> 7;
        int node = base + n;
        Xt[k * 33 + n] = (node < N) ? x[(size_t)node * ND + k] : 0.f;
    }
    float cg4[4];
    #pragma unroll
    for (int i = 0; i < 4; i++) {
        int node = base + eg * 4 + i;
        cg4[i] = (node < N) ? cong[node] : 0.f;
    }
    __syncthreads();

    for (int which = 0; which < 2; which++) {
        const float* W = mW1 + (size_t)which * ND * HD;
        u64 acc[4][2][2];
        #pragma unroll
        for (int i = 0; i < 4; i++)
            #pragma unroll
            for (int p = 0; p < 2; p++) { acc[i][p][0] = 0ull; acc[i][p][1] = 0ull; }

        for (int ko = 0; ko < ND; ko += 16) {
            {
                const float4* srcp = (const float4*)(W + (size_t)ko * HD);
                float4* dstp = (float4*)Bs;
                for (int idx = tid; idx < 16 * HD / 4; idx += 256) dstp[idx] = srcp[idx];
            }
            __syncthreads();
            #pragma unroll 4
            for (int kk = 0; kk < 16; kk++) {
                u64 aa[4];
                #pragma unroll
                for (int i = 0; i < 4; i++) aa[i] = dup2(Xt[(ko + kk) * 33 + eg * 4 + i]);
                #pragma unroll
                for (int p = 0; p < 2; p++) {
                    ulonglong2 b = *(const ulonglong2*)&Bs[kk * HD + 4 * cg + 128 * p];
                    #pragma unroll
                    for (int i = 0; i < 4; i++) {
                        acc[i][p][0] = ffma2(aa[i], b.x, acc[i][p][0]);
                        acc[i][p][1] = ffma2(aa[i], b.y, acc[i][p][1]);
                    }
                }
            }
            __syncthreads();
        }
        #pragma unroll
        for (int p = 0; p < 2; p++) {
            if (which == 0) {
                float4 w2 = *(const float4*)&mW1[(size_t)288 * HD + 128 * p + 4 * cg];
                #pragma unroll
                for (int i = 0; i < 4; i++) {
                    int node = base + eg * 4 + i;
                    if (node < N) {
                        float2 v0 = unpk(acc[i][p][0]), v1 = unpk(acc[i][p][1]);
                        uint2 hh = make_uint2(
                            h2pack(v0.x + cg4[i] * w2.x, v0.y + cg4[i] * w2.y),
                            h2pack(v1.x + cg4[i] * w2.z, v1.y + cg4[i] * w2.w));
                        *(uint2*)&g_Psrc[(size_t)node * HD + 128 * p + 4 * cg] = hh;
                    }
                }
            } else {
                float4 b1 = *(const float4*)&mb1[128 * p + 4 * cg];
                #pragma unroll
                for (int i = 0; i < 4; i++) {
                    int node = base + eg * 4 + i;
                    if (node < N) {
                        float2 v0 = unpk(acc[i][p][0]), v1 = unpk(acc[i][p][1]);
                        uint2 hh = make_uint2(
                            h2pack(v0.x + b1.x, v0.y + b1.y),
                            h2pack(v1.x + b1.z, v1.y + b1.w));
                        *(uint2*)&g_Pdst[(size_t)node * HD + 128 * p + 4 * cg] = hh;
                    }
                }
            }
        }
    }
    for (int idx = tid; idx < 32 * ND; idx += 256) {
        int node = base + (idx >> 7);
        if (node < N) g_agg[(size_t)node * ND + (idx & (ND - 1))] = 0.f;
    }
}

// =================== K2: warp-MMA edge kernel (v7: 64 edges, 2 CTAs/SM) =========
// 64 edges/CTA, 256 threads. Warp w: wm = w&3 (rows 16wm..+15), wn = w>>2 (N half).
// Identical per-warp math to v6; two independent CTAs per SM overlap their
// barrier/gather phases with each other's MMA phases.
// smem layout (bytes):
//   B1  @ 0      [256 rows][32 halves]  stride 80    20480
//   A2c @ 20480  [64 rows][64 halves]   stride 144    9216  (A1 [64][80B] aliases)
//   B2  @ 29696  2 bufs x [128 rows][64 halves] st144 36864
//   src @ 66560  int[64];  dst @ 66816 int[64]
#define B1_OFF  0
#define A2_OFF  20480
#define B2_OFF  29696
#define SRC_OFF 66560
#define DST_OFF 66816
#define EDGE_SMEM 67072
#define B1_ST 80
#define A1_ST 80
#define A2_ST 144
#define B2_ST 144
#define B2_BUF 18432

__global__ __launch_bounds__(256, 2) void k_edge_mma(
    const float* __restrict__ edge_attr, const float* __restrict__ mb2, int E)
{
    extern __shared__ __align__(16) char sm[];
    const u32 smu = smem_u32(sm);
    const int tid = threadIdx.x;
    const int w = tid >> 5, l = tid & 31;
    const int wm = w & 3, wn = w >> 2;
    const int g = l >> 2, t = l & 3;
    const int base = blockIdx.x * 64;
    const char* gB2 = (const char*)g_B2h;

    // ---- prefetch B2 chunk 0 into buf 0 (cp.async): 128 rows x 128B ----
    #pragma unroll
    for (int r = 0; r < 4; r++) {
        int i = tid + 256 * r;
        int row = i >> 3, part = i & 7;
        CP_ASYNC16(smu + B2_OFF + row * B2_ST + part * 16,
                   gB2 + row * 512 + part * 16);
    }
    CP_COMMIT();

    // ---- stage src/dst ----
    if (tid < 64) {
        int e = base + tid;
        ((int*)(sm + SRC_OFF))[tid] = (e < E) ? g_src[e] : 0;
        ((int*)(sm + DST_OFF))[tid] = (e < E) ? g_dst[e] : 0;
    }
    // ---- stage B1: 256 rows x 64B ----
    for (int idx = tid; idx < 256 * 4; idx += 256) {
        int row = idx >> 2, ch = idx & 3;
        *(float4*)(sm + B1_OFF + row * B1_ST + ch * 16) =
            *(const float4*)((const char*)g_B1h + row * 64 + ch * 16);
    }
    // ---- stage A1 (aliases A2c region): edge_attr -> fp16 ----
    if (tid < 128) {
        int e = tid >> 1, h = tid & 1;
        char* arow = sm + A2_OFF + e * A1_ST;
        if (base + e < E) {
            const float4* src4 = (const float4*)(edge_attr + (size_t)(base + e) * ED + 16 * h);
            #pragma unroll
            for (int q = 0; q < 4; q++) {
                float4 v = src4[q];
                int k = 16 * h + 4 * q;
                *(u32*)(arow + k * 2)       = h2pack(v.x, v.y);
                *(u32*)(arow + (k + 2) * 2) = h2pack(v.z, v.w);
            }
        } else {
            #pragma unroll
            for (int q = 0; q < 8; q++)
                *(u32*)(arow + (16 * h + 2 * q) * 2) = 0u;
        }
    }
    __syncthreads();

    // per-lane ldmatrix address components
    const int lr   = l & 7;
    const int aRow = 16 * wm + lr + ((l >> 3) & 1) * 8;
    const int aKh  = (l >> 4) * 8;
    const int bRow = lr + (l >> 4) * 8;
    const int bKh  = ((l >> 3) & 1) * 8;
    const u32 a1base = smu + A2_OFF + aRow * A1_ST + aKh * 2;  // A1 alias
    const u32 a2base = smu + A2_OFF + aRow * A2_ST + aKh * 2;

    // A1 fragments (k-tiles 0-15, 16-31), cached for all chunks
    u32 fa[2][4];
    #pragma unroll
    for (int kt = 0; kt < 2; kt++)
        ldsm_x4(a1base + kt * 32, fa[kt][0], fa[kt][1], fa[kt][2], fa[kt][3]);

    // this lane's two edge rows
    const int m0 = 16 * wm + g, m1 = m0 + 8;
    const int vs0 = ((const int*)(sm + SRC_OFF))[m0];
    const int vd0 = ((const int*)(sm + DST_OFF))[m0];
    const int vs1 = ((const int*)(sm + SRC_OFF))[m1];
    const int vd1 = ((const int*)(sm + DST_OFF))[m1];
    char* a2r0 = sm + A2_OFF + m0 * A2_ST;
    char* a2r1 = sm + A2_OFF + m1 * A2_ST;

    float acc2[8][4];
    #pragma unroll
    for (int j = 0; j < 8; j++)
        #pragma unroll
        for (int q = 0; q < 4; q++) acc2[j][q] = 0.f;

    // ================= fused chunk loop =================
    #pragma unroll 1
    for (int c = 0; c < 4; c++) {
        // ---- PREFETCH fp16 node-partial gathers (hidden by layer-1 MMA) ----
        u32 ps0[4], pd0[4], ps1[4], pd1[4];
        #pragma unroll
        for (int nt = 0; nt < 4; nt++) {
            int col = 64 * c + 32 * wn + 8 * nt + 2 * t;
            ps0[nt] = *(const u32*)(g_Psrc + (size_t)vs0 * HD + col);
            pd0[nt] = *(const u32*)(g_Pdst + (size_t)vd0 * HD + col);
            ps1[nt] = *(const u32*)(g_Psrc + (size_t)vs1 * HD + col);
            pd1[nt] = *(const u32*)(g_Pdst + (size_t)vd1 * HD + col);
        }

        // ---- layer 1: acc1 = EA @ W1c[:, warp's 32 cols of chunk c] ----
        float acc1[4][4];
        #pragma unroll
        for (int j = 0; j < 4; j++)
            #pragma unroll
            for (int q = 0; q < 4; q++) acc1[j][q] = 0.f;

        #pragma unroll
        for (int jp = 0; jp < 2; jp++) {
            u32 bb = smu + B1_OFF + (64 * c + 32 * wn + 16 * jp + bRow) * B1_ST + bKh * 2;
            u32 b0, b1, b2, b3;
            ldsm_x4(bb + 0, b0, b1, b2, b3);      // k0-15
            mma_f16(acc1[2 * jp],     fa[0][0], fa[0][1], fa[0][2], fa[0][3], b0, b1);
            mma_f16(acc1[2 * jp + 1], fa[0][0], fa[0][1], fa[0][2], fa[0][3], b2, b3);
            ldsm_x4(bb + 32, b0, b1, b2, b3);     // k16-31
            mma_f16(acc1[2 * jp],     fa[1][0], fa[1][1], fa[1][2], fa[1][3], b0, b1);
            mma_f16(acc1[2 * jp + 1], fa[1][0], fa[1][1], fa[1][2], fa[1][3], b2, b3);
        }

        // all warps done with previous layer-2 reads (A2c + B2 buf) before overwrite
        __syncthreads();

        // ---- prefetch B2 chunk c+1 into buf (c+1)&1 ----
        if (c < 3) {
            int buf = (c + 1) & 1;
            #pragma unroll
            for (int r = 0; r < 4; r++) {
                int i = tid + 256 * r;
                int row = i >> 3, part = i & 7;
                CP_ASYNC16(smu + B2_OFF + buf * B2_BUF + row * B2_ST + part * 16,
                           gB2 + row * 512 + 128 * (c + 1) + part * 16);
            }
            CP_COMMIT();
        }

        // ---- epilogue: add prefetched partials, relu, fp16 into A2c ----
        #pragma unroll
        for (int nt = 0; nt < 4; nt++) {
            int lc = 32 * wn + 8 * nt + 2 * t;
            float2 a0 = h2unpack(ps0[nt]), b0 = h2unpack(pd0[nt]);
            float2 a1 = h2unpack(ps1[nt]), b1 = h2unpack(pd1[nt]);
            float v00 = fmaxf(acc1[nt][0] + a0.x + b0.x, 0.f);
            float v01 = fmaxf(acc1[nt][1] + a0.y + b0.y, 0.f);
            float v10 = fmaxf(acc1[nt][2] + a1.x + b1.x, 0.f);
            float v11 = fmaxf(acc1[nt][3] + a1.y + b1.y, 0.f);
            *(u32*)(a2r0 + lc * 2) = h2pack(v00, v01);
            *(u32*)(a2r1 + lc * 2) = h2pack(v10, v11);
        }

        if (c < 3) { CP_WAIT(1); } else { CP_WAIT(0); }
        __syncthreads();

        // ---- layer 2: acc2 += h_chunk @ W2_chunk ----
        const u32 b2b = smu + B2_OFF + (c & 1) * B2_BUF;
        #pragma unroll
        for (int t4 = 0; t4 < 4; t4++) {
            u32 ah0, ah1, ah2, ah3;
            ldsm_x4(a2base + t4 * 32, ah0, ah1, ah2, ah3);
            #pragma unroll
            for (int jp = 0; jp < 4; jp++) {
                u32 nrow = (u32)(64 * wn + 16 * jp + bRow);
                u32 kof  = (u32)(16 * t4 + bKh) * 2;
                u32 b0, b1, b2, b3;
                ldsm_x4(b2b + nrow * B2_ST + kof, b0, b1, b2, b3);
                mma_f16(acc2[2 * jp],     ah0, ah1, ah2, ah3, b0, b1);
                mma_f16(acc2[2 * jp + 1], ah0, ah1, ah2, ah3, b2, b3);
            }
        }
    }

    // ---- scatter: + mb2, red.v2 into g_agg[dst] ----
    const bool e0 = (base + m0 < E), e1 = (base + m1 < E);
    #pragma unroll
    for (int j = 0; j < 8; j++) {
        int n = 64 * wn + 8 * j + 2 * t;
        float2 bv = *(const float2*)(mb2 + n);
        if (e0) {
            float x0 = acc2[j][0] + bv.x, x1 = acc2[j][1] + bv.y;
            asm volatile("red.global.add.v2.f32 [%0], {%1, %2};"
                         :: "l"(g_agg + (size_t)vd0 * ND + n), "f"(x0), "f"(x1) : "memory");
        }
        if (e1) {
            float x0 = acc2[j][2] + bv.x, x1 = acc2[j][3] + bv.y;
            asm volatile("red.global.add.v2.f32 [%0], {%1, %2};"
                         :: "l"(g_agg + (size_t)vd1 * ND + n), "f"(x0), "f"(x1) : "memory");
        }
    }
}

// =================== K3: warp-MMA node update (proven) ==========================
#define U_A1_OFF 0
#define U_A2_OFF 67584
#define U_B1_OFF 86016
#define U_B2_OFF 153600
#define U_SMEM   190464
#define U_A1_ST  528
#define U_A2_ST  144
#define U_B1_ST  528
#define U_B2_ST  144
#define U_B1_BUF 33792
#define U_B2_BUF 18432

__global__ __launch_bounds__(512, 1) void k_update_mma(
    const float* __restrict__ x,
    const float* __restrict__ ub1, const float* __restrict__ ub2,
    float* __restrict__ out, int N)
{
    extern __shared__ __align__(16) char sm[];
    const u32 smu = smem_u32(sm);
    const int tid = threadIdx.x;
    const int w = tid >> 5, l = tid & 31;
    const int wm = w & 7, wn = w >> 3;
    const int g = l >> 2, t = l & 3;
    const int base = blockIdx.x * 128;
    const char* gB1 = (const char*)g_U1h;
    const char* gB2 = (const char*)g_U2h;

    #pragma unroll
    for (int r = 0; r < 4; r++) {
        int i = tid + 512 * r;
        int row = i >> 5, part = i & 31;
        CP_ASYNC16(smu + U_B1_OFF + row * U_B1_ST + part * 16,
                   gB1 + row * 512 + part * 16);
    }
    #pragma unroll
    for (int r = 0; r < 2; r++) {
        int i = tid + 512 * r;
        int row = i >> 3, part = i & 7;
        CP_ASYNC16(smu + U_B2_OFF + row * U_B2_ST + part * 16,
                   gB2 + row * 512 + part * 16);
    }
    CP_COMMIT();

    {
        int row = tid >> 2, q = tid & 3;
        int node = base + row;
        char* arow = sm + U_A1_OFF + row * U_A1_ST + q * 128;
        if (node < N) {
            const float4* srcp = (q < 2)
                ? (const float4*)(x + (size_t)node * ND + 64 * q)
                : (const float4*)(g_agg + (size_t)node * ND + 64 * (q - 2));
            #pragma unroll
            for (int i = 0; i < 16; i++) {
                float4 v = srcp[i];
                *(u32*)(arow + i * 8)     = h2pack(v.x, v.y);
                *(u32*)(arow + i * 8 + 4) = h2pack(v.z, v.w);
            }
        } else {
            #pragma unroll
            for (int i = 0; i < 32; i++) *(u32*)(arow + i * 4) = 0u;
        }
    }
    __syncthreads();

    const int lr   = l & 7;
    const int aRow = 16 * wm + lr + ((l >> 3) & 1) * 8;
    const int aKh  = (l >> 4) * 8;
    const int bRow = lr + (l >> 4) * 8;
    const int bKh  = ((l >> 3) & 1) * 8;
    const u32 a1base = smu + U_A1_OFF + aRow * U_A1_ST + aKh * 2;
    const u32 a2base = smu + U_A2_OFF + aRow * U_A2_ST + aKh * 2;

    const int m0 = 16 * wm + g, m1 = m0 + 8;
    char* a2r0 = sm + U_A2_OFF + m0 * U_A2_ST;
    char* a2r1 = sm + U_A2_OFF + m1 * U_A2_ST;

    float acc2[8][4];
    #pragma unroll
    for (int j = 0; j < 8; j++)
        #pragma unroll
        for (int q = 0; q < 4; q++) acc2[j][q] = 0.f;

    #pragma unroll 1
    for (int c = 0; c < 4; c++) {
        if (c > 0) __syncthreads();
        if (c < 3) {
            int buf = (c + 1) & 1;
            #pragma unroll
            for (int r = 0; r < 4; r++) {
                int i = tid + 512 * r;
                int row = i >> 5, part = i & 31;
                CP_ASYNC16(smu + U_B1_OFF + buf * U_B1_BUF + row * U_B1_ST + part * 16,
                           gB1 + (size_t)(64 * (c + 1) + row) * 512 + part * 16);
            }
            #pragma unroll
            for (int r = 0; r < 2; r++) {
                int i = tid + 512 * r;
                int row = i >> 3, part = i & 7;
                CP_ASYNC16(smu + U_B2_OFF + buf * U_B2_BUF + row * U_B2_ST + part * 16,
                           gB2 + row * 512 + 128 * (c + 1) + part * 16);
            }
            CP_COMMIT();
        }
        if (c < 3) { CP_WAIT(1); } else { CP_WAIT(0); }
        __syncthreads();

        float acc1[4][4];
        #pragma unroll
        for (int j = 0; j < 4; j++)
            #pragma unroll
            for (int q = 0; q < 4; q++) acc1[j][q] = 0.f;

        const u32 b1b = smu + U_B1_OFF + (c & 1) * U_B1_BUF;
        #pragma unroll 2
        for (int kt = 0; kt < 16; kt++) {
            u32 fa0, fa1, fa2, fa3;
            ldsm_x4(a1base + kt * 32, fa0, fa1, fa2, fa3);
            #pragma unroll
            for (int jp = 0; jp < 2; jp++) {
                u32 nrow = (u32)(32 * wn + 16 * jp + bRow);
                u32 b0, b1, b2, b3;
                ldsm_x4(b1b + nrow * U_B1_ST + (u32)(16 * kt + bKh) * 2, b0, b1, b2, b3);
                mma_f16(acc1[2 * jp],     fa0, fa1, fa2, fa3, b0, b1);
                mma_f16(acc1[2 * jp + 1], fa0, fa1, fa2, fa3, b2, b3);
            }
        }

        #pragma unroll
        for (int nt = 0; nt < 4; nt++) {
            int col = 64 * c + 32 * wn + 8 * nt + 2 * t;
            int lc  = 32 * wn + 8 * nt + 2 * t;
            float2 bv = *(const float2*)(ub1 + col);
            float v00 = fmaxf(acc1[nt][0] + bv.x, 0.f);
            float v01 = fmaxf(acc1[nt][1] + bv.y, 0.f);
            float v10 = fmaxf(acc1[nt][2] + bv.x, 0.f);
            float v11 = fmaxf(acc1[nt][3] + bv.y, 0.f);
            *(u32*)(a2r0 + lc * 2) = h2pack(v00, v01);
            *(u32*)(a2r1 + lc * 2) = h2pack(v10, v11);
        }
        __syncthreads();

        const u32 b2b = smu + U_B2_OFF + (c & 1) * U_B2_BUF;
        #pragma unroll
        for (int t4 = 0; t4 < 4; t4++) {
            u32 ah0, ah1, ah2, ah3;
            ldsm_x4(a2base + t4 * 32, ah0, ah1, ah2, ah3);
            #pragma unroll
            for (int jp = 0; jp < 4; jp++) {
                u32 nrow = (u32)(64 * wn + 16 * jp + bRow);
                u32 kof  = (u32)(16 * t4 + bKh) * 2;
                u32 b0, b1, b2, b3;
                ldsm_x4(b2b + nrow * U_B2_ST + kof, b0, b1, b2, b3);
                mma_f16(acc2[2 * jp],     ah0, ah1, ah2, ah3, b0, b1);
                mma_f16(acc2[2 * jp + 1], ah0, ah1, ah2, ah3, b2, b3);
            }
        }
    }

    const bool n0 = (base + m0 < N), n1 = (base + m1 < N);
    #pragma unroll
    for (int j = 0; j < 8; j++) {
        int n = 64 * wn + 8 * j + 2 * t;
        float2 bv = *(const float2*)(ub2 + n);
        if (n0) {
            float2 r = make_float2(acc2[j][0] + bv.x, acc2[j][1] + bv.y);
            *(float2*)&out[(size_t)(base + m0) * ND + n] = r;
        }
        if (n1) {
            float2 r = make_float2(acc2[j][2] + bv.x, acc2[j][3] + bv.y);
            *(float2*)&out[(size_t)(base + m1) * ND + n] = r;
        }
    }
}

// =================== launcher ===================================================
extern "C" void kernel_launch(void* const* d_in, const int* in_sizes, int n_in,
                              void* d_out, int out_size)
{
    const float* x    = (const float*)d_in[0];
    const int*   ei   = (const int*)  d_in[1];
    const float* ea   = (const float*)d_in[2];
    const float* cong = (const float*)d_in[3];
    const float* mW1  = (const float*)d_in[4];
    const float* mb1  = (const float*)d_in[5];
    const float* mW2  = (const float*)d_in[6];
    const float* mb2  = (const float*)d_in[7];
    const float* uW1  = (const float*)d_in[8];
    const float* ub1  = (const float*)d_in[9];
    const float* uW2  = (const float*)d_in[10];
    const float* ub2  = (const float*)d_in[11];

    int N = in_sizes[0] / ND;
    int E = in_sizes[1] / 2;
    if (N > N_MAX) N = N_MAX;
    if (E > E_MAX) E = E_MAX;

    cudaFuncSetAttribute(k_edge_mma,   cudaFuncAttributeMaxDynamicSharedMemorySize, EDGE_SMEM);
    cudaFuncSetAttribute(k_update_mma, cudaFuncAttributeMaxDynamicSharedMemorySize, U_SMEM);

    k_convert    <<<(E + 255) / 256, 256>>>(ei, E);
    k_prep       <<<160, 256>>>(mW1, mW2, uW1, uW2);
    k_node_pre   <<<(N + 31) / 32, 256>>>(x, cong, mW1, mb1, N);
    k_edge_mma   <<<(E + 63) / 64, 256, EDGE_SMEM>>>(ea, mb2, E);
    k_update_mma <<<(N + 127) / 128, 512, U_SMEM>>>(x, ub1, ub2, (float*)d_out, N);
}

// round 12
// speedup vs baseline: 2.3235x; 1.2071x over previous
#include <cuda_runtime.h>
#include <cuda_fp16.h>
#include <cstdint>

#define ND 128
#define ED 32
#define HD 256
#define N_MAX 100000
#define E_MAX 1600000

typedef unsigned long long u64;
typedef unsigned int u32;

// ---------------- warp-MMA helpers (family-compatible: sm_80+) ----------------
__device__ __forceinline__ u32 smem_u32(const void* p) {
    u32 a;
    asm("{ .reg .u64 t; cvta.to.shared.u64 t, %1; cvt.u32.u64 %0, t; }" : "=r"(a) : "l"(p));
    return a;
}
__device__ __forceinline__ void ldsm_x4(u32 addr, u32& r0, u32& r1, u32& r2, u32& r3) {
    asm volatile("ldmatrix.sync.aligned.m8n8.x4.shared.b16 {%0,%1,%2,%3}, [%4];"
        : "=r"(r0), "=r"(r1), "=r"(r2), "=r"(r3) : "r"(addr));
}
__device__ __forceinline__ void mma_f16(float* d, u32 a0, u32 a1, u32 a2, u32 a3,
                                        u32 b0, u32 b1) {
    asm volatile("mma.sync.aligned.m16n8k16.row.col.f32.f16.f16.f32 "
        "{%0,%1,%2,%3}, {%4,%5,%6,%7}, {%8,%9}, {%0,%1,%2,%3};"
        : "+f"(d[0]), "+f"(d[1]), "+f"(d[2]), "+f"(d[3])
        : "r"(a0), "r"(a1), "r"(a2), "r"(a3), "r"(b0), "r"(b1));
}
__device__ __forceinline__ u32 h2pack(float a, float b) {
    __half2 h = __floats2half2_rn(a, b);
    return *(u32*)&h;
}
__device__ __forceinline__ float2 h2unpack(u32 p) {
    return __half22float2(*(__half2*)&p);
}
#define CP_ASYNC16(d, s) asm volatile("cp.async.cg.shared.global [%0], [%1], 16;" :: "r"(d), "l"(s) : "memory")
#define CP_COMMIT()      asm volatile("cp.async.commit_group;" ::: "memory")
#define CP_WAIT(n)       asm volatile("cp.async.wait_group %0;" :: "n"(n) : "memory")

// ---------------- scratch ----------------
__device__ int   g_src[E_MAX];
__device__ int   g_dst[E_MAX];
// fp16 node partials: 2 x 100k x 256 x 2B = 102 MB total -> fits in 126 MB L2
__device__ __align__(16) __half g_Psrc[(size_t)N_MAX * HD];
__device__ __align__(16) __half g_Pdst[(size_t)N_MAX * HD];
__device__ float g_agg [(size_t)N_MAX * ND];
// fp16 weight images (row-major, [n][k])
__device__ __align__(16) __half g_B1h[256 * 32];    // W1c^T  [n=256][k=32]
__device__ __align__(16) __half g_B2h[128 * 256];   // W2^T   [n=128][k=256]
__device__ __align__(16) __half g_U1h[256 * 256];   // uW1^T  [n=256][k=256]
__device__ __align__(16) __half g_U2h[128 * 256];   // uW2^T  [n=128][k=256]
__device__ __align__(16) __half g_P1h[512 * 128];   // [W1a|W1b]^T: n<256 -> Psrc cols, n>=256 -> Pdst cols

// =================== K0: edge_index convert (int64 OR int32) ===================
__global__ void k_convert(const int* __restrict__ w, int E)
{
    __shared__ int s64;
    if (threadIdx.x == 0) {
        int b = 1;
        #pragma unroll
        for (int i = 0; i < 8; i++) if (w[2 * i + 1] != 0) b = 0;
        s64 = b;
    }
    __syncthreads();
    int i = blockIdx.x * blockDim.x + threadIdx.x;
    if (i >= E) return;
    if (s64) {
        const long long* e = (const long long*)w;
        g_src[i] = (int)e[i];
        g_dst[i] = (int)e[(size_t)E + i];
    } else {
        g_src[i] = w[i];
        g_dst[i] = w[(size_t)E + i];
    }
}

// =================== K_prep: build fp16 weight images ===========================
__global__ void k_prep(const float* __restrict__ mW1, const float* __restrict__ mW2,
                       const float* __restrict__ uW1, const float* __restrict__ uW2)
{
    int tid = blockIdx.x * blockDim.x + threadIdx.x;
    const int S1 = 256 * 32, S2 = S1 + 128 * 256, S3 = S2 + 256 * 256,
              S4 = S3 + 128 * 256;
    int total = S4 + 512 * 128;
    for (int i = tid; i < total; i += gridDim.x * blockDim.x) {
        if (i < S1) {
            int n = i >> 5, k = i & 31;                 // W1c[k][n]
            g_B1h[n * 32 + k] = __float2half(mW1[(size_t)(2 * ND + k) * HD + n]);
        } else if (i < S2) {
            int q = i - S1;
            int n = q >> 8, j = q & 255;                // W2[j][n]
            g_B2h[n * 256 + j] = __float2half(mW2[(size_t)j * ND + n]);
        } else if (i < S3) {
            int q = i - S2;
            int n = q >> 8, k = q & 255;                // uW1[k][n]
            g_U1h[n * 256 + k] = __float2half(uW1[(size_t)k * HD + n]);
        } else if (i < S4) {
            int q = i - S3;
            int n = q >> 8, k = q & 255;                // uW2[k][n]
            g_U2h[n * 256 + k] = __float2half(uW2[(size_t)k * ND + n]);
        } else {
            int q = i - S4;
            int n = q >> 7, k = q & 127;                // P1: n<256 Psrc, else Pdst
            float v = (n < 256) ? mW1[(size_t)k * HD + n]
                                : mW1[(size_t)(128 + k) * HD + (n - 256)];
            g_P1h[n * 128 + k] = __float2half(v);
        }
    }
}

// =================== K1: warp-MMA node precompute ===============================
// 128 nodes/CTA, 512 threads. Warp w: wm = w&7 (rows 16wm..+15), wn = w>>3.
// A1 = fp16(x[node]) [128][128]. Chunk loop over 4 x 128 output cols of
// [Psrc | Pdst] (c=0,1 -> Psrc, c=2,3 -> Pdst); cp.async double-buffered
// weight chunks; epilogue folds cong*w288 (Psrc) / +mb1 (Pdst), writes fp16
// partials; also zeroes g_agg.
// smem layout (bytes):
//   A1   @ 0      [128 rows][128 halves + pad] stride 272  34816
//   cong @ 34816  float[128]                                 512
//   B    @ 35328  2 bufs x [128 rows][128 halves + pad] st272  69632
#define P_A1_OFF   0
#define P_CONG_OFF 34816
#define P_B_OFF    35328
#define P_SMEM     104960
#define P_A1_ST    272
#define P_B_ST     272
#define P_B_BUF    34816

__global__ __launch_bounds__(512, 1) void k_pre_mma(
    const float* __restrict__ x, const float* __restrict__ cong,
    const float* __restrict__ mW1, const float* __restrict__ mb1, int N)
{
    extern __shared__ __align__(16) char sm[];
    const u32 smu = smem_u32(sm);
    const int tid = threadIdx.x;
    const int w = tid >> 5, l = tid & 31;
    const int wm = w & 7, wn = w >> 3;
    const int g = l >> 2, t = l & 3;
    const int base = blockIdx.x * 128;
    const char* gB = (const char*)g_P1h;

    // ---- prefetch weight chunk 0: 128 rows x 256B ----
    #pragma unroll
    for (int r = 0; r < 4; r++) {
        int i = tid + 512 * r;
        int row = i >> 4, part = i & 15;
        CP_ASYNC16(smu + P_B_OFF + row * P_B_ST + part * 16,
                   gB + row * 256 + part * 16);
    }
    CP_COMMIT();

    // ---- stage A1 = fp16(x), row = tid>>2, quarter (32 cols) = tid&3 ----
    {
        int row = tid >> 2, q = tid & 3;
        int node = base + row;
        char* arow = sm + P_A1_OFF + row * P_A1_ST + q * 64;
        if (node < N) {
            const float4* srcp = (const float4*)(x + (size_t)node * ND + 32 * q);
            #pragma unroll
            for (int i = 0; i < 8; i++) {
                float4 v = srcp[i];
                *(u32*)(arow + i * 8)     = h2pack(v.x, v.y);
                *(u32*)(arow + i * 8 + 4) = h2pack(v.z, v.w);
            }
        } else {
            #pragma unroll
            for (int i = 0; i < 16; i++) *(u32*)(arow + i * 4) = 0u;
        }
    }
    if (tid < 128) {
        int node = base + tid;
        ((float*)(sm + P_CONG_OFF))[tid] = (node < N) ? cong[node] : 0.f;
    }
    __syncthreads();

    // per-lane ldmatrix address components
    const int lr   = l & 7;
    const int aRow = 16 * wm + lr + ((l >> 3) & 1) * 8;
    const int aKh  = (l >> 4) * 8;
    const int bRow = lr + (l >> 4) * 8;
    const int bKh  = ((l >> 3) & 1) * 8;
    const u32 a1base = smu + P_A1_OFF + aRow * P_A1_ST + aKh * 2;

    const int m0 = 16 * wm + g, m1 = m0 + 8;
    const float cg0 = ((const float*)(sm + P_CONG_OFF))[m0];
    const float cg1 = ((const float*)(sm + P_CONG_OFF))[m1];
    const bool n0 = (base + m0 < N), n1 = (base + m1 < N);

    // ================= chunk loop over 4 x 128 output cols =================
    #pragma unroll 1
    for (int c = 0; c < 4; c++) {
        if (c > 0) __syncthreads();   // all warps done reading buf of chunk c-1
        if (c < 3) {
            int buf = (c + 1) & 1;
            #pragma unroll
            for (int r = 0; r < 4; r++) {
                int i = tid + 512 * r;
                int row = i >> 4, part = i & 15;
                CP_ASYNC16(smu + P_B_OFF + buf * P_B_BUF + row * P_B_ST + part * 16,
                           gB + (size_t)(128 * (c + 1) + row) * 256 + part * 16);
            }
            CP_COMMIT();
        }
        if (c < 3) { CP_WAIT(1); } else { CP_WAIT(0); }
        __syncthreads();

        // ---- GEMM: acc = A1 @ Wchunk[:, warp's 64 cols], K=128 ----
        float acc[8][4];
        #pragma unroll
        for (int j = 0; j < 8; j++)
            #pragma unroll
            for (int q = 0; q < 4; q++) acc[j][q] = 0.f;

        const u32 bb = smu + P_B_OFF + (c & 1) * P_B_BUF;
        #pragma unroll 2
        for (int kt = 0; kt < 8; kt++) {
            u32 fa0, fa1, fa2, fa3;
            ldsm_x4(a1base + kt * 32, fa0, fa1, fa2, fa3);
            #pragma unroll
            for (int jp = 0; jp < 4; jp++) {
                u32 nrow = (u32)(64 * wn + 16 * jp + bRow);
                u32 b0, b1, b2, b3;
                ldsm_x4(bb + nrow * P_B_ST + (u32)(16 * kt + bKh) * 2, b0, b1, b2, b3);
                mma_f16(acc[2 * jp],     fa0, fa1, fa2, fa3, b0, b1);
                mma_f16(acc[2 * jp + 1], fa0, fa1, fa2, fa3, b2, b3);
            }
        }

        // ---- epilogue: fold cong*w288 (Psrc chunks) / +mb1 (Pdst chunks) ----
        #pragma unroll
        for (int nt = 0; nt < 8; nt++) {
            int gcol = 128 * c + 64 * wn + 8 * nt + 2 * t;
            if (c < 2) {
                int col = gcol;                      // Psrc col 0..255
                float2 w2 = *(const float2*)&mW1[(size_t)288 * HD + col];
                if (n0) {
                    float v0 = acc[nt][0] + cg0 * w2.x;
                    float v1 = acc[nt][1] + cg0 * w2.y;
                    *(u32*)&g_Psrc[(size_t)(base + m0) * HD + col] = h2pack(v0, v1);
                }
                if (n1) {
                    float v0 = acc[nt][2] + cg1 * w2.x;
                    float v1 = acc[nt][3] + cg1 * w2.y;
                    *(u32*)&g_Psrc[(size_t)(base + m1) * HD + col] = h2pack(v0, v1);
                }
            } else {
                int col = gcol - 256;                // Pdst col 0..255
                float2 bv = *(const float2*)&mb1[col];
                if (n0) {
                    float v0 = acc[nt][0] + bv.x;
                    float v1 = acc[nt][1] + bv.y;
                    *(u32*)&g_Pdst[(size_t)(base + m0) * HD + col] = h2pack(v0, v1);
                }
                if (n1) {
                    float v0 = acc[nt][2] + bv.x;
                    float v1 = acc[nt][3] + bv.y;
                    *(u32*)&g_Pdst[(size_t)(base + m1) * HD + col] = h2pack(v0, v1);
                }
            }
        }
    }

    // ---- zero g_agg rows for this CTA's nodes (coalesced float4) ----
    const float4 z4 = make_float4(0.f, 0.f, 0.f, 0.f);
    for (int idx = tid; idx < 128 * 32; idx += 512) {
        int node = base + (idx >> 5);
        if (node < N)
            ((float4*)g_agg)[(size_t)node * 32 + (idx & 31)] = z4;
    }
}

// =================== K2: warp-MMA edge kernel (v7, proven) ======================
#define B1_OFF  0
#define A2_OFF  20480
#define B2_OFF  29696
#define SRC_OFF 66560
#define DST_OFF 66816
#define EDGE_SMEM 67072
#define B1_ST 80
#define A1_ST 80
#define A2_ST 144
#define B2_ST 144
#define B2_BUF 18432

__global__ __launch_bounds__(256, 2) void k_edge_mma(
    const float* __restrict__ edge_attr, const float* __restrict__ mb2, int E)
{
    extern __shared__ __align__(16) char sm[];
    const u32 smu = smem_u32(sm);
    const int tid = threadIdx.x;
    const int w = tid >> 5, l = tid & 31;
    const int wm = w & 3, wn = w >> 2;
    const int g = l >> 2, t = l & 3;
    const int base = blockIdx.x * 64;
    const char* gB2 = (const char*)g_B2h;

    #pragma unroll
    for (int r = 0; r < 4; r++) {
        int i = tid + 256 * r;
        int row = i >> 3, part = i & 7;
        CP_ASYNC16(smu + B2_OFF + row * B2_ST + part * 16,
                   gB2 + row * 512 + part * 16);
    }
    CP_COMMIT();

    if (tid < 64) {
        int e = base + tid;
        ((int*)(sm + SRC_OFF))[tid] = (e < E) ? g_src[e] : 0;
        ((int*)(sm + DST_OFF))[tid] = (e < E) ? g_dst[e] : 0;
    }
    for (int idx = tid; idx < 256 * 4; idx += 256) {
        int row = idx >> 2, ch = idx & 3;
        *(float4*)(sm + B1_OFF + row * B1_ST + ch * 16) =
            *(const float4*)((const char*)g_B1h + row * 64 + ch * 16);
    }
    if (tid < 128) {
        int e = tid >> 1, h = tid & 1;
        char* arow = sm + A2_OFF + e * A1_ST;
        if (base + e < E) {
            const float4* src4 = (const float4*)(edge_attr + (size_t)(base + e) * ED + 16 * h);
            #pragma unroll
            for (int q = 0; q < 4; q++) {
                float4 v = src4[q];
                int k = 16 * h + 4 * q;
                *(u32*)(arow + k * 2)       = h2pack(v.x, v.y);
                *(u32*)(arow + (k + 2) * 2) = h2pack(v.z, v.w);
            }
        } else {
            #pragma unroll
            for (int q = 0; q < 8; q++)
                *(u32*)(arow + (16 * h + 2 * q) * 2) = 0u;
        }
    }
    __syncthreads();

    const int lr   = l & 7;
    const int aRow = 16 * wm + lr + ((l >> 3) & 1) * 8;
    const int aKh  = (l >> 4) * 8;
    const int bRow = lr + (l >> 4) * 8;
    const int bKh  = ((l >> 3) & 1) * 8;
    const u32 a1base = smu + A2_OFF + aRow * A1_ST + aKh * 2;
    const u32 a2base = smu + A2_OFF + aRow * A2_ST + aKh * 2;

    u32 fa[2][4];
    #pragma unroll
    for (int kt = 0; kt < 2; kt++)
        ldsm_x4(a1base + kt * 32, fa[kt][0], fa[kt][1], fa[kt][2], fa[kt][3]);

    const int m0 = 16 * wm + g, m1 = m0 + 8;
    const int vs0 = ((const int*)(sm + SRC_OFF))[m0];
    const int vd0 = ((const int*)(sm + DST_OFF))[m0];
    const int vs1 = ((const int*)(sm + SRC_OFF))[m1];
    const int vd1 = ((const int*)(sm + DST_OFF))[m1];
    char* a2r0 = sm + A2_OFF + m0 * A2_ST;
    char* a2r1 = sm + A2_OFF + m1 * A2_ST;

    float acc2[8][4];
    #pragma unroll
    for (int j = 0; j < 8; j++)
        #pragma unroll
        for (int q = 0; q < 4; q++) acc2[j][q] = 0.f;

    #pragma unroll 1
    for (int c = 0; c < 4; c++) {
        u32 ps0[4], pd0[4], ps1[4], pd1[4];
        #pragma unroll
        for (int nt = 0; nt < 4; nt++) {
            int col = 64 * c + 32 * wn + 8 * nt + 2 * t;
            ps0[nt] = *(const u32*)(g_Psrc + (size_t)vs0 * HD + col);
            pd0[nt] = *(const u32*)(g_Pdst + (size_t)vd0 * HD + col);
            ps1[nt] = *(const u32*)(g_Psrc + (size_t)vs1 * HD + col);
            pd1[nt] = *(const u32*)(g_Pdst + (size_t)vd1 * HD + col);
        }

        float acc1[4][4];
        #pragma unroll
        for (int j = 0; j < 4; j++)
            #pragma unroll
            for (int q = 0; q < 4; q++) acc1[j][q] = 0.f;

        #pragma unroll
        for (int jp = 0; jp < 2; jp++) {
            u32 bb = smu + B1_OFF + (64 * c + 32 * wn + 16 * jp + bRow) * B1_ST + bKh * 2;
            u32 b0, b1, b2, b3;
            ldsm_x4(bb + 0, b0, b1, b2, b3);
            mma_f16(acc1[2 * jp],     fa[0][0], fa[0][1], fa[0][2], fa[0][3], b0, b1);
            mma_f16(acc1[2 * jp + 1], fa[0][0], fa[0][1], fa[0][2], fa[0][3], b2, b3);
            ldsm_x4(bb + 32, b0, b1, b2, b3);
            mma_f16(acc1[2 * jp],     fa[1][0], fa[1][1], fa[1][2], fa[1][3], b0, b1);
            mma_f16(acc1[2 * jp + 1], fa[1][0], fa[1][1], fa[1][2], fa[1][3], b2, b3);
        }

        __syncthreads();

        if (c < 3) {
            int buf = (c + 1) & 1;
            #pragma unroll
            for (int r = 0; r < 4; r++) {
                int i = tid + 256 * r;
                int row = i >> 3, part = i & 7;
                CP_ASYNC16(smu + B2_OFF + buf * B2_BUF + row * B2_ST + part * 16,
                           gB2 + row * 512 + 128 * (c + 1) + part * 16);
            }
            CP_COMMIT();
        }

        #pragma unroll
        for (int nt = 0; nt < 4; nt++) {
            int lc = 32 * wn + 8 * nt + 2 * t;
            float2 a0 = h2unpack(ps0[nt]), b0 = h2unpack(pd0[nt]);
            float2 a1 = h2unpack(ps1[nt]), b1 = h2unpack(pd1[nt]);
            float v00 = fmaxf(acc1[nt][0] + a0.x + b0.x, 0.f);
            float v01 = fmaxf(acc1[nt][1] + a0.y + b0.y, 0.f);
            float v10 = fmaxf(acc1[nt][2] + a1.x + b1.x, 0.f);
            float v11 = fmaxf(acc1[nt][3] + a1.y + b1.y, 0.f);
            *(u32*)(a2r0 + lc * 2) = h2pack(v00, v01);
            *(u32*)(a2r1 + lc * 2) = h2pack(v10, v11);
        }

        if (c < 3) { CP_WAIT(1); } else { CP_WAIT(0); }
        __syncthreads();

        const u32 b2b = smu + B2_OFF + (c & 1) * B2_BUF;
        #pragma unroll
        for (int t4 = 0; t4 < 4; t4++) {
            u32 ah0, ah1, ah2, ah3;
            ldsm_x4(a2base + t4 * 32, ah0, ah1, ah2, ah3);
            #pragma unroll
            for (int jp = 0; jp < 4; jp++) {
                u32 nrow = (u32)(64 * wn + 16 * jp + bRow);
                u32 kof  = (u32)(16 * t4 + bKh) * 2;
                u32 b0, b1, b2, b3;
                ldsm_x4(b2b + nrow * B2_ST + kof, b0, b1, b2, b3);
                mma_f16(acc2[2 * jp],     ah0, ah1, ah2, ah3, b0, b1);
                mma_f16(acc2[2 * jp + 1], ah0, ah1, ah2, ah3, b2, b3);
            }
        }
    }

    const bool e0 = (base + m0 < E), e1 = (base + m1 < E);
    #pragma unroll
    for (int j = 0; j < 8; j++) {
        int n = 64 * wn + 8 * j + 2 * t;
        float2 bv = *(const float2*)(mb2 + n);
        if (e0) {
            float x0 = acc2[j][0] + bv.x, x1 = acc2[j][1] + bv.y;
            asm volatile("red.global.add.v2.f32 [%0], {%1, %2};"
                         :: "l"(g_agg + (size_t)vd0 * ND + n), "f"(x0), "f"(x1) : "memory");
        }
        if (e1) {
            float x0 = acc2[j][2] + bv.x, x1 = acc2[j][3] + bv.y;
            asm volatile("red.global.add.v2.f32 [%0], {%1, %2};"
                         :: "l"(g_agg + (size_t)vd1 * ND + n), "f"(x0), "f"(x1) : "memory");
        }
    }
}

// =================== K3: warp-MMA node update (proven) ==========================
#define U_A1_OFF 0
#define U_A2_OFF 67584
#define U_B1_OFF 86016
#define U_B2_OFF 153600
#define U_SMEM   190464
#define U_A1_ST  528
#define U_A2_ST  144
#define U_B1_ST  528
#define U_B2_ST  144
#define U_B1_BUF 33792
#define U_B2_BUF 18432

__global__ __launch_bounds__(512, 1) void k_update_mma(
    const float* __restrict__ x,
    const float* __restrict__ ub1, const float* __restrict__ ub2,
    float* __restrict__ out, int N)
{
    extern __shared__ __align__(16) char sm[];
    const u32 smu = smem_u32(sm);
    const int tid = threadIdx.x;
    const int w = tid >> 5, l = tid & 31;
    const int wm = w & 7, wn = w >> 3;
    const int g = l >> 2, t = l & 3;
    const int base = blockIdx.x * 128;
    const char* gB1 = (const char*)g_U1h;
    const char* gB2 = (const char*)g_U2h;

    #pragma unroll
    for (int r = 0; r < 4; r++) {
        int i = tid + 512 * r;
        int row = i >> 5, part = i & 31;
        CP_ASYNC16(smu + U_B1_OFF + row * U_B1_ST + part * 16,
                   gB1 + row * 512 + part * 16);
    }
    #pragma unroll
    for (int r = 0; r < 2; r++) {
        int i = tid + 512 * r;
        int row = i >> 3, part = i & 7;
        CP_ASYNC16(smu + U_B2_OFF + row * U_B2_ST + part * 16,
                   gB2 + row * 512 + part * 16);
    }
    CP_COMMIT();

    {
        int row = tid >> 2, q = tid & 3;
        int node = base + row;
        char* arow = sm + U_A1_OFF + row * U_A1_ST + q * 128;
        if (node < N) {
            const float4* srcp = (q < 2)
                ? (const float4*)(x + (size_t)node * ND + 64 * q)
                : (const float4*)(g_agg + (size_t)node * ND + 64 * (q - 2));
            #pragma unroll
            for (int i = 0; i < 16; i++) {
                float4 v = srcp[i];
                *(u32*)(arow + i * 8)     = h2pack(v.x, v.y);
                *(u32*)(arow + i * 8 + 4) = h2pack(v.z, v.w);
            }
        } else {
            #pragma unroll
            for (int i = 0; i < 32; i++) *(u32*)(arow + i * 4) = 0u;
        }
    }
    __syncthreads();

    const int lr   = l & 7;
    const int aRow = 16 * wm + lr + ((l >> 3) & 1) * 8;
    const int aKh  = (l >> 4) * 8;
    const int bRow = lr + (l >> 4) * 8;
    const int bKh  = ((l >> 3) & 1) * 8;
    const u32 a1base = smu + U_A1_OFF + aRow * U_A1_ST + aKh * 2;
    const u32 a2base = smu + U_A2_OFF + aRow * U_A2_ST + aKh * 2;

    const int m0 = 16 * wm + g, m1 = m0 + 8;
    char* a2r0 = sm + U_A2_OFF + m0 * U_A2_ST;
    char* a2r1 = sm + U_A2_OFF + m1 * U_A2_ST;

    float acc2[8][4];
    #pragma unroll
    for (int j = 0; j < 8; j++)
        #pragma unroll
        for (int q = 0; q < 4; q++) acc2[j][q] = 0.f;

    #pragma unroll 1
    for (int c = 0; c < 4; c++) {
        if (c > 0) __syncthreads();
        if (c < 3) {
            int buf = (c + 1) & 1;
            #pragma unroll
            for (int r = 0; r < 4; r++) {
                int i = tid + 512 * r;
                int row = i >> 5, part = i & 31;
                CP_ASYNC16(smu + U_B1_OFF + buf * U_B1_BUF + row * U_B1_ST + part * 16,
                           gB1 + (size_t)(64 * (c + 1) + row) * 512 + part * 16);
            }
            #pragma unroll
            for (int r = 0; r < 2; r++) {
                int i = tid + 512 * r;
                int row = i >> 3, part = i & 7;
                CP_ASYNC16(smu + U_B2_OFF + buf * U_B2_BUF + row * U_B2_ST + part * 16,
                           gB2 + row * 512 + 128 * (c + 1) + part * 16);
            }
            CP_COMMIT();
        }
        if (c < 3) { CP_WAIT(1); } else { CP_WAIT(0); }
        __syncthreads();

        float acc1[4][4];
        #pragma unroll
        for (int j = 0; j < 4; j++)
            #pragma unroll
            for (int q = 0; q < 4; q++) acc1[j][q] = 0.f;

        const u32 b1b = smu + U_B1_OFF + (c & 1) * U_B1_BUF;
        #pragma unroll 2
        for (int kt = 0; kt < 16; kt++) {
            u32 fa0, fa1, fa2, fa3;
            ldsm_x4(a1base + kt * 32, fa0, fa1, fa2, fa3);
            #pragma unroll
            for (int jp = 0; jp < 2; jp++) {
                u32 nrow = (u32)(32 * wn + 16 * jp + bRow);
                u32 b0, b1, b2, b3;
                ldsm_x4(b1b + nrow * U_B1_ST + (u32)(16 * kt + bKh) * 2, b0, b1, b2, b3);
                mma_f16(acc1[2 * jp],     fa0, fa1, fa2, fa3, b0, b1);
                mma_f16(acc1[2 * jp + 1], fa0, fa1, fa2, fa3, b2, b3);
            }
        }

        #pragma unroll
        for (int nt = 0; nt < 4; nt++) {
            int col = 64 * c + 32 * wn + 8 * nt + 2 * t;
            int lc  = 32 * wn + 8 * nt + 2 * t;
            float2 bv = *(const float2*)(ub1 + col);
            float v00 = fmaxf(acc1[nt][0] + bv.x, 0.f);
            float v01 = fmaxf(acc1[nt][1] + bv.y, 0.f);
            float v10 = fmaxf(acc1[nt][2] + bv.x, 0.f);
            float v11 = fmaxf(acc1[nt][3] + bv.y, 0.f);
            *(u32*)(a2r0 + lc * 2) = h2pack(v00, v01);
            *(u32*)(a2r1 + lc * 2) = h2pack(v10, v11);
        }
        __syncthreads();

        const u32 b2b = smu + U_B2_OFF + (c & 1) * U_B2_BUF;
        #pragma unroll
        for (int t4 = 0; t4 < 4; t4++) {
            u32 ah0, ah1, ah2, ah3;
            ldsm_x4(a2base + t4 * 32, ah0, ah1, ah2, ah3);
            #pragma unroll
            for (int jp = 0; jp < 4; jp++) {
                u32 nrow = (u32)(64 * wn + 16 * jp + bRow);
                u32 kof  = (u32)(16 * t4 + bKh) * 2;
                u32 b0, b1, b2, b3;
                ldsm_x4(b2b + nrow * U_B2_ST + kof, b0, b1, b2, b3);
                mma_f16(acc2[2 * jp],     ah0, ah1, ah2, ah3, b0, b1);
                mma_f16(acc2[2 * jp + 1], ah0, ah1, ah2, ah3, b2, b3);
            }
        }
    }

    const bool n0 = (base + m0 < N), n1 = (base + m1 < N);
    #pragma unroll
    for (int j = 0; j < 8; j++) {
        int n = 64 * wn + 8 * j + 2 * t;
        float2 bv = *(const float2*)(ub2 + n);
        if (n0) {
            float2 r = make_float2(acc2[j][0] + bv.x, acc2[j][1] + bv.y);
            *(float2*)&out[(size_t)(base + m0) * ND + n] = r;
        }
        if (n1) {
            float2 r = make_float2(acc2[j][2] + bv.x, acc2[j][3] + bv.y);
            *(float2*)&out[(size_t)(base + m1) * ND + n] = r;
        }
    }
}

// =================== launcher ===================================================
extern "C" void kernel_launch(void* const* d_in, const int* in_sizes, int n_in,
                              void* d_out, int out_size)
{
    const float* x    = (const float*)d_in[0];
    const int*   ei   = (const int*)  d_in[1];
    const float* ea   = (const float*)d_in[2];
    const float* cong = (const float*)d_in[3];
    const float* mW1  = (const float*)d_in[4];
    const float* mb1  = (const float*)d_in[5];
    const float* mW2  = (const float*)d_in[6];
    const float* mb2  = (const float*)d_in[7];
    const float* uW1  = (const float*)d_in[8];
    const float* ub1  = (const float*)d_in[9];
    const float* uW2  = (const float*)d_in[10];
    const float* ub2  = (const float*)d_in[11];

    int N = in_sizes[0] / ND;
    int E = in_sizes[1] / 2;
    if (N > N_MAX) N = N_MAX;
    if (E > E_MAX) E = E_MAX;

    cudaFuncSetAttribute(k_pre_mma,    cudaFuncAttributeMaxDynamicSharedMemorySize, P_SMEM);
    cudaFuncSetAttribute(k_edge_mma,   cudaFuncAttributeMaxDynamicSharedMemorySize, EDGE_SMEM);
    cudaFuncSetAttribute(k_update_mma, cudaFuncAttributeMaxDynamicSharedMemorySize, U_SMEM);

    k_convert    <<<(E + 255) / 256, 256>>>(ei, E);
    k_prep       <<<160, 256>>>(mW1, mW2, uW1, uW2);
    k_pre_mma    <<<(N + 127) / 128, 512, P_SMEM>>>(x, cong, mW1, mb1, N);
    k_edge_mma   <<<(E + 63) / 64, 256, EDGE_SMEM>>>(ea, mb2, E);
    k_update_mma <<<(N + 127) / 128, 512, U_SMEM>>>(x, ub1, ub2, (float*)d_out, N);
}

// round 13
// speedup vs baseline: 2.7744x; 1.1940x over previous
#include <cuda_runtime.h>
#include <cuda_fp16.h>
#include <cstdint>

#define ND 128
#define ED 32
#define HD 256
#define N_MAX 100000
#define E_MAX 1600000

typedef unsigned long long u64;
typedef unsigned int u32;

// ---------------- warp-MMA helpers (family-compatible: sm_80+) ----------------
__device__ __forceinline__ u32 smem_u32(const void* p) {
    u32 a;
    asm("{ .reg .u64 t; cvta.to.shared.u64 t, %1; cvt.u32.u64 %0, t; }" : "=r"(a) : "l"(p));
    return a;
}
__device__ __forceinline__ void ldsm_x4(u32 addr, u32& r0, u32& r1, u32& r2, u32& r3) {
    asm volatile("ldmatrix.sync.aligned.m8n8.x4.shared.b16 {%0,%1,%2,%3}, [%4];"
        : "=r"(r0), "=r"(r1), "=r"(r2), "=r"(r3) : "r"(addr));
}
__device__ __forceinline__ void mma_f16(float* d, u32 a0, u32 a1, u32 a2, u32 a3,
                                        u32 b0, u32 b1) {
    asm volatile("mma.sync.aligned.m16n8k16.row.col.f32.f16.f16.f32 "
        "{%0,%1,%2,%3}, {%4,%5,%6,%7}, {%8,%9}, {%0,%1,%2,%3};"
        : "+f"(d[0]), "+f"(d[1]), "+f"(d[2]), "+f"(d[3])
        : "r"(a0), "r"(a1), "r"(a2), "r"(a3), "r"(b0), "r"(b1));
}
__device__ __forceinline__ u32 h2pack(float a, float b) {
    __half2 h = __floats2half2_rn(a, b);
    return *(u32*)&h;
}
__device__ __forceinline__ float2 h2unpack(u32 p) {
    return __half22float2(*(__half2*)&p);
}
#define CP_ASYNC16(d, s) asm volatile("cp.async.cg.shared.global [%0], [%1], 16;" :: "r"(d), "l"(s) : "memory")
#define CP_COMMIT()      asm volatile("cp.async.commit_group;" ::: "memory")
#define CP_WAIT(n)       asm volatile("cp.async.wait_group %0;" :: "n"(n) : "memory")

// ---------------- scratch ----------------
__device__ int   g_src[E_MAX];
__device__ int   g_dst[E_MAX];
// fp16 node partials: 2 x 100k x 256 x 2B = 102 MB total -> fits in 126 MB L2
__device__ __align__(16) __half g_Psrc[(size_t)N_MAX * HD];
__device__ __align__(16) __half g_Pdst[(size_t)N_MAX * HD];
__device__ float g_agg [(size_t)N_MAX * ND];
// fp16 weight images (row-major, [n][k])
__device__ __align__(16) __half g_B1h[256 * 32];    // W1c^T  [n=256][k=32]
__device__ __align__(16) __half g_B2h[128 * 256];   // W2^T   [n=128][k=256]
__device__ __align__(16) __half g_U1h[256 * 256];   // uW1^T  [n=256][k=256]
__device__ __align__(16) __half g_U2h[128 * 256];   // uW2^T  [n=128][k=256]
__device__ __align__(16) __half g_P1h[512 * 128];   // [W1a|W1b]^T

// =================== K0: edge_index convert (int64 OR int32) ===================
__global__ void k_convert(const int* __restrict__ w, int E)
{
    __shared__ int s64;
    if (threadIdx.x == 0) {
        int b = 1;
        #pragma unroll
        for (int i = 0; i < 8; i++) if (w[2 * i + 1] != 0) b = 0;
        s64 = b;
    }
    __syncthreads();
    int i = blockIdx.x * blockDim.x + threadIdx.x;
    if (i >= E) return;
    if (s64) {
        const long long* e = (const long long*)w;
        g_src[i] = (int)e[i];
        g_dst[i] = (int)e[(size_t)E + i];
    } else {
        g_src[i] = w[i];
        g_dst[i] = w[(size_t)E + i];
    }
}

// =================== K_prep: build fp16 weight images ===========================
__global__ void k_prep(const float* __restrict__ mW1, const float* __restrict__ mW2,
                       const float* __restrict__ uW1, const float* __restrict__ uW2)
{
    int tid = blockIdx.x * blockDim.x + threadIdx.x;
    const int S1 = 256 * 32, S2 = S1 + 128 * 256, S3 = S2 + 256 * 256,
              S4 = S3 + 128 * 256;
    int total = S4 + 512 * 128;
    for (int i = tid; i < total; i += gridDim.x * blockDim.x) {
        if (i < S1) {
            int n = i >> 5, k = i & 31;
            g_B1h[n * 32 + k] = __float2half(mW1[(size_t)(2 * ND + k) * HD + n]);
        } else if (i < S2) {
            int q = i - S1;
            int n = q >> 8, j = q & 255;
            g_B2h[n * 256 + j] = __float2half(mW2[(size_t)j * ND + n]);
        } else if (i < S3) {
            int q = i - S2;
            int n = q >> 8, k = q & 255;
            g_U1h[n * 256 + k] = __float2half(uW1[(size_t)k * HD + n]);
        } else if (i < S4) {
            int q = i - S3;
            int n = q >> 8, k = q & 255;
            g_U2h[n * 256 + k] = __float2half(uW2[(size_t)k * ND + n]);
        } else {
            int q = i - S4;
            int n = q >> 7, k = q & 127;
            float v = (n < 256) ? mW1[(size_t)k * HD + n]
                                : mW1[(size_t)(128 + k) * HD + (n - 256)];
            g_P1h[n * 128 + k] = __float2half(v);
        }
    }
}

// =================== K1: warp-MMA node precompute (proven) ======================
#define P_A1_OFF   0
#define P_CONG_OFF 34816
#define P_B_OFF    35328
#define P_SMEM     104960
#define P_A1_ST    272
#define P_B_ST     272
#define P_B_BUF    34816

__global__ __launch_bounds__(512, 1) void k_pre_mma(
    const float* __restrict__ x, const float* __restrict__ cong,
    const float* __restrict__ mW1, const float* __restrict__ mb1, int N)
{
    extern __shared__ __align__(16) char sm[];
    const u32 smu = smem_u32(sm);
    const int tid = threadIdx.x;
    const int w = tid >> 5, l = tid & 31;
    const int wm = w & 7, wn = w >> 3;
    const int g = l >> 2, t = l & 3;
    const int base = blockIdx.x * 128;
    const char* gB = (const char*)g_P1h;

    #pragma unroll
    for (int r = 0; r < 4; r++) {
        int i = tid + 512 * r;
        int row = i >> 4, part = i & 15;
        CP_ASYNC16(smu + P_B_OFF + row * P_B_ST + part * 16,
                   gB + row * 256 + part * 16);
    }
    CP_COMMIT();

    {
        int row = tid >> 2, q = tid & 3;
        int node = base + row;
        char* arow = sm + P_A1_OFF + row * P_A1_ST + q * 64;
        if (node < N) {
            const float4* srcp = (const float4*)(x + (size_t)node * ND + 32 * q);
            #pragma unroll
            for (int i = 0; i < 8; i++) {
                float4 v = srcp[i];
                *(u32*)(arow + i * 8)     = h2pack(v.x, v.y);
                *(u32*)(arow + i * 8 + 4) = h2pack(v.z, v.w);
            }
        } else {
            #pragma unroll
            for (int i = 0; i < 16; i++) *(u32*)(arow + i * 4) = 0u;
        }
    }
    if (tid < 128) {
        int node = base + tid;
        ((float*)(sm + P_CONG_OFF))[tid] = (node < N) ? cong[node] : 0.f;
    }
    __syncthreads();

    const int lr   = l & 7;
    const int aRow = 16 * wm + lr + ((l >> 3) & 1) * 8;
    const int aKh  = (l >> 4) * 8;
    const int bRow = lr + (l >> 4) * 8;
    const int bKh  = ((l >> 3) & 1) * 8;
    const u32 a1base = smu + P_A1_OFF + aRow * P_A1_ST + aKh * 2;

    const int m0 = 16 * wm + g, m1 = m0 + 8;
    const float cg0 = ((const float*)(sm + P_CONG_OFF))[m0];
    const float cg1 = ((const float*)(sm + P_CONG_OFF))[m1];
    const bool n0 = (base + m0 < N), n1 = (base + m1 < N);

    #pragma unroll 1
    for (int c = 0; c < 4; c++) {
        if (c > 0) __syncthreads();
        if (c < 3) {
            int buf = (c + 1) & 1;
            #pragma unroll
            for (int r = 0; r < 4; r++) {
                int i = tid + 512 * r;
                int row = i >> 4, part = i & 15;
                CP_ASYNC16(smu + P_B_OFF + buf * P_B_BUF + row * P_B_ST + part * 16,
                           gB + (size_t)(128 * (c + 1) + row) * 256 + part * 16);
            }
            CP_COMMIT();
        }
        if (c < 3) { CP_WAIT(1); } else { CP_WAIT(0); }
        __syncthreads();

        float acc[8][4];
        #pragma unroll
        for (int j = 0; j < 8; j++)
            #pragma unroll
            for (int q = 0; q < 4; q++) acc[j][q] = 0.f;

        const u32 bb = smu + P_B_OFF + (c & 1) * P_B_BUF;
        #pragma unroll 2
        for (int kt = 0; kt < 8; kt++) {
            u32 fa0, fa1, fa2, fa3;
            ldsm_x4(a1base + kt * 32, fa0, fa1, fa2, fa3);
            #pragma unroll
            for (int jp = 0; jp < 4; jp++) {
                u32 nrow = (u32)(64 * wn + 16 * jp + bRow);
                u32 b0, b1, b2, b3;
                ldsm_x4(bb + nrow * P_B_ST + (u32)(16 * kt + bKh) * 2, b0, b1, b2, b3);
                mma_f16(acc[2 * jp],     fa0, fa1, fa2, fa3, b0, b1);
                mma_f16(acc[2 * jp + 1], fa0, fa1, fa2, fa3, b2, b3);
            }
        }

        #pragma unroll
        for (int nt = 0; nt < 8; nt++) {
            int gcol = 128 * c + 64 * wn + 8 * nt + 2 * t;
            if (c < 2) {
                int col = gcol;
                float2 w2 = *(const float2*)&mW1[(size_t)288 * HD + col];
                if (n0) {
                    float v0 = acc[nt][0] + cg0 * w2.x;
                    float v1 = acc[nt][1] + cg0 * w2.y;
                    *(u32*)&g_Psrc[(size_t)(base + m0) * HD + col] = h2pack(v0, v1);
                }
                if (n1) {
                    float v0 = acc[nt][2] + cg1 * w2.x;
                    float v1 = acc[nt][3] + cg1 * w2.y;
                    *(u32*)&g_Psrc[(size_t)(base + m1) * HD + col] = h2pack(v0, v1);
                }
            } else {
                int col = gcol - 256;
                float2 bv = *(const float2*)&mb1[col];
                if (n0) {
                    float v0 = acc[nt][0] + bv.x;
                    float v1 = acc[nt][1] + bv.y;
                    *(u32*)&g_Pdst[(size_t)(base + m0) * HD + col] = h2pack(v0, v1);
                }
                if (n1) {
                    float v0 = acc[nt][2] + bv.x;
                    float v1 = acc[nt][3] + bv.y;
                    *(u32*)&g_Pdst[(size_t)(base + m1) * HD + col] = h2pack(v0, v1);
                }
            }
        }
    }

    const float4 z4 = make_float4(0.f, 0.f, 0.f, 0.f);
    for (int idx = tid; idx < 128 * 32; idx += 512) {
        int node = base + (idx >> 5);
        if (node < N)
            ((float4*)g_agg)[(size_t)node * 32 + (idx & 31)] = z4;
    }
}

// =================== K2: warp-MMA edge kernel (v8: cp.async gather staging) =====
// 64 edges/CTA, 256 threads, 2 CTAs/SM. Node-partial gathers are staged through
// smem via row-contiguous 16B cp.async (double-buffered, one chunk ahead,
// committed with the B2 prefetch). Epilogue reads conflict-free LDS.32.
// smem layout (bytes):
//   B1  @ 0       [256 rows][32 halves]  stride 80    20480
//   A2c @ 20480   [64 rows][64 halves]   stride 144    9216  (A1 [64][80B] aliases)
//   B2  @ 29696   2 bufs x [128 rows][64 halves] st144 36864
//   PS  @ 66560   2 bufs x { Psrc[64][72h] st144 | Pdst +9216 } 36864
//   src @ 103424  int[64];  dst @ 103680 int[64]
#define B1_OFF  0
#define A2_OFF  20480
#define B2_OFF  29696
#define PS_OFF  66560
#define SRC_OFF 103424
#define DST_OFF 103680
#define EDGE_SMEM 103936
#define B1_ST 80
#define A1_ST 80
#define A2_ST 144
#define B2_ST 144
#define PS_ST 144
#define B2_BUF 18432
#define PS_BUF 18432

__global__ __launch_bounds__(256, 2) void k_edge_mma(
    const float* __restrict__ edge_attr, const float* __restrict__ mb2, int E)
{
    extern __shared__ __align__(16) char sm[];
    const u32 smu = smem_u32(sm);
    const int tid = threadIdx.x;
    const int w = tid >> 5, l = tid & 31;
    const int wm = w & 3, wn = w >> 2;
    const int g = l >> 2, t = l & 3;
    const int base = blockIdx.x * 64;
    const char* gB2 = (const char*)g_B2h;

    // ---- group 0: B2 chunk 0 ----
    #pragma unroll
    for (int r = 0; r < 4; r++) {
        int i = tid + 256 * r;
        int row = i >> 3, part = i & 7;
        CP_ASYNC16(smu + B2_OFF + row * B2_ST + part * 16,
                   gB2 + row * 512 + part * 16);
    }
    CP_COMMIT();

    // ---- stage src/dst ----
    if (tid < 64) {
        int e = base + tid;
        ((int*)(sm + SRC_OFF))[tid] = (e < E) ? g_src[e] : 0;
        ((int*)(sm + DST_OFF))[tid] = (e < E) ? g_dst[e] : 0;
    }
    // ---- stage B1: 256 rows x 64B ----
    for (int idx = tid; idx < 256 * 4; idx += 256) {
        int row = idx >> 2, ch = idx & 3;
        *(float4*)(sm + B1_OFF + row * B1_ST + ch * 16) =
            *(const float4*)((const char*)g_B1h + row * 64 + ch * 16);
    }
    // ---- stage A1 (aliases A2c region): edge_attr -> fp16 ----
    if (tid < 128) {
        int e = tid >> 1, h = tid & 1;
        char* arow = sm + A2_OFF + e * A1_ST;
        if (base + e < E) {
            const float4* src4 = (const float4*)(edge_attr + (size_t)(base + e) * ED + 16 * h);
            #pragma unroll
            for (int q = 0; q < 4; q++) {
                float4 v = src4[q];
                int k = 16 * h + 4 * q;
                *(u32*)(arow + k * 2)       = h2pack(v.x, v.y);
                *(u32*)(arow + (k + 2) * 2) = h2pack(v.z, v.w);
            }
        } else {
            #pragma unroll
            for (int q = 0; q < 8; q++)
                *(u32*)(arow + (16 * h + 2 * q) * 2) = 0u;
        }
    }
    __syncthreads();   // src/dst + A1 + B1 visible

    // ---- group 1: PS chunk 0 (row-contiguous gathers of Psrc/Pdst) ----
    #pragma unroll
    for (int r = 0; r < 2; r++) {
        int idx = tid + 256 * r;           // 0..511
        int row = idx >> 3, part = idx & 7;
        int vs = ((const int*)(sm + SRC_OFF))[row];
        int vd = ((const int*)(sm + DST_OFF))[row];
        CP_ASYNC16(smu + PS_OFF + row * PS_ST + part * 16,
                   (const char*)g_Psrc + ((size_t)vs * HD) * 2 + part * 16);
        CP_ASYNC16(smu + PS_OFF + 9216 + row * PS_ST + part * 16,
                   (const char*)g_Pdst + ((size_t)vd * HD) * 2 + part * 16);
    }
    CP_COMMIT();

    // per-lane ldmatrix address components
    const int lr   = l & 7;
    const int aRow = 16 * wm + lr + ((l >> 3) & 1) * 8;
    const int aKh  = (l >> 4) * 8;
    const int bRow = lr + (l >> 4) * 8;
    const int bKh  = ((l >> 3) & 1) * 8;
    const u32 a1base = smu + A2_OFF + aRow * A1_ST + aKh * 2;  // A1 alias
    const u32 a2base = smu + A2_OFF + aRow * A2_ST + aKh * 2;

    // A1 fragments cached for all chunks
    u32 fa[2][4];
    #pragma unroll
    for (int kt = 0; kt < 2; kt++)
        ldsm_x4(a1base + kt * 32, fa[kt][0], fa[kt][1], fa[kt][2], fa[kt][3]);

    const int m0 = 16 * wm + g, m1 = m0 + 8;
    const int vd0 = ((const int*)(sm + DST_OFF))[m0];
    const int vd1 = ((const int*)(sm + DST_OFF))[m1];
    char* a2r0 = sm + A2_OFF + m0 * A2_ST;
    char* a2r1 = sm + A2_OFF + m1 * A2_ST;

    float acc2[8][4];
    #pragma unroll
    for (int j = 0; j < 8; j++)
        #pragma unroll
        for (int q = 0; q < 4; q++) acc2[j][q] = 0.f;

    // ================= fused chunk loop =================
    #pragma unroll 1
    for (int c = 0; c < 4; c++) {
        // ---- layer 1: acc1 = EA @ W1c[:, warp's 32 cols of chunk c] ----
        float acc1[4][4];
        #pragma unroll
        for (int j = 0; j < 4; j++)
            #pragma unroll
            for (int q = 0; q < 4; q++) acc1[j][q] = 0.f;

        #pragma unroll
        for (int jp = 0; jp < 2; jp++) {
            u32 bb = smu + B1_OFF + (64 * c + 32 * wn + 16 * jp + bRow) * B1_ST + bKh * 2;
            u32 b0, b1, b2, b3;
            ldsm_x4(bb + 0, b0, b1, b2, b3);      // k0-15
            mma_f16(acc1[2 * jp],     fa[0][0], fa[0][1], fa[0][2], fa[0][3], b0, b1);
            mma_f16(acc1[2 * jp + 1], fa[0][0], fa[0][1], fa[0][2], fa[0][3], b2, b3);
            ldsm_x4(bb + 32, b0, b1, b2, b3);     // k16-31
            mma_f16(acc1[2 * jp],     fa[1][0], fa[1][1], fa[1][2], fa[1][3], b0, b1);
            mma_f16(acc1[2 * jp + 1], fa[1][0], fa[1][1], fa[1][2], fa[1][3], b2, b3);
        }

        // all warps past layer2(c-1): A2c, B2 buf (c+1)&1, PS buf (c+1)&1 reusable
        __syncthreads();

        // ---- prefetch group for chunk c+1: B2 + PS gathers ----
        if (c < 3) {
            int buf = (c + 1) & 1;
            #pragma unroll
            for (int r = 0; r < 4; r++) {
                int i = tid + 256 * r;
                int row = i >> 3, part = i & 7;
                CP_ASYNC16(smu + B2_OFF + buf * B2_BUF + row * B2_ST + part * 16,
                           gB2 + row * 512 + 128 * (c + 1) + part * 16);
            }
            #pragma unroll
            for (int r = 0; r < 2; r++) {
                int idx = tid + 256 * r;
                int row = idx >> 3, part = idx & 7;
                int vs = ((const int*)(sm + SRC_OFF))[row];
                int vd = ((const int*)(sm + DST_OFF))[row];
                CP_ASYNC16(smu + PS_OFF + buf * PS_BUF + row * PS_ST + part * 16,
                           (const char*)g_Psrc + ((size_t)vs * HD + 64 * (c + 1)) * 2 + part * 16);
                CP_ASYNC16(smu + PS_OFF + buf * PS_BUF + 9216 + row * PS_ST + part * 16,
                           (const char*)g_Pdst + ((size_t)vd * HD + 64 * (c + 1)) * 2 + part * 16);
            }
            CP_COMMIT();
        }

        // wait for chunk-c group (B2(c) + PS(c)), then make visible
        if (c < 3) { CP_WAIT(1); } else { CP_WAIT(0); }
        __syncthreads();

        // ---- epilogue: read staged partials (LDS), relu, fp16 into A2c ----
        const char* psb = sm + PS_OFF + (c & 1) * PS_BUF;
        #pragma unroll
        for (int nt = 0; nt < 4; nt++) {
            int lc = 32 * wn + 8 * nt + 2 * t;
            u32 ps0 = *(const u32*)(psb + m0 * PS_ST + lc * 2);
            u32 pd0 = *(const u32*)(psb + 9216 + m0 * PS_ST + lc * 2);
            u32 ps1 = *(const u32*)(psb + m1 * PS_ST + lc * 2);
            u32 pd1 = *(const u32*)(psb + 9216 + m1 * PS_ST + lc * 2);
            float2 a0 = h2unpack(ps0), b0 = h2unpack(pd0);
            float2 a1 = h2unpack(ps1), b1 = h2unpack(pd1);
            float v00 = fmaxf(acc1[nt][0] + a0.x + b0.x, 0.f);
            float v01 = fmaxf(acc1[nt][1] + a0.y + b0.y, 0.f);
            float v10 = fmaxf(acc1[nt][2] + a1.x + b1.x, 0.f);
            float v11 = fmaxf(acc1[nt][3] + a1.y + b1.y, 0.f);
            *(u32*)(a2r0 + lc * 2) = h2pack(v00, v01);
            *(u32*)(a2r1 + lc * 2) = h2pack(v10, v11);
        }
        __syncthreads();

        // ---- layer 2: acc2 += h_chunk @ W2_chunk ----
        const u32 b2b = smu + B2_OFF + (c & 1) * B2_BUF;
        #pragma unroll
        for (int t4 = 0; t4 < 4; t4++) {
            u32 ah0, ah1, ah2, ah3;
            ldsm_x4(a2base + t4 * 32, ah0, ah1, ah2, ah3);
            #pragma unroll
            for (int jp = 0; jp < 4; jp++) {
                u32 nrow = (u32)(64 * wn + 16 * jp + bRow);
                u32 kof  = (u32)(16 * t4 + bKh) * 2;
                u32 b0, b1, b2, b3;
                ldsm_x4(b2b + nrow * B2_ST + kof, b0, b1, b2, b3);
                mma_f16(acc2[2 * jp],     ah0, ah1, ah2, ah3, b0, b1);
                mma_f16(acc2[2 * jp + 1], ah0, ah1, ah2, ah3, b2, b3);
            }
        }
    }

    // ---- scatter: + mb2, red.v2 into g_agg[dst] ----
    const bool e0 = (base + m0 < E), e1 = (base + m1 < E);
    #pragma unroll
    for (int j = 0; j < 8; j++) {
        int n = 64 * wn + 8 * j + 2 * t;
        float2 bv = *(const float2*)(mb2 + n);
        if (e0) {
            float x0 = acc2[j][0] + bv.x, x1 = acc2[j][1] + bv.y;
            asm volatile("red.global.add.v2.f32 [%0], {%1, %2};"
                         :: "l"(g_agg + (size_t)vd0 * ND + n), "f"(x0), "f"(x1) : "memory");
        }
        if (e1) {
            float x0 = acc2[j][2] + bv.x, x1 = acc2[j][3] + bv.y;
            asm volatile("red.global.add.v2.f32 [%0], {%1, %2};"
                         :: "l"(g_agg + (size_t)vd1 * ND + n), "f"(x0), "f"(x1) : "memory");
        }
    }
}

// =================== K3: warp-MMA node update (proven) ==========================
#define U_A1_OFF 0
#define U_A2_OFF 67584
#define U_B1_OFF 86016
#define U_B2_OFF 153600
#define U_SMEM   190464
#define U_A1_ST  528
#define U_A2_ST  144
#define U_B1_ST  528
#define U_B2_ST  144
#define U_B1_BUF 33792
#define U_B2_BUF 18432

__global__ __launch_bounds__(512, 1) void k_update_mma(
    const float* __restrict__ x,
    const float* __restrict__ ub1, const float* __restrict__ ub2,
    float* __restrict__ out, int N)
{
    extern __shared__ __align__(16) char sm[];
    const u32 smu = smem_u32(sm);
    const int tid = threadIdx.x;
    const int w = tid >> 5, l = tid & 31;
    const int wm = w & 7, wn = w >> 3;
    const int g = l >> 2, t = l & 3;
    const int base = blockIdx.x * 128;
    const char* gB1 = (const char*)g_U1h;
    const char* gB2 = (const char*)g_U2h;

    #pragma unroll
    for (int r = 0; r < 4; r++) {
        int i = tid + 512 * r;
        int row = i >> 5, part = i & 31;
        CP_ASYNC16(smu + U_B1_OFF + row * U_B1_ST + part * 16,
                   gB1 + row * 512 + part * 16);
    }
    #pragma unroll
    for (int r = 0; r < 2; r++) {
        int i = tid + 512 * r;
        int row = i >> 3, part = i & 7;
        CP_ASYNC16(smu + U_B2_OFF + row * U_B2_ST + part * 16,
                   gB2 + row * 512 + part * 16);
    }
    CP_COMMIT();

    {
        int row = tid >> 2, q = tid & 3;
        int node = base + row;
        char* arow = sm + U_A1_OFF + row * U_A1_ST + q * 128;
        if (node < N) {
            const float4* srcp = (q < 2)
                ? (const float4*)(x + (size_t)node * ND + 64 * q)
                : (const float4*)(g_agg + (size_t)node * ND + 64 * (q - 2));
            #pragma unroll
            for (int i = 0; i < 16; i++) {
                float4 v = srcp[i];
                *(u32*)(arow + i * 8)     = h2pack(v.x, v.y);
                *(u32*)(arow + i * 8 + 4) = h2pack(v.z, v.w);
            }
        } else {
            #pragma unroll
            for (int i = 0; i < 32; i++) *(u32*)(arow + i * 4) = 0u;
        }
    }
    __syncthreads();

    const int lr   = l & 7;
    const int aRow = 16 * wm + lr + ((l >> 3) & 1) * 8;
    const int aKh  = (l >> 4) * 8;
    const int bRow = lr + (l >> 4) * 8;
    const int bKh  = ((l >> 3) & 1) * 8;
    const u32 a1base = smu + U_A1_OFF + aRow * U_A1_ST + aKh * 2;
    const u32 a2base = smu + U_A2_OFF + aRow * U_A2_ST + aKh * 2;

    const int m0 = 16 * wm + g, m1 = m0 + 8;
    char* a2r0 = sm + U_A2_OFF + m0 * U_A2_ST;
    char* a2r1 = sm + U_A2_OFF + m1 * U_A2_ST;

    float acc2[8][4];
    #pragma unroll
    for (int j = 0; j < 8; j++)
        #pragma unroll
        for (int q = 0; q < 4; q++) acc2[j][q] = 0.f;

    #pragma unroll 1
    for (int c = 0; c < 4; c++) {
        if (c > 0) __syncthreads();
        if (c < 3) {
            int buf = (c + 1) & 1;
            #pragma unroll
            for (int r = 0; r < 4; r++) {
                int i = tid + 512 * r;
                int row = i >> 5, part = i & 31;
                CP_ASYNC16(smu + U_B1_OFF + buf * U_B1_BUF + row * U_B1_ST + part * 16,
                           gB1 + (size_t)(64 * (c + 1) + row) * 512 + part * 16);
            }
            #pragma unroll
            for (int r = 0; r < 2; r++) {
                int i = tid + 512 * r;
                int row = i >> 3, part = i & 7;
                CP_ASYNC16(smu + U_B2_OFF + buf * U_B2_BUF + row * U_B2_ST + part * 16,
                           gB2 + row * 512 + 128 * (c + 1) + part * 16);
            }
            CP_COMMIT();
        }
        if (c < 3) { CP_WAIT(1); } else { CP_WAIT(0); }
        __syncthreads();

        float acc1[4][4];
        #pragma unroll
        for (int j = 0; j < 4; j++)
            #pragma unroll
            for (int q = 0; q < 4; q++) acc1[j][q] = 0.f;

        const u32 b1b = smu + U_B1_OFF + (c & 1) * U_B1_BUF;
        #pragma unroll 2
        for (int kt = 0; kt < 16; kt++) {
            u32 fa0, fa1, fa2, fa3;
            ldsm_x4(a1base + kt * 32, fa0, fa1, fa2, fa3);
            #pragma unroll
            for (int jp = 0; jp < 2; jp++) {
                u32 nrow = (u32)(32 * wn + 16 * jp + bRow);
                u32 b0, b1, b2, b3;
                ldsm_x4(b1b + nrow * U_B1_ST + (u32)(16 * kt + bKh) * 2, b0, b1, b2, b3);
                mma_f16(acc1[2 * jp],     fa0, fa1, fa2, fa3, b0, b1);
                mma_f16(acc1[2 * jp + 1], fa0, fa1, fa2, fa3, b2, b3);
            }
        }

        #pragma unroll
        for (int nt = 0; nt < 4; nt++) {
            int col = 64 * c + 32 * wn + 8 * nt + 2 * t;
            int lc  = 32 * wn + 8 * nt + 2 * t;
            float2 bv = *(const float2*)(ub1 + col);
            float v00 = fmaxf(acc1[nt][0] + bv.x, 0.f);
            float v01 = fmaxf(acc1[nt][1] + bv.y, 0.f);
            float v10 = fmaxf(acc1[nt][2] + bv.x, 0.f);
            float v11 = fmaxf(acc1[nt][3] + bv.y, 0.f);
            *(u32*)(a2r0 + lc * 2) = h2pack(v00, v01);
            *(u32*)(a2r1 + lc * 2) = h2pack(v10, v11);
        }
        __syncthreads();

        const u32 b2b = smu + U_B2_OFF + (c & 1) * U_B2_BUF;
        #pragma unroll
        for (int t4 = 0; t4 < 4; t4++) {
            u32 ah0, ah1, ah2, ah3;
            ldsm_x4(a2base + t4 * 32, ah0, ah1, ah2, ah3);
            #pragma unroll
            for (int jp = 0; jp < 4; jp++) {
                u32 nrow = (u32)(64 * wn + 16 * jp + bRow);
                u32 kof  = (u32)(16 * t4 + bKh) * 2;
                u32 b0, b1, b2, b3;
                ldsm_x4(b2b + nrow * U_B2_ST + kof, b0, b1, b2, b3);
                mma_f16(acc2[2 * jp],     ah0, ah1, ah2, ah3, b0, b1);
                mma_f16(acc2[2 * jp + 1], ah0, ah1, ah2, ah3, b2, b3);
            }
        }
    }

    const bool n0 = (base + m0 < N), n1 = (base + m1 < N);
    #pragma unroll
    for (int j = 0; j < 8; j++) {
        int n = 64 * wn + 8 * j + 2 * t;
        float2 bv = *(const float2*)(ub2 + n);
        if (n0) {
            float2 r = make_float2(acc2[j][0] + bv.x, acc2[j][1] + bv.y);
            *(float2*)&out[(size_t)(base + m0) * ND + n] = r;
        }
        if (n1) {
            float2 r = make_float2(acc2[j][2] + bv.x, acc2[j][3] + bv.y);
            *(float2*)&out[(size_t)(base + m1) * ND + n] = r;
        }
    }
}

// =================== launcher ===================================================
extern "C" void kernel_launch(void* const* d_in, const int* in_sizes, int n_in,
                              void* d_out, int out_size)
{
    const float* x    = (const float*)d_in[0];
    const int*   ei   = (const int*)  d_in[1];
    const float* ea   = (const float*)d_in[2];
    const float* cong = (const float*)d_in[3];
    const float* mW1  = (const float*)d_in[4];
    const float* mb1  = (const float*)d_in[5];
    const float* mW2  = (const float*)d_in[6];
    const float* mb2  = (const float*)d_in[7];
    const float* uW1  = (const float*)d_in[8];
    const float* ub1  = (const float*)d_in[9];
    const float* uW2  = (const float*)d_in[10];
    const float* ub2  = (const float*)d_in[11];

    int N = in_sizes[0] / ND;
    int E = in_sizes[1] / 2;
    if (N > N_MAX) N = N_MAX;
    if (E > E_MAX) E = E_MAX;

    cudaFuncSetAttribute(k_pre_mma,    cudaFuncAttributeMaxDynamicSharedMemorySize, P_SMEM);
    cudaFuncSetAttribute(k_edge_mma,   cudaFuncAttributeMaxDynamicSharedMemorySize, EDGE_SMEM);
    cudaFuncSetAttribute(k_update_mma, cudaFuncAttributeMaxDynamicSharedMemorySize, U_SMEM);

    k_convert    <<<(E + 255) / 256, 256>>>(ei, E);
    k_prep       <<<160, 256>>>(mW1, mW2, uW1, uW2);
    k_pre_mma    <<<(N + 127) / 128, 512, P_SMEM>>>(x, cong, mW1, mb1, N);
    k_edge_mma   <<<(E + 63) / 64, 256, EDGE_SMEM>>>(ea, mb2, E);
    k_update_mma <<<(N + 127) / 128, 512, U_SMEM>>>(x, ub1, ub2, (float*)d_out, N);
}

// round 14
// speedup vs baseline: 3.0705x; 1.1068x over previous
#include <cuda_runtime.h>
#include <cuda_fp16.h>
#include <cstdint>

#define ND 128
#define ED 32
#define HD 256
#define N_MAX 100000
#define E_MAX 1600000

typedef unsigned long long u64;
typedef unsigned int u32;

// ---------------- warp-MMA helpers (family-compatible: sm_80+) ----------------
__device__ __forceinline__ u32 smem_u32(const void* p) {
    u32 a;
    asm("{ .reg .u64 t; cvta.to.shared.u64 t, %1; cvt.u32.u64 %0, t; }" : "=r"(a) : "l"(p));
    return a;
}
__device__ __forceinline__ void ldsm_x4(u32 addr, u32& r0, u32& r1, u32& r2, u32& r3) {
    asm volatile("ldmatrix.sync.aligned.m8n8.x4.shared.b16 {%0,%1,%2,%3}, [%4];"
        : "=r"(r0), "=r"(r1), "=r"(r2), "=r"(r3) : "r"(addr));
}
__device__ __forceinline__ void mma_f16(float* d, u32 a0, u32 a1, u32 a2, u32 a3,
                                        u32 b0, u32 b1) {
    asm volatile("mma.sync.aligned.m16n8k16.row.col.f32.f16.f16.f32 "
        "{%0,%1,%2,%3}, {%4,%5,%6,%7}, {%8,%9}, {%0,%1,%2,%3};"
        : "+f"(d[0]), "+f"(d[1]), "+f"(d[2]), "+f"(d[3])
        : "r"(a0), "r"(a1), "r"(a2), "r"(a3), "r"(b0), "r"(b1));
}
__device__ __forceinline__ u32 h2pack(float a, float b) {
    __half2 h = __floats2half2_rn(a, b);
    return *(u32*)&h;
}
__device__ __forceinline__ float2 h2unpack(u32 p) {
    return __half22float2(*(__half2*)&p);
}
#define CP_ASYNC16(d, s) asm volatile("cp.async.cg.shared.global [%0], [%1], 16;" :: "r"(d), "l"(s) : "memory")
#define CP_COMMIT()      asm volatile("cp.async.commit_group;" ::: "memory")
#define CP_WAIT(n)       asm volatile("cp.async.wait_group %0;" :: "n"(n) : "memory")

// ---------------- scratch ----------------
__device__ int   g_src[E_MAX];
__device__ int   g_dst[E_MAX];
// fp16 node partials: 2 x 100k x 256 x 2B = 102 MB total -> fits in 126 MB L2
__device__ __align__(16) __half g_Psrc[(size_t)N_MAX * HD];
__device__ __align__(16) __half g_Pdst[(size_t)N_MAX * HD];
__device__ float g_agg [(size_t)N_MAX * ND];
// fp16 weight images (row-major, [n][k])
__device__ __align__(16) __half g_B1h[256 * 32];    // W1c^T  [n=256][k=32]
__device__ __align__(16) __half g_B2h[128 * 256];   // W2^T   [n=128][k=256]
__device__ __align__(16) __half g_U1h[256 * 256];   // uW1^T  [n=256][k=256]
__device__ __align__(16) __half g_U2h[128 * 256];   // uW2^T  [n=128][k=256]
__device__ __align__(16) __half g_P1h[512 * 128];   // [W1a|W1b]^T

// =================== K0: edge_index convert (int64 OR int32) ===================
__global__ void k_convert(const int* __restrict__ w, int E)
{
    __shared__ int s64;
    if (threadIdx.x == 0) {
        int b = 1;
        #pragma unroll
        for (int i = 0; i < 8; i++) if (w[2 * i + 1] != 0) b = 0;
        s64 = b;
    }
    __syncthreads();
    int i = blockIdx.x * blockDim.x + threadIdx.x;
    if (i >= E) return;
    if (s64) {
        const long long* e = (const long long*)w;
        g_src[i] = (int)e[i];
        g_dst[i] = (int)e[(size_t)E + i];
    } else {
        g_src[i] = w[i];
        g_dst[i] = w[(size_t)E + i];
    }
}

// =================== K_prep: build fp16 weight images ===========================
__global__ void k_prep(const float* __restrict__ mW1, const float* __restrict__ mW2,
                       const float* __restrict__ uW1, const float* __restrict__ uW2)
{
    int tid = blockIdx.x * blockDim.x + threadIdx.x;
    const int S1 = 256 * 32, S2 = S1 + 128 * 256, S3 = S2 + 256 * 256,
              S4 = S3 + 128 * 256;
    int total = S4 + 512 * 128;
    for (int i = tid; i < total; i += gridDim.x * blockDim.x) {
        if (i < S1) {
            int n = i >> 5, k = i & 31;
            g_B1h[n * 32 + k] = __float2half(mW1[(size_t)(2 * ND + k) * HD + n]);
        } else if (i < S2) {
            int q = i - S1;
            int n = q >> 8, j = q & 255;
            g_B2h[n * 256 + j] = __float2half(mW2[(size_t)j * ND + n]);
        } else if (i < S3) {
            int q = i - S2;
            int n = q >> 8, k = q & 255;
            g_U1h[n * 256 + k] = __float2half(uW1[(size_t)k * HD + n]);
        } else if (i < S4) {
            int q = i - S3;
            int n = q >> 8, k = q & 255;
            g_U2h[n * 256 + k] = __float2half(uW2[(size_t)k * ND + n]);
        } else {
            int q = i - S4;
            int n = q >> 7, k = q & 127;
            float v = (n < 256) ? mW1[(size_t)k * HD + n]
                                : mW1[(size_t)(128 + k) * HD + (n - 256)];
            g_P1h[n * 128 + k] = __float2half(v);
        }
    }
}

// =================== K1: warp-MMA node precompute (proven) ======================
#define P_A1_OFF   0
#define P_CONG_OFF 34816
#define P_B_OFF    35328
#define P_SMEM     104960
#define P_A1_ST    272
#define P_B_ST     272
#define P_B_BUF    34816

__global__ __launch_bounds__(512, 1) void k_pre_mma(
    const float* __restrict__ x, const float* __restrict__ cong,
    const float* __restrict__ mW1, const float* __restrict__ mb1, int N)
{
    extern __shared__ __align__(16) char sm[];
    const u32 smu = smem_u32(sm);
    const int tid = threadIdx.x;
    const int w = tid >> 5, l = tid & 31;
    const int wm = w & 7, wn = w >> 3;
    const int g = l >> 2, t = l & 3;
    const int base = blockIdx.x * 128;
    const char* gB = (const char*)g_P1h;

    #pragma unroll
    for (int r = 0; r < 4; r++) {
        int i = tid + 512 * r;
        int row = i >> 4, part = i & 15;
        CP_ASYNC16(smu + P_B_OFF + row * P_B_ST + part * 16,
                   gB + row * 256 + part * 16);
    }
    CP_COMMIT();

    {
        int row = tid >> 2, q = tid & 3;
        int node = base + row;
        char* arow = sm + P_A1_OFF + row * P_A1_ST + q * 64;
        if (node < N) {
            const float4* srcp = (const float4*)(x + (size_t)node * ND + 32 * q);
            #pragma unroll
            for (int i = 0; i < 8; i++) {
                float4 v = srcp[i];
                *(u32*)(arow + i * 8)     = h2pack(v.x, v.y);
                *(u32*)(arow + i * 8 + 4) = h2pack(v.z, v.w);
            }
        } else {
            #pragma unroll
            for (int i = 0; i < 16; i++) *(u32*)(arow + i * 4) = 0u;
        }
    }
    if (tid < 128) {
        int node = base + tid;
        ((float*)(sm + P_CONG_OFF))[tid] = (node < N) ? cong[node] : 0.f;
    }
    __syncthreads();

    const int lr   = l & 7;
    const int aRow = 16 * wm + lr + ((l >> 3) & 1) * 8;
    const int aKh  = (l >> 4) * 8;
    const int bRow = lr + (l >> 4) * 8;
    const int bKh  = ((l >> 3) & 1) * 8;
    const u32 a1base = smu + P_A1_OFF + aRow * P_A1_ST + aKh * 2;

    const int m0 = 16 * wm + g, m1 = m0 + 8;
    const float cg0 = ((const float*)(sm + P_CONG_OFF))[m0];
    const float cg1 = ((const float*)(sm + P_CONG_OFF))[m1];
    const bool n0 = (base + m0 < N), n1 = (base + m1 < N);

    #pragma unroll 1
    for (int c = 0; c < 4; c++) {
        if (c > 0) __syncthreads();
        if (c < 3) {
            int buf = (c + 1) & 1;
            #pragma unroll
            for (int r = 0; r < 4; r++) {
                int i = tid + 512 * r;
                int row = i >> 4, part = i & 15;
                CP_ASYNC16(smu + P_B_OFF + buf * P_B_BUF + row * P_B_ST + part * 16,
                           gB + (size_t)(128 * (c + 1) + row) * 256 + part * 16);
            }
            CP_COMMIT();
        }
        if (c < 3) { CP_WAIT(1); } else { CP_WAIT(0); }
        __syncthreads();

        float acc[8][4];
        #pragma unroll
        for (int j = 0; j < 8; j++)
            #pragma unroll
            for (int q = 0; q < 4; q++) acc[j][q] = 0.f;

        const u32 bb = smu + P_B_OFF + (c & 1) * P_B_BUF;
        #pragma unroll 2
        for (int kt = 0; kt < 8; kt++) {
            u32 fa0, fa1, fa2, fa3;
            ldsm_x4(a1base + kt * 32, fa0, fa1, fa2, fa3);
            #pragma unroll
            for (int jp = 0; jp < 4; jp++) {
                u32 nrow = (u32)(64 * wn + 16 * jp + bRow);
                u32 b0, b1, b2, b3;
                ldsm_x4(bb + nrow * P_B_ST + (u32)(16 * kt + bKh) * 2, b0, b1, b2, b3);
                mma_f16(acc[2 * jp],     fa0, fa1, fa2, fa3, b0, b1);
                mma_f16(acc[2 * jp + 1], fa0, fa1, fa2, fa3, b2, b3);
            }
        }

        #pragma unroll
        for (int nt = 0; nt < 8; nt++) {
            int gcol = 128 * c + 64 * wn + 8 * nt + 2 * t;
            if (c < 2) {
                int col = gcol;
                float2 w2 = *(const float2*)&mW1[(size_t)288 * HD + col];
                if (n0) {
                    float v0 = acc[nt][0] + cg0 * w2.x;
                    float v1 = acc[nt][1] + cg0 * w2.y;
                    *(u32*)&g_Psrc[(size_t)(base + m0) * HD + col] = h2pack(v0, v1);
                }
                if (n1) {
                    float v0 = acc[nt][2] + cg1 * w2.x;
                    float v1 = acc[nt][3] + cg1 * w2.y;
                    *(u32*)&g_Psrc[(size_t)(base + m1) * HD + col] = h2pack(v0, v1);
                }
            } else {
                int col = gcol - 256;
                float2 bv = *(const float2*)&mb1[col];
                if (n0) {
                    float v0 = acc[nt][0] + bv.x;
                    float v1 = acc[nt][1] + bv.y;
                    *(u32*)&g_Pdst[(size_t)(base + m0) * HD + col] = h2pack(v0, v1);
                }
                if (n1) {
                    float v0 = acc[nt][2] + bv.x;
                    float v1 = acc[nt][3] + bv.y;
                    *(u32*)&g_Pdst[(size_t)(base + m1) * HD + col] = h2pack(v0, v1);
                }
            }
        }
    }

    const float4 z4 = make_float4(0.f, 0.f, 0.f, 0.f);
    for (int idx = tid; idx < 128 * 32; idx += 512) {
        int node = base + (idx >> 5);
        if (node < N)
            ((float4*)g_agg)[(size_t)node * 32 + (idx & 31)] = z4;
    }
}

// =================== K2: warp-MMA edge kernel (v9: persistent, resident weights) ====
// Persistent CTAs (2/SM, 256 thr) loop over 64-edge tiles. B1/B2 staged ONCE per
// CTA into swizzled unpadded smem (XOR swizzle keeps ldsm conflict-free):
//   B1: row*64  + (kb ^ (((row>>1)&3)<<4))   [256 rows x 64B]   16384
//   B2: row*512 + (kb ^ ((row&7)<<4))        [128 rows x 512B]  65536
// PS gathers single-buffered cp.async, prefetch(c+1) after epilogue(c).
// smem map (bytes):
//   B1  @ 0       16384
//   B2  @ 16384   65536
//   A2c @ 81920   [64 rows][64 halves] stride 144 = 9216 (A1 [64][80B] aliases)
//   PS  @ 91136   { Psrc[64][72h] st144 | Pdst +9216 } = 18432
//   src @ 109568  int[64];  dst @ 109824 int[64]
#define B1_OFF  0
#define B2R_OFF 16384
#define A2_OFF  81920
#define PS_OFF  91136
#define SRC_OFF 109568
#define DST_OFF 109824
#define EDGE_SMEM 110080
#define A1_ST 80
#define A2_ST 144
#define PS_ST 144

__global__ __launch_bounds__(256, 2) void k_edge_mma(
    const float* __restrict__ edge_attr, const float* __restrict__ mb2, int E)
{
    extern __shared__ __align__(16) char sm[];
    const u32 smu = smem_u32(sm);
    const int tid = threadIdx.x;
    const int w = tid >> 5, l = tid & 31;
    const int wm = w & 3, wn = w >> 2;
    const int g = l >> 2, t = l & 3;

    // ---- stage B1 + B2 ONCE (swizzled, unpadded) ----
    for (int i = tid; i < 1024; i += 256) {        // B1: 256 rows x 4 parts
        int row = i >> 2, part = i & 3;
        u32 kb = (u32)part * 16;
        *(float4*)(sm + B1_OFF + row * 64 + (kb ^ ((((u32)row >> 1) & 3) << 4))) =
            *(const float4*)((const char*)g_B1h + row * 64 + kb);
    }
    for (int i = tid; i < 4096; i += 256) {        // B2: 128 rows x 32 parts
        int row = i >> 5, part = i & 31;
        u32 kb = (u32)part * 16;
        *(float4*)(sm + B2R_OFF + row * 512 + (kb ^ (((u32)row & 7) << 4))) =
            *(const float4*)((const char*)g_B2h + row * 512 + kb);
    }

    // per-lane ldmatrix address components
    const int lr   = l & 7;
    const int aRow = 16 * wm + lr + ((l >> 3) & 1) * 8;
    const int aKh  = (l >> 4) * 8;
    const int bRow = lr + (l >> 4) * 8;
    const int bKh  = ((l >> 3) & 1) * 8;
    const u32 a1base = smu + A2_OFF + aRow * A1_ST + aKh * 2;  // A1 alias
    const u32 a2base = smu + A2_OFF + aRow * A2_ST + aKh * 2;
    const int m0 = 16 * wm + g, m1 = m0 + 8;

    const int tiles = (E + 63) >> 6;
    #pragma unroll 1
    for (int tile = blockIdx.x; tile < tiles; tile += gridDim.x) {
        const int base = tile * 64;

        __syncthreads();   // previous tile's layer2/A2 reads done; weights visible (1st tile)

        // ---- stage src/dst ----
        if (tid < 64) {
            int e = base + tid;
            ((int*)(sm + SRC_OFF))[tid] = (e < E) ? g_src[e] : 0;
            ((int*)(sm + DST_OFF))[tid] = (e < E) ? g_dst[e] : 0;
        }
        // ---- stage A1: edge_attr -> fp16 (aliases A2c region) ----
        if (tid < 128) {
            int e = tid >> 1, h = tid & 1;
            char* arow = sm + A2_OFF + e * A1_ST;
            if (base + e < E) {
                const float4* src4 = (const float4*)(edge_attr + (size_t)(base + e) * ED + 16 * h);
                #pragma unroll
                for (int q = 0; q < 4; q++) {
                    float4 v = src4[q];
                    int k = 16 * h + 4 * q;
                    *(u32*)(arow + k * 2)       = h2pack(v.x, v.y);
                    *(u32*)(arow + (k + 2) * 2) = h2pack(v.z, v.w);
                }
            } else {
                #pragma unroll
                for (int q = 0; q < 8; q++)
                    *(u32*)(arow + (16 * h + 2 * q) * 2) = 0u;
            }
        }
        __syncthreads();   // src/dst + A1 visible

        // ---- PS chunk 0 prefetch (row-contiguous gathers) ----
        #pragma unroll
        for (int r = 0; r < 2; r++) {
            int idx = tid + 256 * r;
            int row = idx >> 3, part = idx & 7;
            int vs = ((const int*)(sm + SRC_OFF))[row];
            int vd = ((const int*)(sm + DST_OFF))[row];
            CP_ASYNC16(smu + PS_OFF + row * PS_ST + part * 16,
                       (const char*)g_Psrc + ((size_t)vs * HD) * 2 + part * 16);
            CP_ASYNC16(smu + PS_OFF + 9216 + row * PS_ST + part * 16,
                       (const char*)g_Pdst + ((size_t)vd * HD) * 2 + part * 16);
        }
        CP_COMMIT();

        // A1 fragments for this tile
        u32 fa[2][4];
        #pragma unroll
        for (int kt = 0; kt < 2; kt++)
            ldsm_x4(a1base + kt * 32, fa[kt][0], fa[kt][1], fa[kt][2], fa[kt][3]);

        const int vd0 = ((const int*)(sm + DST_OFF))[m0];
        const int vd1 = ((const int*)(sm + DST_OFF))[m1];
        char* a2r0 = sm + A2_OFF + m0 * A2_ST;
        char* a2r1 = sm + A2_OFF + m1 * A2_ST;

        float acc2[8][4];
        #pragma unroll
        for (int j = 0; j < 8; j++)
            #pragma unroll
            for (int q = 0; q < 4; q++) acc2[j][q] = 0.f;

        // ================= fused chunk loop =================
        #pragma unroll 1
        for (int c = 0; c < 4; c++) {
            // ---- layer 1: acc1 = EA @ W1c[:, warp's 32 cols of chunk c] ----
            float acc1[4][4];
            #pragma unroll
            for (int j = 0; j < 4; j++)
                #pragma unroll
                for (int q = 0; q < 4; q++) acc1[j][q] = 0.f;

            #pragma unroll
            for (int jp = 0; jp < 2; jp++) {
                u32 nrow = (u32)(64 * c + 32 * wn + 16 * jp + bRow);
                u32 sw = ((nrow >> 1) & 3) << 4;
                u32 rb = smu + B1_OFF + nrow * 64;
                u32 b0, b1, b2, b3;
                ldsm_x4(rb + (((u32)(2 * bKh)) ^ sw), b0, b1, b2, b3);        // k0-15
                mma_f16(acc1[2 * jp],     fa[0][0], fa[0][1], fa[0][2], fa[0][3], b0, b1);
                mma_f16(acc1[2 * jp + 1], fa[0][0], fa[0][1], fa[0][2], fa[0][3], b2, b3);
                ldsm_x4(rb + (((u32)(32 + 2 * bKh)) ^ sw), b0, b1, b2, b3);   // k16-31
                mma_f16(acc1[2 * jp],     fa[1][0], fa[1][1], fa[1][2], fa[1][3], b0, b1);
                mma_f16(acc1[2 * jp + 1], fa[1][0], fa[1][1], fa[1][2], fa[1][3], b2, b3);
            }

            // PS(c) arrived + all warps past layer2(c-1) (A2 reusable)
            CP_WAIT(0);
            __syncthreads();

            // ---- epilogue: staged partials (LDS), relu, fp16 into A2c ----
            const char* psb = sm + PS_OFF;
            #pragma unroll
            for (int nt = 0; nt < 4; nt++) {
                int lc = 32 * wn + 8 * nt + 2 * t;
                u32 ps0 = *(const u32*)(psb + m0 * PS_ST + lc * 2);
                u32 pd0 = *(const u32*)(psb + 9216 + m0 * PS_ST + lc * 2);
                u32 ps1 = *(const u32*)(psb + m1 * PS_ST + lc * 2);
                u32 pd1 = *(const u32*)(psb + 9216 + m1 * PS_ST + lc * 2);
                float2 a0 = h2unpack(ps0), b0 = h2unpack(pd0);
                float2 a1 = h2unpack(ps1), b1 = h2unpack(pd1);
                float v00 = fmaxf(acc1[nt][0] + a0.x + b0.x, 0.f);
                float v01 = fmaxf(acc1[nt][1] + a0.y + b0.y, 0.f);
                float v10 = fmaxf(acc1[nt][2] + a1.x + b1.x, 0.f);
                float v11 = fmaxf(acc1[nt][3] + a1.y + b1.y, 0.f);
                *(u32*)(a2r0 + lc * 2) = h2pack(v00, v01);
                *(u32*)(a2r1 + lc * 2) = h2pack(v10, v11);
            }
            __syncthreads();   // A2 ready; PS consumed

            // ---- PS(c+1) prefetch (single buffer, now free) ----
            if (c < 3) {
                #pragma unroll
                for (int r = 0; r < 2; r++) {
                    int idx = tid + 256 * r;
                    int row = idx >> 3, part = idx & 7;
                    int vs = ((const int*)(sm + SRC_OFF))[row];
                    int vd = ((const int*)(sm + DST_OFF))[row];
                    CP_ASYNC16(smu + PS_OFF + row * PS_ST + part * 16,
                               (const char*)g_Psrc + ((size_t)vs * HD + 64 * (c + 1)) * 2 + part * 16);
                    CP_ASYNC16(smu + PS_OFF + 9216 + row * PS_ST + part * 16,
                               (const char*)g_Pdst + ((size_t)vd * HD + 64 * (c + 1)) * 2 + part * 16);
                }
                CP_COMMIT();
            }

            // ---- layer 2: acc2 += h_chunk @ W2_chunk (B2 resident) ----
            #pragma unroll
            for (int t4 = 0; t4 < 4; t4++) {
                u32 ah0, ah1, ah2, ah3;
                ldsm_x4(a2base + t4 * 32, ah0, ah1, ah2, ah3);
                #pragma unroll
                for (int jp = 0; jp < 4; jp++) {
                    u32 nrow = (u32)(64 * wn + 16 * jp + bRow);
                    u32 kof  = (u32)((16 * t4 + bKh) * 2);
                    u32 addr = smu + B2R_OFF + nrow * 512 + 128u * (u32)c
                             + (kof ^ ((nrow & 7) << 4));
                    u32 b0, b1, b2, b3;
                    ldsm_x4(addr, b0, b1, b2, b3);
                    mma_f16(acc2[2 * jp],     ah0, ah1, ah2, ah3, b0, b1);
                    mma_f16(acc2[2 * jp + 1], ah0, ah1, ah2, ah3, b2, b3);
                }
            }
        }

        // ---- scatter: + mb2, red.v2 into g_agg[dst] ----
        const bool e0 = (base + m0 < E), e1 = (base + m1 < E);
        #pragma unroll
        for (int j = 0; j < 8; j++) {
            int n = 64 * wn + 8 * j + 2 * t;
            float2 bv = *(const float2*)(mb2 + n);
            if (e0) {
                float x0 = acc2[j][0] + bv.x, x1 = acc2[j][1] + bv.y;
                asm volatile("red.global.add.v2.f32 [%0], {%1, %2};"
                             :: "l"(g_agg + (size_t)vd0 * ND + n), "f"(x0), "f"(x1) : "memory");
            }
            if (e1) {
                float x0 = acc2[j][2] + bv.x, x1 = acc2[j][3] + bv.y;
                asm volatile("red.global.add.v2.f32 [%0], {%1, %2};"
                             :: "l"(g_agg + (size_t)vd1 * ND + n), "f"(x0), "f"(x1) : "memory");
            }
        }
    }
}

// =================== K3: warp-MMA node update (proven) ==========================
#define U_A1_OFF 0
#define U_A2_OFF 67584
#define U_B1_OFF 86016
#define U_B2_OFF 153600
#define U_SMEM   190464
#define U_A1_ST  528
#define U_A2_ST  144
#define U_B1_ST  528
#define U_B2_ST  144
#define U_B1_BUF 33792
#define U_B2_BUF 18432

__global__ __launch_bounds__(512, 1) void k_update_mma(
    const float* __restrict__ x,
    const float* __restrict__ ub1, const float* __restrict__ ub2,
    float* __restrict__ out, int N)
{
    extern __shared__ __align__(16) char sm[];
    const u32 smu = smem_u32(sm);
    const int tid = threadIdx.x;
    const int w = tid >> 5, l = tid & 31;
    const int wm = w & 7, wn = w >> 3;
    const int g = l >> 2, t = l & 3;
    const int base = blockIdx.x * 128;
    const char* gB1 = (const char*)g_U1h;
    const char* gB2 = (const char*)g_U2h;

    #pragma unroll
    for (int r = 0; r < 4; r++) {
        int i = tid + 512 * r;
        int row = i >> 5, part = i & 31;
        CP_ASYNC16(smu + U_B1_OFF + row * U_B1_ST + part * 16,
                   gB1 + row * 512 + part * 16);
    }
    #pragma unroll
    for (int r = 0; r < 2; r++) {
        int i = tid + 512 * r;
        int row = i >> 3, part = i & 7;
        CP_ASYNC16(smu + U_B2_OFF + row * U_B2_ST + part * 16,
                   gB2 + row * 512 + part * 16);
    }
    CP_COMMIT();

    {
        int row = tid >> 2, q = tid & 3;
        int node = base + row;
        char* arow = sm + U_A1_OFF + row * U_A1_ST + q * 128;
        if (node < N) {
            const float4* srcp = (q < 2)
                ? (const float4*)(x + (size_t)node * ND + 64 * q)
                : (const float4*)(g_agg + (size_t)node * ND + 64 * (q - 2));
            #pragma unroll
            for (int i = 0; i < 16; i++) {
                float4 v = srcp[i];
                *(u32*)(arow + i * 8)     = h2pack(v.x, v.y);
                *(u32*)(arow + i * 8 + 4) = h2pack(v.z, v.w);
            }
        } else {
            #pragma unroll
            for (int i = 0; i < 32; i++) *(u32*)(arow + i * 4) = 0u;
        }
    }
    __syncthreads();

    const int lr   = l & 7;
    const int aRow = 16 * wm + lr + ((l >> 3) & 1) * 8;
    const int aKh  = (l >> 4) * 8;
    const int bRow = lr + (l >> 4) * 8;
    const int bKh  = ((l >> 3) & 1) * 8;
    const u32 a1base = smu + U_A1_OFF + aRow * U_A1_ST + aKh * 2;
    const u32 a2base = smu + U_A2_OFF + aRow * U_A2_ST + aKh * 2;

    const int m0 = 16 * wm + g, m1 = m0 + 8;
    char* a2r0 = sm + U_A2_OFF + m0 * U_A2_ST;
    char* a2r1 = sm + U_A2_OFF + m1 * U_A2_ST;

    float acc2[8][4];
    #pragma unroll
    for (int j = 0; j < 8; j++)
        #pragma unroll
        for (int q = 0; q < 4; q++) acc2[j][q] = 0.f;

    #pragma unroll 1
    for (int c = 0; c < 4; c++) {
        if (c > 0) __syncthreads();
        if (c < 3) {
            int buf = (c + 1) & 1;
            #pragma unroll
            for (int r = 0; r < 4; r++) {
                int i = tid + 512 * r;
                int row = i >> 5, part = i & 31;
                CP_ASYNC16(smu + U_B1_OFF + buf * U_B1_BUF + row * U_B1_ST + part * 16,
                           gB1 + (size_t)(64 * (c + 1) + row) * 512 + part * 16);
            }
            #pragma unroll
            for (int r = 0; r < 2; r++) {
                int i = tid + 512 * r;
                int row = i >> 3, part = i & 7;
                CP_ASYNC16(smu + U_B2_OFF + buf * U_B2_BUF + row * U_B2_ST + part * 16,
                           gB2 + row * 512 + 128 * (c + 1) + part * 16);
            }
            CP_COMMIT();
        }
        if (c < 3) { CP_WAIT(1); } else { CP_WAIT(0); }
        __syncthreads();

        float acc1[4][4];
        #pragma unroll
        for (int j = 0; j < 4; j++)
            #pragma unroll
            for (int q = 0; q < 4; q++) acc1[j][q] = 0.f;

        const u32 b1b = smu + U_B1_OFF + (c & 1) * U_B1_BUF;
        #pragma unroll 2
        for (int kt = 0; kt < 16; kt++) {
            u32 fa0, fa1, fa2, fa3;
            ldsm_x4(a1base + kt * 32, fa0, fa1, fa2, fa3);
            #pragma unroll
            for (int jp = 0; jp < 2; jp++) {
                u32 nrow = (u32)(32 * wn + 16 * jp + bRow);
                u32 b0, b1, b2, b3;
                ldsm_x4(b1b + nrow * U_B1_ST + (u32)(16 * kt + bKh) * 2, b0, b1, b2, b3);
                mma_f16(acc1[2 * jp],     fa0, fa1, fa2, fa3, b0, b1);
                mma_f16(acc1[2 * jp + 1], fa0, fa1, fa2, fa3, b2, b3);
            }
        }

        #pragma unroll
        for (int nt = 0; nt < 4; nt++) {
            int col = 64 * c + 32 * wn + 8 * nt + 2 * t;
            int lc  = 32 * wn + 8 * nt + 2 * t;
            float2 bv = *(const float2*)(ub1 + col);
            float v00 = fmaxf(acc1[nt][0] + bv.x, 0.f);
            float v01 = fmaxf(acc1[nt][1] + bv.y, 0.f);
            float v10 = fmaxf(acc1[nt][2] + bv.x, 0.f);
            float v11 = fmaxf(acc1[nt][3] + bv.y, 0.f);
            *(u32*)(a2r0 + lc * 2) = h2pack(v00, v01);
            *(u32*)(a2r1 + lc * 2) = h2pack(v10, v11);
        }
        __syncthreads();

        const u32 b2b = smu + U_B2_OFF + (c & 1) * U_B2_BUF;
        #pragma unroll
        for (int t4 = 0; t4 < 4; t4++) {
            u32 ah0, ah1, ah2, ah3;
            ldsm_x4(a2base + t4 * 32, ah0, ah1, ah2, ah3);
            #pragma unroll
            for (int jp = 0; jp < 4; jp++) {
                u32 nrow = (u32)(64 * wn + 16 * jp + bRow);
                u32 kof  = (u32)(16 * t4 + bKh) * 2;
                u32 b0, b1, b2, b3;
                ldsm_x4(b2b + nrow * U_B2_ST + kof, b0, b1, b2, b3);
                mma_f16(acc2[2 * jp],     ah0, ah1, ah2, ah3, b0, b1);
                mma_f16(acc2[2 * jp + 1], ah0, ah1, ah2, ah3, b2, b3);
            }
        }
    }

    const bool n0 = (base + m0 < N), n1 = (base + m1 < N);
    #pragma unroll
    for (int j = 0; j < 8; j++) {
        int n = 64 * wn + 8 * j + 2 * t;
        float2 bv = *(const float2*)(ub2 + n);
        if (n0) {
            float2 r = make_float2(acc2[j][0] + bv.x, acc2[j][1] + bv.y);
            *(float2*)&out[(size_t)(base + m0) * ND + n] = r;
        }
        if (n1) {
            float2 r = make_float2(acc2[j][2] + bv.x, acc2[j][3] + bv.y);
            *(float2*)&out[(size_t)(base + m1) * ND + n] = r;
        }
    }
}

// =================== launcher ===================================================
extern "C" void kernel_launch(void* const* d_in, const int* in_sizes, int n_in,
                              void* d_out, int out_size)
{
    const float* x    = (const float*)d_in[0];
    const int*   ei   = (const int*)  d_in[1];
    const float* ea   = (const float*)d_in[2];
    const float* cong = (const float*)d_in[3];
    const float* mW1  = (const float*)d_in[4];
    const float* mb1  = (const float*)d_in[5];
    const float* mW2  = (const float*)d_in[6];
    const float* mb2  = (const float*)d_in[7];
    const float* uW1  = (const float*)d_in[8];
    const float* ub1  = (const float*)d_in[9];
    const float* uW2  = (const float*)d_in[10];
    const float* ub2  = (const float*)d_in[11];

    int N = in_sizes[0] / ND;
    int E = in_sizes[1] / 2;
    if (N > N_MAX) N = N_MAX;
    if (E > E_MAX) E = E_MAX;

    cudaFuncSetAttribute(k_pre_mma,    cudaFuncAttributeMaxDynamicSharedMemorySize, P_SMEM);
    cudaFuncSetAttribute(k_edge_mma,   cudaFuncAttributeMaxDynamicSharedMemorySize, EDGE_SMEM);
    cudaFuncSetAttribute(k_update_mma, cudaFuncAttributeMaxDynamicSharedMemorySize, U_SMEM);

    int tiles = (E + 63) / 64;
    int egrid = 304;                    // 2 persistent CTAs per SM (152 SMs)
    if (egrid > tiles) egrid = tiles;

    k_convert    <<<(E + 255) / 256, 256>>>(ei, E);
    k_prep       <<<160, 256>>>(mW1, mW2, uW1, uW2);
    k_pre_mma    <<<(N + 127) / 128, 512, P_SMEM>>>(x, cong, mW1, mb1, N);
    k_edge_mma   <<<egrid, 256, EDGE_SMEM>>>(ea, mb2, E);
    k_update_mma <<<(N + 127) / 128, 512, U_SMEM>>>(x, ub1, ub2, (float*)d_out, N);
}

// round 15
// speedup vs baseline: 3.0750x; 1.0015x over previous
#include <cuda_runtime.h>
#include <cuda_fp16.h>
#include <cstdint>

#define ND 128
#define ED 32
#define HD 256
#define N_MAX 100000
#define E_MAX 1600000

typedef unsigned long long u64;
typedef unsigned int u32;

// ---------------- warp-MMA helpers (family-compatible: sm_80+) ----------------
__device__ __forceinline__ u32 smem_u32(const void* p) {
    u32 a;
    asm("{ .reg .u64 t; cvta.to.shared.u64 t, %1; cvt.u32.u64 %0, t; }" : "=r"(a) : "l"(p));
    return a;
}
__device__ __forceinline__ void ldsm_x4(u32 addr, u32& r0, u32& r1, u32& r2, u32& r3) {
    asm volatile("ldmatrix.sync.aligned.m8n8.x4.shared.b16 {%0,%1,%2,%3}, [%4];"
        : "=r"(r0), "=r"(r1), "=r"(r2), "=r"(r3) : "r"(addr));
}
__device__ __forceinline__ void mma_f16(float* d, u32 a0, u32 a1, u32 a2, u32 a3,
                                        u32 b0, u32 b1) {
    asm volatile("mma.sync.aligned.m16n8k16.row.col.f32.f16.f16.f32 "
        "{%0,%1,%2,%3}, {%4,%5,%6,%7}, {%8,%9}, {%0,%1,%2,%3};"
        : "+f"(d[0]), "+f"(d[1]), "+f"(d[2]), "+f"(d[3])
        : "r"(a0), "r"(a1), "r"(a2), "r"(a3), "r"(b0), "r"(b1));
}
__device__ __forceinline__ u32 h2pack(float a, float b) {
    __half2 h = __floats2half2_rn(a, b);
    return *(u32*)&h;
}
__device__ __forceinline__ float2 h2unpack(u32 p) {
    return __half22float2(*(__half2*)&p);
}
#define CP_ASYNC16(d, s) asm volatile("cp.async.cg.shared.global [%0], [%1], 16;" :: "r"(d), "l"(s) : "memory")
#define CP_COMMIT()      asm volatile("cp.async.commit_group;" ::: "memory")
#define CP_WAIT(n)       asm volatile("cp.async.wait_group %0;" :: "n"(n) : "memory")

// ---------------- scratch ----------------
__device__ int   g_src[E_MAX];
__device__ int   g_dst[E_MAX];
// fp16 node partials: 2 x 100k x 256 x 2B = 102 MB total -> fits in 126 MB L2
__device__ __align__(16) __half g_Psrc[(size_t)N_MAX * HD];
__device__ __align__(16) __half g_Pdst[(size_t)N_MAX * HD];
__device__ float g_agg [(size_t)N_MAX * ND];
// fp16 weight images (row-major, [n][k])
__device__ __align__(16) __half g_B1h[256 * 32];    // W1c^T  [n=256][k=32]
__device__ __align__(16) __half g_B2h[128 * 256];   // W2^T   [n=128][k=256]
__device__ __align__(16) __half g_U1h[256 * 256];   // uW1^T  [n=256][k=256]
__device__ __align__(16) __half g_U2h[128 * 256];   // uW2^T  [n=128][k=256]
__device__ __align__(16) __half g_P1h[512 * 128];   // [W1a|W1b]^T

// =================== K0: edge_index convert (int64 OR int32) ===================
__global__ void k_convert(const int* __restrict__ w, int E)
{
    __shared__ int s64;
    if (threadIdx.x == 0) {
        int b = 1;
        #pragma unroll
        for (int i = 0; i < 8; i++) if (w[2 * i + 1] != 0) b = 0;
        s64 = b;
    }
    __syncthreads();
    int i = blockIdx.x * blockDim.x + threadIdx.x;
    if (i >= E) return;
    if (s64) {
        const long long* e = (const long long*)w;
        g_src[i] = (int)e[i];
        g_dst[i] = (int)e[(size_t)E + i];
    } else {
        g_src[i] = w[i];
        g_dst[i] = w[(size_t)E + i];
    }
}

// =================== K_prep: build fp16 weight images ===========================
__global__ void k_prep(const float* __restrict__ mW1, const float* __restrict__ mW2,
                       const float* __restrict__ uW1, const float* __restrict__ uW2)
{
    int tid = blockIdx.x * blockDim.x + threadIdx.x;
    const int S1 = 256 * 32, S2 = S1 + 128 * 256, S3 = S2 + 256 * 256,
              S4 = S3 + 128 * 256;
    int total = S4 + 512 * 128;
    for (int i = tid; i < total; i += gridDim.x * blockDim.x) {
        if (i < S1) {
            int n = i >> 5, k = i & 31;
            g_B1h[n * 32 + k] = __float2half(mW1[(size_t)(2 * ND + k) * HD + n]);
        } else if (i < S2) {
            int q = i - S1;
            int n = q >> 8, j = q & 255;
            g_B2h[n * 256 + j] = __float2half(mW2[(size_t)j * ND + n]);
        } else if (i < S3) {
            int q = i - S2;
            int n = q >> 8, k = q & 255;
            g_U1h[n * 256 + k] = __float2half(uW1[(size_t)k * HD + n]);
        } else if (i < S4) {
            int q = i - S3;
            int n = q >> 8, k = q & 255;
            g_U2h[n * 256 + k] = __float2half(uW2[(size_t)k * ND + n]);
        } else {
            int q = i - S4;
            int n = q >> 7, k = q & 127;
            float v = (n < 256) ? mW1[(size_t)k * HD + n]
                                : mW1[(size_t)(128 + k) * HD + (n - 256)];
            g_P1h[n * 128 + k] = __float2half(v);
        }
    }
}

// =================== K1: warp-MMA node precompute (proven) ======================
#define P_A1_OFF   0
#define P_CONG_OFF 34816
#define P_B_OFF    35328
#define P_SMEM     104960
#define P_A1_ST    272
#define P_B_ST     272
#define P_B_BUF    34816

__global__ __launch_bounds__(512, 1) void k_pre_mma(
    const float* __restrict__ x, const float* __restrict__ cong,
    const float* __restrict__ mW1, const float* __restrict__ mb1, int N)
{
    extern __shared__ __align__(16) char sm[];
    const u32 smu = smem_u32(sm);
    const int tid = threadIdx.x;
    const int w = tid >> 5, l = tid & 31;
    const int wm = w & 7, wn = w >> 3;
    const int g = l >> 2, t = l & 3;
    const int base = blockIdx.x * 128;
    const char* gB = (const char*)g_P1h;

    #pragma unroll
    for (int r = 0; r < 4; r++) {
        int i = tid + 512 * r;
        int row = i >> 4, part = i & 15;
        CP_ASYNC16(smu + P_B_OFF + row * P_B_ST + part * 16,
                   gB + row * 256 + part * 16);
    }
    CP_COMMIT();

    {
        int row = tid >> 2, q = tid & 3;
        int node = base + row;
        char* arow = sm + P_A1_OFF + row * P_A1_ST + q * 64;
        if (node < N) {
            const float4* srcp = (const float4*)(x + (size_t)node * ND + 32 * q);
            #pragma unroll
            for (int i = 0; i < 8; i++) {
                float4 v = srcp[i];
                *(u32*)(arow + i * 8)     = h2pack(v.x, v.y);
                *(u32*)(arow + i * 8 + 4) = h2pack(v.z, v.w);
            }
        } else {
            #pragma unroll
            for (int i = 0; i < 16; i++) *(u32*)(arow + i * 4) = 0u;
        }
    }
    if (tid < 128) {
        int node = base + tid;
        ((float*)(sm + P_CONG_OFF))[tid] = (node < N) ? cong[node] : 0.f;
    }
    __syncthreads();

    const int lr   = l & 7;
    const int aRow = 16 * wm + lr + ((l >> 3) & 1) * 8;
    const int aKh  = (l >> 4) * 8;
    const int bRow = lr + (l >> 4) * 8;
    const int bKh  = ((l >> 3) & 1) * 8;
    const u32 a1base = smu + P_A1_OFF + aRow * P_A1_ST + aKh * 2;

    const int m0 = 16 * wm + g, m1 = m0 + 8;
    const float cg0 = ((const float*)(sm + P_CONG_OFF))[m0];
    const float cg1 = ((const float*)(sm + P_CONG_OFF))[m1];
    const bool n0 = (base + m0 < N), n1 = (base + m1 < N);

    #pragma unroll 1
    for (int c = 0; c < 4; c++) {
        if (c > 0) __syncthreads();
        if (c < 3) {
            int buf = (c + 1) & 1;
            #pragma unroll
            for (int r = 0; r < 4; r++) {
                int i = tid + 512 * r;
                int row = i >> 4, part = i & 15;
                CP_ASYNC16(smu + P_B_OFF + buf * P_B_BUF + row * P_B_ST + part * 16,
                           gB + (size_t)(128 * (c + 1) + row) * 256 + part * 16);
            }
            CP_COMMIT();
        }
        if (c < 3) { CP_WAIT(1); } else { CP_WAIT(0); }
        __syncthreads();

        float acc[8][4];
        #pragma unroll
        for (int j = 0; j < 8; j++)
            #pragma unroll
            for (int q = 0; q < 4; q++) acc[j][q] = 0.f;

        const u32 bb = smu + P_B_OFF + (c & 1) * P_B_BUF;
        #pragma unroll 2
        for (int kt = 0; kt < 8; kt++) {
            u32 fa0, fa1, fa2, fa3;
            ldsm_x4(a1base + kt * 32, fa0, fa1, fa2, fa3);
            #pragma unroll
            for (int jp = 0; jp < 4; jp++) {
                u32 nrow = (u32)(64 * wn + 16 * jp + bRow);
                u32 b0, b1, b2, b3;
                ldsm_x4(bb + nrow * P_B_ST + (u32)(16 * kt + bKh) * 2, b0, b1, b2, b3);
                mma_f16(acc[2 * jp],     fa0, fa1, fa2, fa3, b0, b1);
                mma_f16(acc[2 * jp + 1], fa0, fa1, fa2, fa3, b2, b3);
            }
        }

        #pragma unroll
        for (int nt = 0; nt < 8; nt++) {
            int gcol = 128 * c + 64 * wn + 8 * nt + 2 * t;
            if (c < 2) {
                int col = gcol;
                float2 w2 = *(const float2*)&mW1[(size_t)288 * HD + col];
                if (n0) {
                    float v0 = acc[nt][0] + cg0 * w2.x;
                    float v1 = acc[nt][1] + cg0 * w2.y;
                    *(u32*)&g_Psrc[(size_t)(base + m0) * HD + col] = h2pack(v0, v1);
                }
                if (n1) {
                    float v0 = acc[nt][2] + cg1 * w2.x;
                    float v1 = acc[nt][3] + cg1 * w2.y;
                    *(u32*)&g_Psrc[(size_t)(base + m1) * HD + col] = h2pack(v0, v1);
                }
            } else {
                int col = gcol - 256;
                float2 bv = *(const float2*)&mb1[col];
                if (n0) {
                    float v0 = acc[nt][0] + bv.x;
                    float v1 = acc[nt][1] + bv.y;
                    *(u32*)&g_Pdst[(size_t)(base + m0) * HD + col] = h2pack(v0, v1);
                }
                if (n1) {
                    float v0 = acc[nt][2] + bv.x;
                    float v1 = acc[nt][3] + bv.y;
                    *(u32*)&g_Pdst[(size_t)(base + m1) * HD + col] = h2pack(v0, v1);
                }
            }
        }
    }

    const float4 z4 = make_float4(0.f, 0.f, 0.f, 0.f);
    for (int idx = tid; idx < 128 * 32; idx += 512) {
        int node = base + (idx >> 5);
        if (node < N)
            ((float4*)g_agg)[(size_t)node * 32 + (idx & 31)] = z4;
    }
}

// =================== K2: warp-MMA edge kernel (v9: persistent, resident weights) ====
// Persistent CTAs (2/SM, 256 thr) loop over 64-edge tiles. B1/B2 staged ONCE per
// CTA into swizzled unpadded smem (XOR swizzle keeps ldsm conflict-free):
//   B1: row*64  + (kb ^ (((row>>1)&3)<<4))   [256 rows x 64B]   16384
//   B2: row*512 + (kb ^ ((row&7)<<4))        [128 rows x 512B]  65536
// PS gathers single-buffered cp.async, prefetch(c+1) after epilogue(c).
// smem map (bytes):
//   B1  @ 0       16384
//   B2  @ 16384   65536
//   A2c @ 81920   [64 rows][64 halves] stride 144 = 9216 (A1 [64][80B] aliases)
//   PS  @ 91136   { Psrc[64][72h] st144 | Pdst +9216 } = 18432
//   src @ 109568  int[64];  dst @ 109824 int[64]
#define B1_OFF  0
#define B2R_OFF 16384
#define A2_OFF  81920
#define PS_OFF  91136
#define SRC_OFF 109568
#define DST_OFF 109824
#define EDGE_SMEM 110080
#define A1_ST 80
#define A2_ST 144
#define PS_ST 144

__global__ __launch_bounds__(256, 2) void k_edge_mma(
    const float* __restrict__ edge_attr, const float* __restrict__ mb2, int E)
{
    extern __shared__ __align__(16) char sm[];
    const u32 smu = smem_u32(sm);
    const int tid = threadIdx.x;
    const int w = tid >> 5, l = tid & 31;
    const int wm = w & 3, wn = w >> 2;
    const int g = l >> 2, t = l & 3;

    // ---- stage B1 + B2 ONCE (swizzled, unpadded) ----
    for (int i = tid; i < 1024; i += 256) {        // B1: 256 rows x 4 parts
        int row = i >> 2, part = i & 3;
        u32 kb = (u32)part * 16;
        *(float4*)(sm + B1_OFF + row * 64 + (kb ^ ((((u32)row >> 1) & 3) << 4))) =
            *(const float4*)((const char*)g_B1h + row * 64 + kb);
    }
    for (int i = tid; i < 4096; i += 256) {        // B2: 128 rows x 32 parts
        int row = i >> 5, part = i & 31;
        u32 kb = (u32)part * 16;
        *(float4*)(sm + B2R_OFF + row * 512 + (kb ^ (((u32)row & 7) << 4))) =
            *(const float4*)((const char*)g_B2h + row * 512 + kb);
    }

    // per-lane ldmatrix address components
    const int lr   = l & 7;
    const int aRow = 16 * wm + lr + ((l >> 3) & 1) * 8;
    const int aKh  = (l >> 4) * 8;
    const int bRow = lr + (l >> 4) * 8;
    const int bKh  = ((l >> 3) & 1) * 8;
    const u32 a1base = smu + A2_OFF + aRow * A1_ST + aKh * 2;  // A1 alias
    const u32 a2base = smu + A2_OFF + aRow * A2_ST + aKh * 2;
    const int m0 = 16 * wm + g, m1 = m0 + 8;

    const int tiles = (E + 63) >> 6;
    #pragma unroll 1
    for (int tile = blockIdx.x; tile < tiles; tile += gridDim.x) {
        const int base = tile * 64;

        __syncthreads();   // previous tile's layer2/A2 reads done; weights visible (1st tile)

        // ---- stage src/dst ----
        if (tid < 64) {
            int e = base + tid;
            ((int*)(sm + SRC_OFF))[tid] = (e < E) ? g_src[e] : 0;
            ((int*)(sm + DST_OFF))[tid] = (e < E) ? g_dst[e] : 0;
        }
        // ---- stage A1: edge_attr -> fp16 (aliases A2c region) ----
        if (tid < 128) {
            int e = tid >> 1, h = tid & 1;
            char* arow = sm + A2_OFF + e * A1_ST;
            if (base + e < E) {
                const float4* src4 = (const float4*)(edge_attr + (size_t)(base + e) * ED + 16 * h);
                #pragma unroll
                for (int q = 0; q < 4; q++) {
                    float4 v = src4[q];
                    int k = 16 * h + 4 * q;
                    *(u32*)(arow + k * 2)       = h2pack(v.x, v.y);
                    *(u32*)(arow + (k + 2) * 2) = h2pack(v.z, v.w);
                }
            } else {
                #pragma unroll
                for (int q = 0; q < 8; q++)
                    *(u32*)(arow + (16 * h + 2 * q) * 2) = 0u;
            }
        }
        __syncthreads();   // src/dst + A1 visible

        // ---- PS chunk 0 prefetch (row-contiguous gathers) ----
        #pragma unroll
        for (int r = 0; r < 2; r++) {
            int idx = tid + 256 * r;
            int row = idx >> 3, part = idx & 7;
            int vs = ((const int*)(sm + SRC_OFF))[row];
            int vd = ((const int*)(sm + DST_OFF))[row];
            CP_ASYNC16(smu + PS_OFF + row * PS_ST + part * 16,
                       (const char*)g_Psrc + ((size_t)vs * HD) * 2 + part * 16);
            CP_ASYNC16(smu + PS_OFF + 9216 + row * PS_ST + part * 16,
                       (const char*)g_Pdst + ((size_t)vd * HD) * 2 + part * 16);
        }
        CP_COMMIT();

        // A1 fragments for this tile
        u32 fa[2][4];
        #pragma unroll
        for (int kt = 0; kt < 2; kt++)
            ldsm_x4(a1base + kt * 32, fa[kt][0], fa[kt][1], fa[kt][2], fa[kt][3]);

        const int vd0 = ((const int*)(sm + DST_OFF))[m0];
        const int vd1 = ((const int*)(sm + DST_OFF))[m1];
        char* a2r0 = sm + A2_OFF + m0 * A2_ST;
        char* a2r1 = sm + A2_OFF + m1 * A2_ST;

        float acc2[8][4];
        #pragma unroll
        for (int j = 0; j < 8; j++)
            #pragma unroll
            for (int q = 0; q < 4; q++) acc2[j][q] = 0.f;

        // ================= fused chunk loop =================
        #pragma unroll 1
        for (int c = 0; c < 4; c++) {
            // ---- layer 1: acc1 = EA @ W1c[:, warp's 32 cols of chunk c] ----
            float acc1[4][4];
            #pragma unroll
            for (int j = 0; j < 4; j++)
                #pragma unroll
                for (int q = 0; q < 4; q++) acc1[j][q] = 0.f;

            #pragma unroll
            for (int jp = 0; jp < 2; jp++) {
                u32 nrow = (u32)(64 * c + 32 * wn + 16 * jp + bRow);
                u32 sw = ((nrow >> 1) & 3) << 4;
                u32 rb = smu + B1_OFF + nrow * 64;
                u32 b0, b1, b2, b3;
                ldsm_x4(rb + (((u32)(2 * bKh)) ^ sw), b0, b1, b2, b3);        // k0-15
                mma_f16(acc1[2 * jp],     fa[0][0], fa[0][1], fa[0][2], fa[0][3], b0, b1);
                mma_f16(acc1[2 * jp + 1], fa[0][0], fa[0][1], fa[0][2], fa[0][3], b2, b3);
                ldsm_x4(rb + (((u32)(32 + 2 * bKh)) ^ sw), b0, b1, b2, b3);   // k16-31
                mma_f16(acc1[2 * jp],     fa[1][0], fa[1][1], fa[1][2], fa[1][3], b0, b1);
                mma_f16(acc1[2 * jp + 1], fa[1][0], fa[1][1], fa[1][2], fa[1][3], b2, b3);
            }

            // PS(c) arrived + all warps past layer2(c-1) (A2 reusable)
            CP_WAIT(0);
            __syncthreads();

            // ---- epilogue: staged partials (LDS), relu, fp16 into A2c ----
            const char* psb = sm + PS_OFF;
            #pragma unroll
            for (int nt = 0; nt < 4; nt++) {
                int lc = 32 * wn + 8 * nt + 2 * t;
                u32 ps0 = *(const u32*)(psb + m0 * PS_ST + lc * 2);
                u32 pd0 = *(const u32*)(psb + 9216 + m0 * PS_ST + lc * 2);
                u32 ps1 = *(const u32*)(psb + m1 * PS_ST + lc * 2);
                u32 pd1 = *(const u32*)(psb + 9216 + m1 * PS_ST + lc * 2);
                float2 a0 = h2unpack(ps0), b0 = h2unpack(pd0);
                float2 a1 = h2unpack(ps1), b1 = h2unpack(pd1);
                float v00 = fmaxf(acc1[nt][0] + a0.x + b0.x, 0.f);
                float v01 = fmaxf(acc1[nt][1] + a0.y + b0.y, 0.f);
                float v10 = fmaxf(acc1[nt][2] + a1.x + b1.x, 0.f);
                float v11 = fmaxf(acc1[nt][3] + a1.y + b1.y, 0.f);
                *(u32*)(a2r0 + lc * 2) = h2pack(v00, v01);
                *(u32*)(a2r1 + lc * 2) = h2pack(v10, v11);
            }
            __syncthreads();   // A2 ready; PS consumed

            // ---- PS(c+1) prefetch (single buffer, now free) ----
            if (c < 3) {
                #pragma unroll
                for (int r = 0; r < 2; r++) {
                    int idx = tid + 256 * r;
                    int row = idx >> 3, part = idx & 7;
                    int vs = ((const int*)(sm + SRC_OFF))[row];
                    int vd = ((const int*)(sm + DST_OFF))[row];
                    CP_ASYNC16(smu + PS_OFF + row * PS_ST + part * 16,
                               (const char*)g_Psrc + ((size_t)vs * HD + 64 * (c + 1)) * 2 + part * 16);
                    CP_ASYNC16(smu + PS_OFF + 9216 + row * PS_ST + part * 16,
                               (const char*)g_Pdst + ((size_t)vd * HD + 64 * (c + 1)) * 2 + part * 16);
                }
                CP_COMMIT();
            }

            // ---- layer 2: acc2 += h_chunk @ W2_chunk (B2 resident) ----
            #pragma unroll
            for (int t4 = 0; t4 < 4; t4++) {
                u32 ah0, ah1, ah2, ah3;
                ldsm_x4(a2base + t4 * 32, ah0, ah1, ah2, ah3);
                #pragma unroll
                for (int jp = 0; jp < 4; jp++) {
                    u32 nrow = (u32)(64 * wn + 16 * jp + bRow);
                    u32 kof  = (u32)((16 * t4 + bKh) * 2);
                    u32 addr = smu + B2R_OFF + nrow * 512 + 128u * (u32)c
                             + (kof ^ ((nrow & 7) << 4));
                    u32 b0, b1, b2, b3;
                    ldsm_x4(addr, b0, b1, b2, b3);
                    mma_f16(acc2[2 * jp],     ah0, ah1, ah2, ah3, b0, b1);
                    mma_f16(acc2[2 * jp + 1], ah0, ah1, ah2, ah3, b2, b3);
                }
            }
        }

        // ---- scatter: + mb2, red.v2 into g_agg[dst] ----
        const bool e0 = (base + m0 < E), e1 = (base + m1 < E);
        #pragma unroll
        for (int j = 0; j < 8; j++) {
            int n = 64 * wn + 8 * j + 2 * t;
            float2 bv = *(const float2*)(mb2 + n);
            if (e0) {
                float x0 = acc2[j][0] + bv.x, x1 = acc2[j][1] + bv.y;
                asm volatile("red.global.add.v2.f32 [%0], {%1, %2};"
                             :: "l"(g_agg + (size_t)vd0 * ND + n), "f"(x0), "f"(x1) : "memory");
            }
            if (e1) {
                float x0 = acc2[j][2] + bv.x, x1 = acc2[j][3] + bv.y;
                asm volatile("red.global.add.v2.f32 [%0], {%1, %2};"
                             :: "l"(g_agg + (size_t)vd1 * ND + n), "f"(x0), "f"(x1) : "memory");
            }
        }
    }
}

// =================== K3: warp-MMA node update (proven) ==========================
#define U_A1_OFF 0
#define U_A2_OFF 67584
#define U_B1_OFF 86016
#define U_B2_OFF 153600
#define U_SMEM   190464
#define U_A1_ST  528
#define U_A2_ST  144
#define U_B1_ST  528
#define U_B2_ST  144
#define U_B1_BUF 33792
#define U_B2_BUF 18432

__global__ __launch_bounds__(512, 1) void k_update_mma(
    const float* __restrict__ x,
    const float* __restrict__ ub1, const float* __restrict__ ub2,
    float* __restrict__ out, int N)
{
    extern __shared__ __align__(16) char sm[];
    const u32 smu = smem_u32(sm);
    const int tid = threadIdx.x;
    const int w = tid >> 5, l = tid & 31;
    const int wm = w & 7, wn = w >> 3;
    const int g = l >> 2, t = l & 3;
    const int base = blockIdx.x * 128;
    const char* gB1 = (const char*)g_U1h;
    const char* gB2 = (const char*)g_U2h;

    #pragma unroll
    for (int r = 0; r < 4; r++) {
        int i = tid + 512 * r;
        int row = i >> 5, part = i & 31;
        CP_ASYNC16(smu + U_B1_OFF + row * U_B1_ST + part * 16,
                   gB1 + row * 512 + part * 16);
    }
    #pragma unroll
    for (int r = 0; r < 2; r++) {
        int i = tid + 512 * r;
        int row = i >> 3, part = i & 7;
        CP_ASYNC16(smu + U_B2_OFF + row * U_B2_ST + part * 16,
                   gB2 + row * 512 + part * 16);
    }
    CP_COMMIT();

    {
        int row = tid >> 2, q = tid & 3;
        int node = base + row;
        char* arow = sm + U_A1_OFF + row * U_A1_ST + q * 128;
        if (node < N) {
            const float4* srcp = (q < 2)
                ? (const float4*)(x + (size_t)node * ND + 64 * q)
                : (const float4*)(g_agg + (size_t)node * ND + 64 * (q - 2));
            #pragma unroll
            for (int i = 0; i < 16; i++) {
                float4 v = srcp[i];
                *(u32*)(arow + i * 8)     = h2pack(v.x, v.y);
                *(u32*)(arow + i * 8 + 4) = h2pack(v.z, v.w);
            }
        } else {
            #pragma unroll
            for (int i = 0; i < 32; i++) *(u32*)(arow + i * 4) = 0u;
        }
    }
    __syncthreads();

    const int lr   = l & 7;
    const int aRow = 16 * wm + lr + ((l >> 3) & 1) * 8;
    const int aKh  = (l >> 4) * 8;
    const int bRow = lr + (l >> 4) * 8;
    const int bKh  = ((l >> 3) & 1) * 8;
    const u32 a1base = smu + U_A1_OFF + aRow * U_A1_ST + aKh * 2;
    const u32 a2base = smu + U_A2_OFF + aRow * U_A2_ST + aKh * 2;

    const int m0 = 16 * wm + g, m1 = m0 + 8;
    char* a2r0 = sm + U_A2_OFF + m0 * U_A2_ST;
    char* a2r1 = sm + U_A2_OFF + m1 * U_A2_ST;

    float acc2[8][4];
    #pragma unroll
    for (int j = 0; j < 8; j++)
        #pragma unroll
        for (int q = 0; q < 4; q++) acc2[j][q] = 0.f;

    #pragma unroll 1
    for (int c = 0; c < 4; c++) {
        if (c > 0) __syncthreads();
        if (c < 3) {
            int buf = (c + 1) & 1;
            #pragma unroll
            for (int r = 0; r < 4; r++) {
                int i = tid + 512 * r;
                int row = i >> 5, part = i & 31;
                CP_ASYNC16(smu + U_B1_OFF + buf * U_B1_BUF + row * U_B1_ST + part * 16,
                           gB1 + (size_t)(64 * (c + 1) + row) * 512 + part * 16);
            }
            #pragma unroll
            for (int r = 0; r < 2; r++) {
                int i = tid + 512 * r;
                int row = i >> 3, part = i & 7;
                CP_ASYNC16(smu + U_B2_OFF + buf * U_B2_BUF + row * U_B2_ST + part * 16,
                           gB2 + row * 512 + 128 * (c + 1) + part * 16);
            }
            CP_COMMIT();
        }
        if (c < 3) { CP_WAIT(1); } else { CP_WAIT(0); }
        __syncthreads();

        float acc1[4][4];
        #pragma unroll
        for (int j = 0; j < 4; j++)
            #pragma unroll
            for (int q = 0; q < 4; q++) acc1[j][q] = 0.f;

        const u32 b1b = smu + U_B1_OFF + (c & 1) * U_B1_BUF;
        #pragma unroll 2
        for (int kt = 0; kt < 16; kt++) {
            u32 fa0, fa1, fa2, fa3;
            ldsm_x4(a1base + kt * 32, fa0, fa1, fa2, fa3);
            #pragma unroll
            for (int jp = 0; jp < 2; jp++) {
                u32 nrow = (u32)(32 * wn + 16 * jp + bRow);
                u32 b0, b1, b2, b3;
                ldsm_x4(b1b + nrow * U_B1_ST + (u32)(16 * kt + bKh) * 2, b0, b1, b2, b3);
                mma_f16(acc1[2 * jp],     fa0, fa1, fa2, fa3, b0, b1);
                mma_f16(acc1[2 * jp + 1], fa0, fa1, fa2, fa3, b2, b3);
            }
        }

        #pragma unroll
        for (int nt = 0; nt < 4; nt++) {
            int col = 64 * c + 32 * wn + 8 * nt + 2 * t;
            int lc  = 32 * wn + 8 * nt + 2 * t;
            float2 bv = *(const float2*)(ub1 + col);
            float v00 = fmaxf(acc1[nt][0] + bv.x, 0.f);
            float v01 = fmaxf(acc1[nt][1] + bv.y, 0.f);
            float v10 = fmaxf(acc1[nt][2] + bv.x, 0.f);
            float v11 = fmaxf(acc1[nt][3] + bv.y, 0.f);
            *(u32*)(a2r0 + lc * 2) = h2pack(v00, v01);
            *(u32*)(a2r1 + lc * 2) = h2pack(v10, v11);
        }
        __syncthreads();

        const u32 b2b = smu + U_B2_OFF + (c & 1) * U_B2_BUF;
        #pragma unroll
        for (int t4 = 0; t4 < 4; t4++) {
            u32 ah0, ah1, ah2, ah3;
            ldsm_x4(a2base + t4 * 32, ah0, ah1, ah2, ah3);
            #pragma unroll
            for (int jp = 0; jp < 4; jp++) {
                u32 nrow = (u32)(64 * wn + 16 * jp + bRow);
                u32 kof  = (u32)(16 * t4 + bKh) * 2;
                u32 b0, b1, b2, b3;
                ldsm_x4(b2b + nrow * U_B2_ST + kof, b0, b1, b2, b3);
                mma_f16(acc2[2 * jp],     ah0, ah1, ah2, ah3, b0, b1);
                mma_f16(acc2[2 * jp + 1], ah0, ah1, ah2, ah3, b2, b3);
            }
        }
    }

    const bool n0 = (base + m0 < N), n1 = (base + m1 < N);
    #pragma unroll
    for (int j = 0; j < 8; j++) {
        int n = 64 * wn + 8 * j + 2 * t;
        float2 bv = *(const float2*)(ub2 + n);
        if (n0) {
            float2 r = make_float2(acc2[j][0] + bv.x, acc2[j][1] + bv.y);
            *(float2*)&out[(size_t)(base + m0) * ND + n] = r;
        }
        if (n1) {
            float2 r = make_float2(acc2[j][2] + bv.x, acc2[j][3] + bv.y);
            *(float2*)&out[(size_t)(base + m1) * ND + n] = r;
        }
    }
}

// =================== launcher ===================================================
extern "C" void kernel_launch(void* const* d_in, const int* in_sizes, int n_in,
                              void* d_out, int out_size)
{
    const float* x    = (const float*)d_in[0];
    const int*   ei   = (const int*)  d_in[1];
    const float* ea   = (const float*)d_in[2];
    const float* cong = (const float*)d_in[3];
    const float* mW1  = (const float*)d_in[4];
    const float* mb1  = (const float*)d_in[5];
    const float* mW2  = (const float*)d_in[6];
    const float* mb2  = (const float*)d_in[7];
    const float* uW1  = (const float*)d_in[8];
    const float* ub1  = (const float*)d_in[9];
    const float* uW2  = (const float*)d_in[10];
    const float* ub2  = (const float*)d_in[11];

    int N = in_sizes[0] / ND;
    int E = in_sizes[1] / 2;
    if (N > N_MAX) N = N_MAX;
    if (E > E_MAX) E = E_MAX;

    cudaFuncSetAttribute(k_pre_mma,    cudaFuncAttributeMaxDynamicSharedMemorySize, P_SMEM);
    cudaFuncSetAttribute(k_edge_mma,   cudaFuncAttributeMaxDynamicSharedMemorySize, EDGE_SMEM);
    cudaFuncSetAttribute(k_update_mma, cudaFuncAttributeMaxDynamicSharedMemorySize, U_SMEM);

    int tiles = (E + 63) / 64;
    int egrid = 304;                    // 2 persistent CTAs per SM (152 SMs)
    if (egrid > tiles) egrid = tiles;

    k_convert    <<<(E + 255) / 256, 256>>>(ei, E);
    k_prep       <<<160, 256>>>(mW1, mW2, uW1, uW2);
    k_pre_mma    <<<(N + 127) / 128, 512, P_SMEM>>>(x, cong, mW1, mb1, N);
    k_edge_mma   <<<egrid, 256, EDGE_SMEM>>>(ea, mb2, E);
    k_update_mma <<<(N + 127) / 128, 512, U_SMEM>>>(x, ub1, ub2, (float*)d_out, N);
}